// round 11
// baseline (speedup 1.0000x reference)
#include <cuda_runtime.h>
#include <cuda_fp16.h>
#include <math.h>

#define N_NODES 50000
#define KNBR    12
#define NEDGE   (N_NODES*KNBR)
#define EPSV    1e-5f
#define NSM     152
#define LENS_BLOCKS 196

typedef unsigned long long ull;

// ---------------- device scratch ----------------
__device__ __half g_elinh[NEDGE*64];    // e_lin fp16 (k1 -> k3)
__device__ __half g_ph[NEDGE*64];       // p fp16 (k3 -> k5)
__device__ float  g_pooled[N_NODES*64];
__device__ float  g_pc[N_NODES*384];    // f32: cols 0-63 (k1 self), 128-255 (k3 self)
__device__ __half g_pch1[N_NODES*64];   // fp16: k1 nbr contribution
__device__ __half g_pchAV[N_NODES*128]; // fp16: k3 att|val nbr contribution
__device__ float  g_lens[N_NODES];
__device__ float  g_cntPart[LENS_BLOCKS];
__device__ double g_sumE[64], g_ssqE[64];
__device__ double g_sumP[64], g_ssqP[64];
__device__ double g_sumO[64], g_ssqO[64];
__device__ double g_cnt;
__device__ unsigned int g_tick = 0;

// ---------------- f32x2 helpers ----------------
__device__ __forceinline__ ull pack2(float x, float y) {
    ull r; asm("mov.b64 %0,{%1,%2};" : "=l"(r) : "f"(x), "f"(y)); return r;
}
__device__ __forceinline__ void ffma2(ull& d, ull a, ull b) {
    asm("fma.rn.f32x2 %0,%1,%2,%0;" : "+l"(d) : "l"(a), "l"(b));
}
__device__ __forceinline__ float2 unpack2(ull v) {
    float2 r; asm("mov.b64 {%0,%1},%2;" : "=f"(r.x), "=f"(r.y) : "l"(v)); return r;
}

// ---------------- cp.async helpers ----------------
__device__ __forceinline__ unsigned su32(const void* p) {
    return (unsigned)__cvta_generic_to_shared(p);
}
#define CP16(dst, src) asm volatile( \
    "cp.async.cg.shared.global [%0], [%1], 16;" :: "r"(dst), "l"(src) : "memory")
#define CPCOMMIT() asm volatile("cp.async.commit_group;" ::: "memory")
#define CPWAIT0()  asm volatile("cp.async.wait_group 0;" ::: "memory")

// ---------------- softplus on MUFU pipe ----------------
__device__ __forceinline__ float fsp(float x) {
    return fmaxf(x, 0.f) + __logf(1.f + __expf(-fabsf(x)));
}

// ---------------- K_lens: lens + global count + zero stats (fused) ---------
__global__ void k_lens(const float* __restrict__ nmask) {
    int n = blockIdx.x * 256 + threadIdx.x;
    int tid = threadIdx.x;
    float eff = 0.f;
    if (n < N_NODES) {
        float L = 0.f;
#pragma unroll
        for (int k = 0; k < KNBR; k++) L += nmask[n*KNBR + k];
        g_lens[n] = L;
        eff = (L > 0.f) ? L : 1.0f;
    }
    __shared__ float red[256];
    __shared__ unsigned int tk;
    red[tid] = eff;
    __syncthreads();
    for (int s = 128; s > 0; s >>= 1) {
        if (tid < s) red[tid] += red[tid + s];
        __syncthreads();
    }
    if (tid == 0) g_cntPart[blockIdx.x] = red[0];
    __threadfence();
    if (tid == 0) tk = atomicInc(&g_tick, gridDim.x - 1);
    __syncthreads();
    if (tk == gridDim.x - 1) {
        if (tid < 64) {
            g_sumE[tid] = 0.0; g_ssqE[tid] = 0.0;
            g_sumP[tid] = 0.0; g_ssqP[tid] = 0.0;
            g_sumO[tid] = 0.0; g_ssqO[tid] = 0.0;
        }
        if (tid == 64) {
            double s = 0.0;
            for (int i = 0; i < LENS_BLOCKS; i++) s += (double)g_cntPart[i];
            g_cnt = s;
        }
    }
}

// ---------------- weight catalog for pre-GEMM ----------------
__device__ __forceinline__ float wcat(const float* We, const float* W1,
                                      const float* Wv, int c, int j) {
    if (j < 64)  return We[c*64 + j];
    if (j < 128) return We[(64+c)*64 + (j-64)];
    if (j < 192) { int jj = j-128; return W1[((jj>>4)*192 + c)*16 + (jj&15)]; }
    if (j < 256) { int jj = j-192; return Wv[((jj>>4)*192 + c)*16 + (jj&15)]; }
    if (j < 320) { int jj = j-256; return W1[((jj>>4)*192 + 64 + c)*16 + (jj&15)]; }
    { int jj = j-320; return Wv[((jj>>4)*192 + 64 + c)*16 + (jj&15)]; }
}

// ---------------- K_pre: per-node contributions, mixed precision ------------
__global__ __launch_bounds__(384,2) void k_pre(
    const float* __restrict__ nodef,
    const float* __restrict__ We, const float* __restrict__ W1,
    const float* __restrict__ Wv)
{
    extern __shared__ float smem[];
    ull* sW  = (ull*)smem;            // 96 jq * 130
    ull* sX  = sW + 96*130;           // 16 nodes * 33

    int t = threadIdx.x;
    for (int idx = t; idx < 12288; idx += 384) {
        int jq = idx >> 7, r = idx & 127, p = r >> 2, i = r & 3;
        int j = jq*4 + i, c0 = 2*p;
        sW[jq*130 + p*4 + i] = pack2(wcat(We,W1,Wv,c0,j), wcat(We,W1,Wv,c0+1,j));
    }

    int jq = t % 96, ng = t / 96;
    const int GRID = gridDim.x;
    const int NT = N_NODES / 16;  // 3125
    for (int tile = blockIdx.x; tile < NT; tile += GRID) {
        int n0 = tile * 16;
        __syncthreads();
        for (int idx = t; idx < 512; idx += 384) {
            int node = idx >> 5, p = idx & 31;
            float2 x2 = *(const float2*)&nodef[(n0+node)*64 + 2*p];
            sX[node*33 + p] = pack2(x2.x, x2.y);
        }
        __syncthreads();

        ull acc[4][4];
#pragma unroll
        for (int a = 0; a < 4; a++) { acc[a][0]=0; acc[a][1]=0; acc[a][2]=0; acc[a][3]=0; }
        const ull* wp = &sW[jq*130];
#pragma unroll 4
        for (int p = 0; p < 32; p++) {
            ulonglong2 w01 = *(const ulonglong2*)&wp[p*4];
            ulonglong2 w23 = *(const ulonglong2*)&wp[p*4 + 2];
#pragma unroll
            for (int ee = 0; ee < 4; ee++) {
                ull xv = sX[(ng*4+ee)*33 + p];
                ffma2(acc[ee][0], xv, w01.x);
                ffma2(acc[ee][1], xv, w01.y);
                ffma2(acc[ee][2], xv, w23.x);
                ffma2(acc[ee][3], xv, w23.y);
            }
        }
#pragma unroll
        for (int ee = 0; ee < 4; ee++) {
            int n = n0 + ng*4 + ee;
            float2 u0 = unpack2(acc[ee][0]), u1 = unpack2(acc[ee][1]);
            float2 u2 = unpack2(acc[ee][2]), u3 = unpack2(acc[ee][3]);
            float4 o;
            o.x = u0.x+u0.y; o.y = u1.x+u1.y; o.z = u2.x+u2.y; o.w = u3.x+u3.y;
            if (jq < 16 || (jq >= 32 && jq < 64)) {
                *(float4*)&g_pc[(size_t)n*384 + jq*4] = o;
            } else {
                __half2 h0 = __floats2half2_rn(o.x, o.y);
                __half2 h1 = __floats2half2_rn(o.z, o.w);
                uint2 uu; uu.x = *(unsigned*)&h0; uu.y = *(unsigned*)&h1;
                if (jq < 32)
                    *(uint2*)&g_pch1[(size_t)n*64 + (jq-16)*4] = uu;
                else
                    *(uint2*)&g_pchAV[(size_t)n*128 + (jq-64)*4] = uu;
            }
        }
    }
}

// ---------------- K1: e_lin (fp16 out) -------------------------------------
__global__ __launch_bounds__(256,3) void k1_edge(
    const float* __restrict__ edgef, const int* __restrict__ nbr,
    const float* __restrict__ nmask, const float* __restrict__ W,
    const float* __restrict__ bE,
    const float* __restrict__ gE, const float* __restrict__ bEbn)
{
    extern __shared__ float smem[];
    ull*    sW   = (ull*)smem;                    // 16*130
    float*  sC   = (float*)(sW + 2080);           // 2 * 48*68
    __half* sNPC = (__half*)(sC + 2*3264);        // 2 * 48*72 halves
    float*  sPS  = (float*)(sNPC + 2*3456);       // 4*68
    float*  sM   = sPS + 272;                     // 48
    int*    sNI  = (int*)(sM + 48);               // 2*48
    float*  sSum = (float*)(sNI + 96);            // 64
    float*  sSsq = sSum + 64;                     // 64

    int t = threadIdx.x;
    for (int idx = t; idx < 2048; idx += 256) {
        int jq = idx >> 7, r = idx & 127, p = r >> 2, i = r & 3;
        int j = jq*4 + i, c0 = 2*p;
        sW[jq*130 + p*4 + i] = pack2(W[(128+c0)*64 + j], W[(129+c0)*64 + j]);
    }
    if (t < 64) { sSum[t] = 0.f; sSsq[t] = 0.f; }

    int j16 = t & 15, eg = t >> 4;
    int j0 = j16*4, e0 = eg*3;
    float4 bj = *(const float4*)&bE[j0];
    const ull* wbase = &sW[j16*130];
    float pS[4] = {0,0,0,0}, pQ[4] = {0,0,0,0};

    const int GRID = gridDim.x;
    const int NT = NEDGE / 48;   // 12500
    int bid = blockIdx.x;

    if (t < 12) CP16(su32(&sNI[t*4]), &nbr[bid*48 + t*4]);
    CPCOMMIT(); CPWAIT0();
    __syncthreads();
    {
        for (int i = t; i < 768; i += 256) {
            int le = i >> 4, c4 = (i & 15) << 2;
            CP16(su32(&sC[le*68 + c4]), &edgef[(size_t)(bid*48+le)*64 + c4]);
        }
        for (int i = t; i < 384; i += 256) {
            int le = i >> 3, c8 = (i & 7) * 8;
            int nb = sNI[le];
            CP16(su32(&sNPC[le*72 + c8]), &g_pch1[(size_t)nb*64 + c8]);
        }
        int T1 = bid + GRID;
        if (T1 < NT && t < 12)
            CP16(su32(&sNI[48 + t*4]), &nbr[T1*48 + t*4]);
    }
    CPCOMMIT();

    int w = 0;
    for (int T = bid; T < NT; T += GRID, w ^= 1) {
        int cur = w, nxt = w ^ 1;
        CPWAIT0();
        __syncthreads();

        int Tn = T + GRID;
        if (Tn < NT) {
            for (int i = t; i < 768; i += 256) {
                int le = i >> 4, c4 = (i & 15) << 2;
                CP16(su32(&sC[nxt*3264 + le*68 + c4]),
                     &edgef[(size_t)(Tn*48+le)*64 + c4]);
            }
            for (int i = t; i < 384; i += 256) {
                int le = i >> 3, c8 = (i & 7) * 8;
                int nb = sNI[nxt*48 + le];
                CP16(su32(&sNPC[nxt*3456 + le*72 + c8]),
                     &g_pch1[(size_t)nb*64 + c8]);
            }
            int Tn2 = Tn + GRID;
            if (Tn2 < NT && t < 12)
                CP16(su32(&sNI[cur*48 + t*4]), &nbr[Tn2*48 + t*4]);
            CPCOMMIT();
        }

        int eb = T*48, n0 = T*4;
        if (t < 64) {
            int node = t >> 4, q = (t & 15) << 2;
            *(float4*)&sPS[node*68 + q] =
                *(const float4*)&g_pc[(size_t)(n0+node)*384 + q];
        }
        if (t < 48) {
            int e = eb + t, n = n0 + t/KNBR, k = t % KNBR;
            float L = g_lens[n];
            sM[t] = (L > 0.f) ? nmask[e] : (k == 0 ? 1.f : 0.f);
        }
        __syncthreads();

        ull acc[3][4];
#pragma unroll
        for (int a = 0; a < 3; a++) { acc[a][0]=0; acc[a][1]=0; acc[a][2]=0; acc[a][3]=0; }
        const float* cb = &sC[cur*3264 + e0*68];
#pragma unroll 4
        for (int c4 = 0, p = 0; c4 < 64; c4 += 4, p += 2) {
            ulonglong2 cv[3];
#pragma unroll
            for (int ee = 0; ee < 3; ee++) cv[ee] = *(const ulonglong2*)(cb + ee*68 + c4);
#pragma unroll
            for (int pp = 0; pp < 2; pp++) {
                ulonglong2 wa = *(const ulonglong2*)&wbase[(p+pp)*4];
                ulonglong2 wb = *(const ulonglong2*)&wbase[(p+pp)*4 + 2];
#pragma unroll
                for (int ee = 0; ee < 3; ee++) {
                    ull c2 = pp ? cv[ee].y : cv[ee].x;
                    ffma2(acc[ee][0], c2, wa.x);
                    ffma2(acc[ee][1], c2, wa.y);
                    ffma2(acc[ee][2], c2, wb.x);
                    ffma2(acc[ee][3], c2, wb.y);
                }
            }
        }
        const __half* npcb = &sNPC[cur*3456];
#pragma unroll
        for (int ee = 0; ee < 3; ee++) {
            int le = e0 + ee, e = eb + le, ln = le / KNBR;
            uint2 nu = *(const uint2*)&npcb[le*72 + j0];
            float2 n01 = __half22float2(*(__half2*)&nu.x);
            float2 n23 = __half22float2(*(__half2*)&nu.y);
            float4 sa = *(const float4*)&sPS[ln*68 + j0];
            float m = sM[le];
            float2 u;
            float o0, o1, o2, o3;
            u = unpack2(acc[ee][0]); o0 = u.x+u.y + bj.x + sa.x + n01.x;
            u = unpack2(acc[ee][1]); o1 = u.x+u.y + bj.y + sa.y + n01.y;
            u = unpack2(acc[ee][2]); o2 = u.x+u.y + bj.z + sa.z + n23.x;
            u = unpack2(acc[ee][3]); o3 = u.x+u.y + bj.w + sa.w + n23.y;
            __half2 h0 = __floats2half2_rn(o0, o1);
            __half2 h1 = __floats2half2_rn(o2, o3);
            uint2 ou; ou.x = *(unsigned*)&h0; ou.y = *(unsigned*)&h1;
            *(uint2*)&g_elinh[(size_t)e*64 + j0] = ou;
            pS[0] += o0*m; pQ[0] += o0*o0*m;
            pS[1] += o1*m; pQ[1] += o1*o1*m;
            pS[2] += o2*m; pQ[2] += o2*o2*m;
            pS[3] += o3*m; pQ[3] += o3*o3*m;
        }
    }
#pragma unroll
    for (int i = 0; i < 4; i++) {
        pS[i] += __shfl_down_sync(0xffffffffu, pS[i], 16);
        pQ[i] += __shfl_down_sync(0xffffffffu, pQ[i], 16);
    }
    __syncthreads();
    if ((t & 31) < 16) {
#pragma unroll
        for (int i = 0; i < 4; i++) {
            atomicAdd(&sSum[j0+i], pS[i]);
            atomicAdd(&sSsq[j0+i], pQ[i]);
        }
    }
    __syncthreads();
    if (t < 64) {
        atomicAdd(&g_sumE[t], (double)sSum[t]);
        atomicAdd(&g_ssqE[t], (double)sSsq[t]);
    }
}

// row c (128..191) weight for fused att|val col j in [0,128)
__device__ __forceinline__ float wrow3(const float* W1, const float* Wv,
                                       int crow, int j) {
    if (j < 64) return W1[((j>>4)*192 + crow)*16 + (j&15)];
    int jv = j - 64;
    return Wv[((jv>>4)*192 + crow)*16 + (jv&15)];
}

// ---------------- K3: fused edge-update + attention + value ----------------
// persistent, 384 threads, 2 CTAs/SM, tile = 4 nodes (48 edges);
// edgef + e_lin(fp16) + att|val nbr gathers ALL double-buffered via cp.async.
__global__ __launch_bounds__(384,2) void k3_att(
    const float* __restrict__ edgef, const int* __restrict__ nbr,
    const float* __restrict__ nmask,
    const float* __restrict__ W1, const float* __restrict__ b1,
    const float* __restrict__ W2,
    const float* __restrict__ Wv, const float* __restrict__ bv,
    const float* __restrict__ gE, const float* __restrict__ bEbn,
    float* __restrict__ out_edges)
{
    extern __shared__ float smem[];
    ull*    sW   = (ull*)smem;                    // 32*130 ull      (33280B)
    float*  sC   = (float*)(sW + 32*130);         // 48*68           (13056B)
    float*  sE   = sC + 3264;                     // 2 * 48*68       (26112B)
    __half* sNAV = (__half*)(sE + 2*3264);        // 2 * 48*136      (26112B)
    __half* sEL  = sNAV + 2*6528;                 // 2 * 48*64       (12288B)
    float*  sPS  = (float*)(sEL + 2*3072);        // 4*132           (2112B)
    float*  sLog = sPS + 528;                     // 192
    float*  sM   = sLog + 192;                    // 48
    int*    sNI  = (int*)(sM + 48);               // 2*48
    float*  sCoef= (float*)(sNI + 96);            // 128
    float*  sB1  = sCoef + 128;                   // 64
    float*  sBV  = sB1 + 64;                      // 64
    float*  sW2  = sBV + 64;                      // 64
    float*  sSum = sW2 + 64;                      // 64
    float*  sSsq = sSum + 64;                     // 64

    int t = threadIdx.x;
    for (int idx = t; idx < 4096; idx += 384) {
        int jq = idx >> 7, r = idx & 127, p = r >> 2, i = r & 3;
        int j = jq*4 + i, crow = 128 + 2*p;
        sW[jq*130 + p*4 + i] = pack2(wrow3(W1,Wv,crow,j), wrow3(W1,Wv,crow+1,j));
    }
    if (t < 64) {   // inline edge-BN coefs
        float cnt = (float)g_cnt;
        float s = (float)g_sumE[t], q = (float)g_ssqE[t];
        float mean = s / cnt, var = q / cnt - mean*mean;
        float inv = rsqrtf(var + EPSV);
        float sc = gE[t] * inv;
        sCoef[t] = sc;
        sCoef[64 + t] = bEbn[t] - mean*sc;
        sB1[t] = b1[t]; sBV[t] = bv[t]; sW2[t] = W2[t];
        sSum[t] = 0.f; sSsq[t] = 0.f;
    }

    int wid = t >> 5, l = t & 31;
    int isAtt = (wid < 6);
    int jq16 = l & 15;
    int eg = (isAtt ? wid : wid - 6)*2 + (l >> 4);   // 0..11
    int e0 = eg*4, ln = eg/3;
    int j0 = jq16*4;                                  // col within half
    int h4 = jq16 >> 2;
    int jq32 = (isAtt ? 0 : 16) + jq16;
    const ull* wbase = &sW[jq32*130];
    float pS[4] = {0,0,0,0}, pQ[4] = {0,0,0,0};

    const int GRID = gridDim.x;
    const int NT = N_NODES / 4;    // 12500
    int bid = blockIdx.x;

    // prolog
    if (t < 12) CP16(su32(&sNI[t*4]), &nbr[bid*48 + t*4]);
    CPCOMMIT(); CPWAIT0();
    __syncthreads();
    {
        for (int i = t; i < 768; i += 384) {
            int le = i >> 4, c4 = (i & 15) << 2;
            CP16(su32(&sE[le*68 + c4]), &edgef[(size_t)(bid*48+le)*64 + c4]);
        }
        for (int i = t; i < 768; i += 384) {
            int le = i >> 4, c8 = (i & 15) * 8;
            int nb = sNI[le];
            CP16(su32(&sNAV[le*136 + c8]), &g_pchAV[(size_t)nb*128 + c8]);
        }
        for (int i = t; i < 384; i += 384) {
            int le = i >> 3, c8 = (i & 7) * 8;
            CP16(su32(&sEL[le*64 + c8]), &g_elinh[(size_t)(bid*48+le)*64 + c8]);
        }
        int T1 = bid + GRID;
        if (T1 < NT && t < 12)
            CP16(su32(&sNI[48 + t*4]), &nbr[T1*48 + t*4]);
    }
    CPCOMMIT();

    int w = 0;
    for (int T = bid; T < NT; T += GRID, w ^= 1) {
        int cur = w, nxt = w ^ 1;
        CPWAIT0();
        __syncthreads();

        int Tn = T + GRID;
        if (Tn < NT) {
            for (int i = t; i < 768; i += 384) {
                int le = i >> 4, c4 = (i & 15) << 2;
                CP16(su32(&sE[nxt*3264 + le*68 + c4]),
                     &edgef[(size_t)(Tn*48+le)*64 + c4]);
            }
            for (int i = t; i < 768; i += 384) {
                int le = i >> 4, c8 = (i & 15) * 8;
                int nb = sNI[nxt*48 + le];
                CP16(su32(&sNAV[nxt*6528 + le*136 + c8]),
                     &g_pchAV[(size_t)nb*128 + c8]);
            }
            for (int i = t; i < 384; i += 384) {
                int le = i >> 3, c8 = (i & 7) * 8;
                CP16(su32(&sEL[nxt*3072 + le*64 + c8]),
                     &g_elinh[(size_t)(Tn*48+le)*64 + c8]);
            }
            int Tn2 = Tn + GRID;
            if (Tn2 < NT && t < 12)
                CP16(su32(&sNI[cur*48 + t*4]), &nbr[Tn2*48 + t*4]);
            CPCOMMIT();
        }

        int n0 = T*4, eb = n0*KNBR;
        if (t < 48) {
            int e = eb + t, n = n0 + t/KNBR, k = t % KNBR;
            float L = g_lens[n];
            sM[t] = (L > 0.f) ? nmask[e] : (k == 0 ? 1.f : 0.f);
        }
        if (t < 128) {
            int node = t >> 5, q = (t & 31) << 2;
            *(float4*)&sPS[node*132 + q] =
                *(const float4*)&g_pc[(size_t)(n0+node)*384 + 128 + q];
        }
        __syncthreads();

        // edge_updated — all inputs now in smem
        const float*  eE = &sE[cur*3264];
        const __half* eL = &sEL[cur*3072];
        for (int i = t; i < 768; i += 384) {
            int le = i >> 4, j = (i & 15) << 2;
            int e = eb + le;
            float m = sM[le];
            uint2 elu = *(const uint2*)&eL[le*64 + j];
            float2 el01 = __half22float2(*(__half2*)&elu.x);
            float2 el23 = __half22float2(*(__half2*)&elu.y);
            float4 ef = *(const float4*)&eE[le*68 + j];
            float4 sc = *(const float4*)&sCoef[j];
            float4 sh = *(const float4*)&sCoef[64 + j];
            float4 eu;
            eu.x = fsp(ef.x + (el01.x*sc.x + sh.x)*m);
            eu.y = fsp(ef.y + (el01.y*sc.y + sh.y)*m);
            eu.z = fsp(ef.z + (el23.x*sc.z + sh.z)*m);
            eu.w = fsp(ef.w + (el23.y*sc.w + sh.w)*m);
            *(float4*)&out_edges[(size_t)e*64 + j] = eu;
            *(float4*)&sC[le*68 + j] = eu;
        }
        __syncthreads();

        // GEMV: 4 edges x 4 cols per thread
        ull acc[4][4];
#pragma unroll
        for (int a = 0; a < 4; a++) { acc[a][0]=0; acc[a][1]=0; acc[a][2]=0; acc[a][3]=0; }
        const float* cb = &sC[e0*68];
#pragma unroll 4
        for (int c4 = 0, p = 0; c4 < 64; c4 += 4, p += 2) {
            ulonglong2 cv[4];
#pragma unroll
            for (int ee = 0; ee < 4; ee++) cv[ee] = *(const ulonglong2*)(cb + ee*68 + c4);
#pragma unroll
            for (int pp = 0; pp < 2; pp++) {
                ulonglong2 wa = *(const ulonglong2*)&wbase[(p+pp)*4];
                ulonglong2 wb = *(const ulonglong2*)&wbase[(p+pp)*4 + 2];
#pragma unroll
                for (int ee = 0; ee < 4; ee++) {
                    ull c2 = pp ? cv[ee].y : cv[ee].x;
                    ffma2(acc[ee][0], c2, wa.x);
                    ffma2(acc[ee][1], c2, wa.y);
                    ffma2(acc[ee][2], c2, wb.x);
                    ffma2(acc[ee][3], c2, wb.y);
                }
            }
        }

        const __half* nav = &sNAV[cur*6528];
        float vreg[4][4];
        if (isAtt) {
            float4 b1v = *(const float4*)&sB1[j0];
            float4 w2v = *(const float4*)&sW2[j0];
#pragma unroll
            for (int ee = 0; ee < 4; ee++) {
                int le = e0 + ee;
                uint2 nu = *(const uint2*)&nav[le*136 + j0];
                float2 f0 = __half22float2(*(__half2*)&nu.x);
                float2 f1 = __half22float2(*(__half2*)&nu.y);
                float4 sa = *(const float4*)&sPS[ln*132 + j0];
                float2 u;
                float lp = 0.f;
                u = unpack2(acc[ee][0]); lp += fsp(u.x+u.y + b1v.x + sa.x + f0.x) * w2v.x;
                u = unpack2(acc[ee][1]); lp += fsp(u.x+u.y + b1v.y + sa.y + f0.y) * w2v.y;
                u = unpack2(acc[ee][2]); lp += fsp(u.x+u.y + b1v.z + sa.z + f1.x) * w2v.z;
                u = unpack2(acc[ee][3]); lp += fsp(u.x+u.y + b1v.w + sa.w + f1.y) * w2v.w;
                lp += __shfl_xor_sync(0xffffffffu, lp, 1);
                lp += __shfl_xor_sync(0xffffffffu, lp, 2);
                if ((l & 3) == 0) sLog[le*4 + h4] = lp;
            }
        } else {
            float4 bvv = *(const float4*)&sBV[j0];
#pragma unroll
            for (int ee = 0; ee < 4; ee++) {
                int le = e0 + ee;
                uint2 nu = *(const uint2*)&nav[le*136 + 64 + j0];
                float2 f0 = __half22float2(*(__half2*)&nu.x);
                float2 f1 = __half22float2(*(__half2*)&nu.y);
                float4 sa = *(const float4*)&sPS[ln*132 + 64 + j0];
                float2 u;
                u = unpack2(acc[ee][0]); vreg[ee][0] = u.x+u.y + bvv.x + sa.x + f0.x;
                u = unpack2(acc[ee][1]); vreg[ee][1] = u.x+u.y + bvv.y + sa.y + f0.y;
                u = unpack2(acc[ee][2]); vreg[ee][2] = u.x+u.y + bvv.z + sa.z + f1.x;
                u = unpack2(acc[ee][3]); vreg[ee][3] = u.x+u.y + bvv.w + sa.w + f1.y;
            }
        }
        __syncthreads();   // logits ready

        if (!isAtt) {
            // per-thread softmax over this node's 12 edges, head h4
            int le0 = ln*KNBR;
            float mx = -1e30f;
#pragma unroll
            for (int k = 0; k < KNBR; k++) {
                int le = le0 + k;
                if (sM[le] > 0.f) mx = fmaxf(mx, sLog[le*4 + h4]);
            }
            float ss = 0.f;
#pragma unroll
            for (int k = 0; k < KNBR; k++) {
                int le = le0 + k;
                ss += (sM[le] > 0.f) ? __expf(sLog[le*4 + h4] - mx) : 0.f;
            }
            float inv = 1.f / ss;
#pragma unroll
            for (int ee = 0; ee < 4; ee++) {
                int le = e0 + ee, e = eb + le;
                float m = sM[le];
                float a = (m > 0.f) ? __expf(sLog[le*4 + h4] - mx) * inv : 0.f;
                float p0 = a*vreg[ee][0], p1 = a*vreg[ee][1];
                float p2 = a*vreg[ee][2], p3 = a*vreg[ee][3];
                __half2 h0 = __floats2half2_rn(p0, p1);
                __half2 h1 = __floats2half2_rn(p2, p3);
                uint2 uu; uu.x = *(unsigned*)&h0; uu.y = *(unsigned*)&h1;
                *(uint2*)&g_ph[(size_t)e*64 + j0] = uu;
                pS[0] += p0*m; pQ[0] += p0*p0*m;
                pS[1] += p1*m; pQ[1] += p1*p1*m;
                pS[2] += p2*m; pQ[2] += p2*p2*m;
                pS[3] += p3*m; pQ[3] += p3*p3*m;
            }
        }
    }
    __syncthreads();
    if (!isAtt) {
#pragma unroll
        for (int i = 0; i < 4; i++) {
            atomicAdd(&sSum[j0+i], pS[i]);
            atomicAdd(&sSsq[j0+i], pQ[i]);
        }
    }
    __syncthreads();
    if (t < 64) {
        atomicAdd(&g_sumP[t], (double)sSum[t]);
        atomicAdd(&g_ssqP[t], (double)sSsq[t]);
    }
}

// ---------------- K5: head_feats + pooled + out-BN stats ----------------
__global__ __launch_bounds__(256) void k5_pool(
    const float* __restrict__ nmask,
    const float* __restrict__ gP, const float* __restrict__ bP)
{
    __shared__ float scf[64], shf[64];
    int t = threadIdx.x;
    if (t < 64) {
        float cnt = (float)g_cnt;
        float s = (float)g_sumP[t], q = (float)g_ssqP[t];
        float mean = s / cnt, var = q / cnt - mean*mean;
        float inv = rsqrtf(var + EPSV);
        float sc = gP[t] * inv;
        scf[t] = sc; shf[t] = bP[t] - mean*sc;
    }
    __syncthreads();
    int j = t & 63, nl = t >> 6;
    int n0 = blockIdx.x * 64;
    float scP = scf[j], shP = shf[j];
    float psum = 0.f, pssq = 0.f;
    for (int i = 0; i < 16; i++) {
        int n = n0 + nl*16 + i;
        if (n >= N_NODES) break;
        float L = g_lens[n];
        float pooled = 0.f;
#pragma unroll
        for (int k = 0; k < KNBR; k++) {
            float m = (L > 0.f) ? nmask[n*KNBR + k] : (k == 0 ? 1.f : 0.f);
            float p = __half2float(g_ph[(size_t)(n*KNBR + k)*64 + j]);
            pooled += fsp(p*scP + shP) * m;
        }
        g_pooled[n*64 + j] = pooled;
        psum += pooled; pssq += pooled*pooled;
    }
    __shared__ float red[256], red2[256];
    red[t] = psum; red2[t] = pssq;
    __syncthreads();
    if (nl == 0) {
        float s = red[j] + red[64+j] + red[128+j] + red[192+j];
        float q = red2[j] + red2[64+j] + red2[128+j] + red2[192+j];
        atomicAdd(&g_sumO[j], (double)s);
        atomicAdd(&g_ssqO[j], (double)q);
    }
}

// ---------------- K7: residual + out-BN ----------------
__global__ __launch_bounds__(256) void k7_out(
    const float* __restrict__ nodef,
    const float* __restrict__ gO, const float* __restrict__ bO,
    float* __restrict__ out_nodes)
{
    __shared__ float scf[64], shf[64];
    int t = threadIdx.x;
    if (t < 64) {
        float cnt = (float)N_NODES;
        float s = (float)g_sumO[t], q = (float)g_ssqO[t];
        float mean = s / cnt, var = q / cnt - mean*mean;
        float inv = rsqrtf(var + EPSV);
        float sc = gO[t] * inv;
        scf[t] = sc; shf[t] = bO[t] - mean*sc;
    }
    __syncthreads();
    int i = blockIdx.x * 256 + t;
    if (i < N_NODES*64) {
        int j = i & 63;
        out_nodes[i] = nodef[i] + scf[j]*g_pooled[i] + shf[j];
    }
}

// ---------------- launch ----------------
extern "C" void kernel_launch(void* const* d_in, const int* in_sizes, int n_in,
                              void* d_out, int out_size)
{
    const float* nodef  = (const float*)d_in[0];
    const float* edgef  = (const float*)d_in[1];
    const int*   nbr    = (const int*)d_in[2];
    const float* nmask  = (const float*)d_in[3];
    const float* W_edge = (const float*)d_in[4];
    const float* b_edge = (const float*)d_in[5];
    const float* g_ebn  = (const float*)d_in[6];
    const float* b_ebn  = (const float*)d_in[7];
    const float* W1     = (const float*)d_in[8];
    const float* b1     = (const float*)d_in[9];
    const float* W2     = (const float*)d_in[10];
    const float* Wv     = (const float*)d_in[12];
    const float* bv     = (const float*)d_in[13];
    const float* g_abn  = (const float*)d_in[14];
    const float* b_abn  = (const float*)d_in[15];
    const float* g_obn  = (const float*)d_in[16];
    const float* b_obn  = (const float*)d_in[17];

    float* out_nodes = (float*)d_out;
    float* out_edges = out_nodes + (size_t)N_NODES * 64;

    const int smemP = (96*130 + 16*33) * 8;
    const int smem1 = 2080*8 + 2*3264*4 + 2*3456*2 +
                      (272 + 48 + 128) * 4 + 96*4;
    const int smem3 = 32*130*8 + 3264*4 + 2*3264*4 + 2*6528*2 + 2*3072*2 +
                      (528 + 192 + 48 + 128 + 64*3 + 128) * 4 + 96*4;
    static int inited = 0;
    if (!inited) {
        cudaFuncSetAttribute(k_pre,  cudaFuncAttributeMaxDynamicSharedMemorySize, smemP);
        cudaFuncSetAttribute(k1_edge, cudaFuncAttributeMaxDynamicSharedMemorySize, smem1);
        cudaFuncSetAttribute(k3_att,  cudaFuncAttributeMaxDynamicSharedMemorySize, smem3);
        inited = 1;
    }

    k_lens<<<LENS_BLOCKS, 256>>>(nmask);                               // 1
    k_pre<<<2*NSM, 384, smemP>>>(nodef, W_edge, W1, Wv);               // 2
    k1_edge<<<3*NSM, 256, smem1>>>(edgef, nbr, nmask, W_edge, b_edge,
                                   g_ebn, b_ebn);                      // 3
    k3_att<<<2*NSM, 384, smem3>>>(edgef, nbr, nmask, W1, b1, W2, Wv, bv,
                                  g_ebn, b_ebn, out_edges);            // 4 -> profiled
    k5_pool<<<(N_NODES + 63)/64, 256>>>(nmask, g_abn, b_abn);          // 5
    k7_out<<<(N_NODES*64 + 255)/256, 256>>>(nodef, g_obn, b_obn,
                                            out_nodes);                // 6
}

// round 13
// speedup vs baseline: 1.2437x; 1.2437x over previous
#include <cuda_runtime.h>
#include <cuda_fp16.h>
#include <math.h>

#define N_NODES 50000
#define KNBR    12
#define NEDGE   (N_NODES*KNBR)
#define EPSV    1e-5f
#define NSM     152
#define LENS_BLOCKS 196

typedef unsigned long long ull;

// ---------------- device scratch ----------------
__device__ __half g_elinh[NEDGE*64];    // e_lin fp16 (k1 -> k3)
__device__ __half g_ph[NEDGE*64];       // p fp16 (k3 -> k5)
__device__ float  g_pooled[N_NODES*64];
__device__ float  g_pc[N_NODES*384];    // f32: cols 0-63 (k1 self), 128-255 (k3 self)
__device__ __half g_pch1[N_NODES*64];   // fp16: k1 nbr contribution
__device__ __half g_pchAV[N_NODES*128]; // fp16: k3 att|val nbr contribution
__device__ float  g_lens[N_NODES];
__device__ float  g_cntPart[LENS_BLOCKS];
__device__ double g_sumE[64], g_ssqE[64];
__device__ double g_sumP[64], g_ssqP[64];
__device__ double g_sumO[64], g_ssqO[64];
__device__ double g_cnt;
__device__ unsigned int g_tick = 0;

// ---------------- f32x2 helpers ----------------
__device__ __forceinline__ ull pack2(float x, float y) {
    ull r; asm("mov.b64 %0,{%1,%2};" : "=l"(r) : "f"(x), "f"(y)); return r;
}
__device__ __forceinline__ void ffma2(ull& d, ull a, ull b) {
    asm("fma.rn.f32x2 %0,%1,%2,%0;" : "+l"(d) : "l"(a), "l"(b));
}
__device__ __forceinline__ float2 unpack2(ull v) {
    float2 r; asm("mov.b64 {%0,%1},%2;" : "=f"(r.x), "=f"(r.y) : "l"(v)); return r;
}

// ---------------- cp.async helpers ----------------
__device__ __forceinline__ unsigned su32(const void* p) {
    return (unsigned)__cvta_generic_to_shared(p);
}
#define CP16(dst, src) asm volatile( \
    "cp.async.cg.shared.global [%0], [%1], 16;" :: "r"(dst), "l"(src) : "memory")
#define CPCOMMIT() asm volatile("cp.async.commit_group;" ::: "memory")
#define CPWAIT0()  asm volatile("cp.async.wait_group 0;" ::: "memory")

// ---------------- softplus on MUFU pipe ----------------
__device__ __forceinline__ float fsp(float x) {
    return fmaxf(x, 0.f) + __logf(1.f + __expf(-fabsf(x)));
}

// ---------------- K_lens: lens + global count + zero stats (fused) ---------
__global__ void k_lens(const float* __restrict__ nmask) {
    int n = blockIdx.x * 256 + threadIdx.x;
    int tid = threadIdx.x;
    float eff = 0.f;
    if (n < N_NODES) {
        float L = 0.f;
#pragma unroll
        for (int k = 0; k < KNBR; k++) L += nmask[n*KNBR + k];
        g_lens[n] = L;
        eff = (L > 0.f) ? L : 1.0f;
    }
    __shared__ float red[256];
    __shared__ unsigned int tk;
    red[tid] = eff;
    __syncthreads();
    for (int s = 128; s > 0; s >>= 1) {
        if (tid < s) red[tid] += red[tid + s];
        __syncthreads();
    }
    if (tid == 0) g_cntPart[blockIdx.x] = red[0];
    __threadfence();
    if (tid == 0) tk = atomicInc(&g_tick, gridDim.x - 1);
    __syncthreads();
    if (tk == gridDim.x - 1) {
        if (tid < 64) {
            g_sumE[tid] = 0.0; g_ssqE[tid] = 0.0;
            g_sumP[tid] = 0.0; g_ssqP[tid] = 0.0;
            g_sumO[tid] = 0.0; g_ssqO[tid] = 0.0;
        }
        if (tid == 64) {
            double s = 0.0;
            for (int i = 0; i < LENS_BLOCKS; i++) s += (double)g_cntPart[i];
            g_cnt = s;
        }
    }
}

// ---------------- weight catalog for pre-GEMM ----------------
__device__ __forceinline__ float wcat(const float* We, const float* W1,
                                      const float* Wv, int c, int j) {
    if (j < 64)  return We[c*64 + j];
    if (j < 128) return We[(64+c)*64 + (j-64)];
    if (j < 192) { int jj = j-128; return W1[((jj>>4)*192 + c)*16 + (jj&15)]; }
    if (j < 256) { int jj = j-192; return Wv[((jj>>4)*192 + c)*16 + (jj&15)]; }
    if (j < 320) { int jj = j-256; return W1[((jj>>4)*192 + 64 + c)*16 + (jj&15)]; }
    { int jj = j-320; return Wv[((jj>>4)*192 + 64 + c)*16 + (jj&15)]; }
}

// ---------------- K_pre: per-node contributions, mixed precision ------------
__global__ __launch_bounds__(384,2) void k_pre(
    const float* __restrict__ nodef,
    const float* __restrict__ We, const float* __restrict__ W1,
    const float* __restrict__ Wv)
{
    extern __shared__ float smem[];
    ull* sW  = (ull*)smem;            // 96 jq * 130
    ull* sX  = sW + 96*130;           // 16 nodes * 33

    int t = threadIdx.x;
    for (int idx = t; idx < 12288; idx += 384) {
        int jq = idx >> 7, r = idx & 127, p = r >> 2, i = r & 3;
        int j = jq*4 + i, c0 = 2*p;
        sW[jq*130 + p*4 + i] = pack2(wcat(We,W1,Wv,c0,j), wcat(We,W1,Wv,c0+1,j));
    }

    int jq = t % 96, ng = t / 96;
    const int GRID = gridDim.x;
    const int NT = N_NODES / 16;  // 3125
    for (int tile = blockIdx.x; tile < NT; tile += GRID) {
        int n0 = tile * 16;
        __syncthreads();
        for (int idx = t; idx < 512; idx += 384) {
            int node = idx >> 5, p = idx & 31;
            float2 x2 = *(const float2*)&nodef[(n0+node)*64 + 2*p];
            sX[node*33 + p] = pack2(x2.x, x2.y);
        }
        __syncthreads();

        ull acc[4][4];
#pragma unroll
        for (int a = 0; a < 4; a++) { acc[a][0]=0; acc[a][1]=0; acc[a][2]=0; acc[a][3]=0; }
        const ull* wp = &sW[jq*130];
#pragma unroll 4
        for (int p = 0; p < 32; p++) {
            ulonglong2 w01 = *(const ulonglong2*)&wp[p*4];
            ulonglong2 w23 = *(const ulonglong2*)&wp[p*4 + 2];
#pragma unroll
            for (int ee = 0; ee < 4; ee++) {
                ull xv = sX[(ng*4+ee)*33 + p];
                ffma2(acc[ee][0], xv, w01.x);
                ffma2(acc[ee][1], xv, w01.y);
                ffma2(acc[ee][2], xv, w23.x);
                ffma2(acc[ee][3], xv, w23.y);
            }
        }
#pragma unroll
        for (int ee = 0; ee < 4; ee++) {
            int n = n0 + ng*4 + ee;
            float2 u0 = unpack2(acc[ee][0]), u1 = unpack2(acc[ee][1]);
            float2 u2 = unpack2(acc[ee][2]), u3 = unpack2(acc[ee][3]);
            float4 o;
            o.x = u0.x+u0.y; o.y = u1.x+u1.y; o.z = u2.x+u2.y; o.w = u3.x+u3.y;
            if (jq < 16 || (jq >= 32 && jq < 64)) {
                *(float4*)&g_pc[(size_t)n*384 + jq*4] = o;
            } else {
                __half2 h0 = __floats2half2_rn(o.x, o.y);
                __half2 h1 = __floats2half2_rn(o.z, o.w);
                uint2 uu; uu.x = *(unsigned*)&h0; uu.y = *(unsigned*)&h1;
                if (jq < 32)
                    *(uint2*)&g_pch1[(size_t)n*64 + (jq-16)*4] = uu;
                else
                    *(uint2*)&g_pchAV[(size_t)n*128 + (jq-64)*4] = uu;
            }
        }
    }
}

// ---------------- K1: e_lin (fp16 out) -------------------------------------
__global__ __launch_bounds__(256,3) void k1_edge(
    const float* __restrict__ edgef, const int* __restrict__ nbr,
    const float* __restrict__ nmask, const float* __restrict__ W,
    const float* __restrict__ bE,
    const float* __restrict__ gE, const float* __restrict__ bEbn)
{
    extern __shared__ float smem[];
    ull*    sW   = (ull*)smem;                    // 16*130
    float*  sC   = (float*)(sW + 2080);           // 2 * 48*68
    __half* sNPC = (__half*)(sC + 2*3264);        // 2 * 48*72 halves
    float*  sPS  = (float*)(sNPC + 2*3456);       // 4*68
    float*  sM   = sPS + 272;                     // 48
    int*    sNI  = (int*)(sM + 48);               // 2*48
    float*  sSum = (float*)(sNI + 96);            // 64
    float*  sSsq = sSum + 64;                     // 64

    int t = threadIdx.x;
    for (int idx = t; idx < 2048; idx += 256) {
        int jq = idx >> 7, r = idx & 127, p = r >> 2, i = r & 3;
        int j = jq*4 + i, c0 = 2*p;
        sW[jq*130 + p*4 + i] = pack2(W[(128+c0)*64 + j], W[(129+c0)*64 + j]);
    }
    if (t < 64) { sSum[t] = 0.f; sSsq[t] = 0.f; }

    int j16 = t & 15, eg = t >> 4;
    int j0 = j16*4, e0 = eg*3;
    float4 bj = *(const float4*)&bE[j0];
    const ull* wbase = &sW[j16*130];
    float pS[4] = {0,0,0,0}, pQ[4] = {0,0,0,0};

    const int GRID = gridDim.x;
    const int NT = NEDGE / 48;   // 12500
    int bid = blockIdx.x;

    if (t < 12) CP16(su32(&sNI[t*4]), &nbr[bid*48 + t*4]);
    CPCOMMIT(); CPWAIT0();
    __syncthreads();
    {
        for (int i = t; i < 768; i += 256) {
            int le = i >> 4, c4 = (i & 15) << 2;
            CP16(su32(&sC[le*68 + c4]), &edgef[(size_t)(bid*48+le)*64 + c4]);
        }
        for (int i = t; i < 384; i += 256) {
            int le = i >> 3, c8 = (i & 7) * 8;
            int nb = sNI[le];
            CP16(su32(&sNPC[le*72 + c8]), &g_pch1[(size_t)nb*64 + c8]);
        }
        int T1 = bid + GRID;
        if (T1 < NT && t < 12)
            CP16(su32(&sNI[48 + t*4]), &nbr[T1*48 + t*4]);
    }
    CPCOMMIT();

    int w = 0;
    for (int T = bid; T < NT; T += GRID, w ^= 1) {
        int cur = w, nxt = w ^ 1;
        CPWAIT0();
        __syncthreads();

        int Tn = T + GRID;
        if (Tn < NT) {
            for (int i = t; i < 768; i += 256) {
                int le = i >> 4, c4 = (i & 15) << 2;
                CP16(su32(&sC[nxt*3264 + le*68 + c4]),
                     &edgef[(size_t)(Tn*48+le)*64 + c4]);
            }
            for (int i = t; i < 384; i += 256) {
                int le = i >> 3, c8 = (i & 7) * 8;
                int nb = sNI[nxt*48 + le];
                CP16(su32(&sNPC[nxt*3456 + le*72 + c8]),
                     &g_pch1[(size_t)nb*64 + c8]);
            }
            int Tn2 = Tn + GRID;
            if (Tn2 < NT && t < 12)
                CP16(su32(&sNI[cur*48 + t*4]), &nbr[Tn2*48 + t*4]);
            CPCOMMIT();
        }

        int eb = T*48, n0 = T*4;
        if (t < 64) {
            int node = t >> 4, q = (t & 15) << 2;
            *(float4*)&sPS[node*68 + q] =
                *(const float4*)&g_pc[(size_t)(n0+node)*384 + q];
        }
        if (t < 48) {
            int e = eb + t, n = n0 + t/KNBR, k = t % KNBR;
            float L = g_lens[n];
            sM[t] = (L > 0.f) ? nmask[e] : (k == 0 ? 1.f : 0.f);
        }
        __syncthreads();

        ull acc[3][4];
#pragma unroll
        for (int a = 0; a < 3; a++) { acc[a][0]=0; acc[a][1]=0; acc[a][2]=0; acc[a][3]=0; }
        const float* cb = &sC[cur*3264 + e0*68];
#pragma unroll 4
        for (int c4 = 0, p = 0; c4 < 64; c4 += 4, p += 2) {
            ulonglong2 cv[3];
#pragma unroll
            for (int ee = 0; ee < 3; ee++) cv[ee] = *(const ulonglong2*)(cb + ee*68 + c4);
#pragma unroll
            for (int pp = 0; pp < 2; pp++) {
                ulonglong2 wa = *(const ulonglong2*)&wbase[(p+pp)*4];
                ulonglong2 wb = *(const ulonglong2*)&wbase[(p+pp)*4 + 2];
#pragma unroll
                for (int ee = 0; ee < 3; ee++) {
                    ull c2 = pp ? cv[ee].y : cv[ee].x;
                    ffma2(acc[ee][0], c2, wa.x);
                    ffma2(acc[ee][1], c2, wa.y);
                    ffma2(acc[ee][2], c2, wb.x);
                    ffma2(acc[ee][3], c2, wb.y);
                }
            }
        }
        const __half* npcb = &sNPC[cur*3456];
#pragma unroll
        for (int ee = 0; ee < 3; ee++) {
            int le = e0 + ee, e = eb + le, ln = le / KNBR;
            uint2 nu = *(const uint2*)&npcb[le*72 + j0];
            float2 n01 = __half22float2(*(__half2*)&nu.x);
            float2 n23 = __half22float2(*(__half2*)&nu.y);
            float4 sa = *(const float4*)&sPS[ln*68 + j0];
            float m = sM[le];
            float2 u;
            float o0, o1, o2, o3;
            u = unpack2(acc[ee][0]); o0 = u.x+u.y + bj.x + sa.x + n01.x;
            u = unpack2(acc[ee][1]); o1 = u.x+u.y + bj.y + sa.y + n01.y;
            u = unpack2(acc[ee][2]); o2 = u.x+u.y + bj.z + sa.z + n23.x;
            u = unpack2(acc[ee][3]); o3 = u.x+u.y + bj.w + sa.w + n23.y;
            __half2 h0 = __floats2half2_rn(o0, o1);
            __half2 h1 = __floats2half2_rn(o2, o3);
            uint2 ou; ou.x = *(unsigned*)&h0; ou.y = *(unsigned*)&h1;
            *(uint2*)&g_elinh[(size_t)e*64 + j0] = ou;
            pS[0] += o0*m; pQ[0] += o0*o0*m;
            pS[1] += o1*m; pQ[1] += o1*o1*m;
            pS[2] += o2*m; pQ[2] += o2*o2*m;
            pS[3] += o3*m; pQ[3] += o3*o3*m;
        }
    }
#pragma unroll
    for (int i = 0; i < 4; i++) {
        pS[i] += __shfl_down_sync(0xffffffffu, pS[i], 16);
        pQ[i] += __shfl_down_sync(0xffffffffu, pQ[i], 16);
    }
    __syncthreads();
    if ((t & 31) < 16) {
#pragma unroll
        for (int i = 0; i < 4; i++) {
            atomicAdd(&sSum[j0+i], pS[i]);
            atomicAdd(&sSsq[j0+i], pQ[i]);
        }
    }
    __syncthreads();
    if (t < 64) {
        atomicAdd(&g_sumE[t], (double)sSum[t]);
        atomicAdd(&g_ssqE[t], (double)sSsq[t]);
    }
}

// row c (128..191) weight for fused att|val col j in [0,128)
__device__ __forceinline__ float wrow3(const float* W1, const float* Wv,
                                       int crow, int j) {
    if (j < 64) return W1[((j>>4)*192 + crow)*16 + (j&15)];
    int jv = j - 64;
    return Wv[((jv>>4)*192 + crow)*16 + (jv&15)];
}

// ---------------- K3: fused edge-update + attention + value ----------------
// persistent, 384 threads, 2 CTAs/SM, tile = 4 nodes (48 edges);
// edgef + e_lin(fp16) + att|val nbr gathers ALL cp.async double-buffered.
// edge_update runs IN PLACE in the staged edgef buffer.
__global__ __launch_bounds__(384,2) void k3_att(
    const float* __restrict__ edgef, const int* __restrict__ nbr,
    const float* __restrict__ nmask,
    const float* __restrict__ W1, const float* __restrict__ b1,
    const float* __restrict__ W2,
    const float* __restrict__ Wv, const float* __restrict__ bv,
    const float* __restrict__ gE, const float* __restrict__ bEbn,
    float* __restrict__ out_edges)
{
    extern __shared__ float smem[];
    ull*    sW   = (ull*)smem;                    // 32*130 ull      (33280B)
    float*  sE   = (float*)(sW + 32*130);         // 2 * 48*68       (26112B)
    __half* sNAV = (__half*)(sE + 2*3264);        // 2 * 48*136      (26112B)
    __half* sEL  = sNAV + 2*6528;                 // 2 * 48*64       (12288B)
    float*  sPS  = (float*)(sEL + 2*3072);        // 4*132           (2112B)
    float*  sLog = sPS + 528;                     // 192
    float*  sM   = sLog + 192;                    // 48
    int*    sNI  = (int*)(sM + 48);               // 2*48
    float*  sCoef= (float*)(sNI + 96);            // 128
    float*  sB1  = sCoef + 128;                   // 64
    float*  sBV  = sB1 + 64;                      // 64
    float*  sW2  = sBV + 64;                      // 64
    float*  sSum = sW2 + 64;                      // 64
    float*  sSsq = sSum + 64;                     // 64

    int t = threadIdx.x;
    for (int idx = t; idx < 4096; idx += 384) {
        int jq = idx >> 7, r = idx & 127, p = r >> 2, i = r & 3;
        int j = jq*4 + i, crow = 128 + 2*p;
        sW[jq*130 + p*4 + i] = pack2(wrow3(W1,Wv,crow,j), wrow3(W1,Wv,crow+1,j));
    }
    if (t < 64) {   // inline edge-BN coefs
        float cnt = (float)g_cnt;
        float s = (float)g_sumE[t], q = (float)g_ssqE[t];
        float mean = s / cnt, var = q / cnt - mean*mean;
        float inv = rsqrtf(var + EPSV);
        float sc = gE[t] * inv;
        sCoef[t] = sc;
        sCoef[64 + t] = bEbn[t] - mean*sc;
        sB1[t] = b1[t]; sBV[t] = bv[t]; sW2[t] = W2[t];
        sSum[t] = 0.f; sSsq[t] = 0.f;
    }

    int wid = t >> 5, l = t & 31;
    int isAtt = (wid < 6);
    int jq16 = l & 15;
    int eg = (isAtt ? wid : wid - 6)*2 + (l >> 4);   // 0..11
    int e0 = eg*4, ln = eg/3;
    int j0 = jq16*4;                                  // col within half
    int h4 = jq16 >> 2;
    int jq32 = (isAtt ? 0 : 16) + jq16;
    const ull* wbase = &sW[jq32*130];
    float pS[4] = {0,0,0,0}, pQ[4] = {0,0,0,0};

    const int GRID = gridDim.x;
    const int NT = N_NODES / 4;    // 12500
    int bid = blockIdx.x;

    // prolog
    if (t < 12) CP16(su32(&sNI[t*4]), &nbr[bid*48 + t*4]);
    CPCOMMIT(); CPWAIT0();
    __syncthreads();
    {
        for (int i = t; i < 768; i += 384) {
            int le = i >> 4, c4 = (i & 15) << 2;
            CP16(su32(&sE[le*68 + c4]), &edgef[(size_t)(bid*48+le)*64 + c4]);
        }
        for (int i = t; i < 768; i += 384) {
            int le = i >> 4, c8 = (i & 15) * 8;
            int nb = sNI[le];
            CP16(su32(&sNAV[le*136 + c8]), &g_pchAV[(size_t)nb*128 + c8]);
        }
        for (int i = t; i < 384; i += 384) {
            int le = i >> 3, c8 = (i & 7) * 8;
            CP16(su32(&sEL[le*64 + c8]), &g_elinh[(size_t)(bid*48+le)*64 + c8]);
        }
        int T1 = bid + GRID;
        if (T1 < NT && t < 12)
            CP16(su32(&sNI[48 + t*4]), &nbr[T1*48 + t*4]);
    }
    CPCOMMIT();

    int w = 0;
    for (int T = bid; T < NT; T += GRID, w ^= 1) {
        int cur = w, nxt = w ^ 1;
        CPWAIT0();
        __syncthreads();

        int Tn = T + GRID;
        if (Tn < NT) {
            for (int i = t; i < 768; i += 384) {
                int le = i >> 4, c4 = (i & 15) << 2;
                CP16(su32(&sE[nxt*3264 + le*68 + c4]),
                     &edgef[(size_t)(Tn*48+le)*64 + c4]);
            }
            for (int i = t; i < 768; i += 384) {
                int le = i >> 4, c8 = (i & 15) * 8;
                int nb = sNI[nxt*48 + le];
                CP16(su32(&sNAV[nxt*6528 + le*136 + c8]),
                     &g_pchAV[(size_t)nb*128 + c8]);
            }
            for (int i = t; i < 384; i += 384) {
                int le = i >> 3, c8 = (i & 7) * 8;
                CP16(su32(&sEL[nxt*3072 + le*64 + c8]),
                     &g_elinh[(size_t)(Tn*48+le)*64 + c8]);
            }
            int Tn2 = Tn + GRID;
            if (Tn2 < NT && t < 12)
                CP16(su32(&sNI[cur*48 + t*4]), &nbr[Tn2*48 + t*4]);
            CPCOMMIT();
        }

        int n0 = T*4, eb = n0*KNBR;
        if (t < 48) {
            int e = eb + t, n = n0 + t/KNBR, k = t % KNBR;
            float L = g_lens[n];
            sM[t] = (L > 0.f) ? nmask[e] : (k == 0 ? 1.f : 0.f);
        }
        if (t < 128) {
            int node = t >> 5, q = (t & 31) << 2;
            *(float4*)&sPS[node*132 + q] =
                *(const float4*)&g_pc[(size_t)(n0+node)*384 + 128 + q];
        }
        __syncthreads();

        // edge_updated — in place in sE[cur] (read ef, write eu, same addr)
        float*        eEm = &sE[cur*3264];
        const __half* eL  = &sEL[cur*3072];
        for (int i = t; i < 768; i += 384) {
            int le = i >> 4, j = (i & 15) << 2;
            int e = eb + le;
            float m = sM[le];
            uint2 elu = *(const uint2*)&eL[le*64 + j];
            float2 el01 = __half22float2(*(__half2*)&elu.x);
            float2 el23 = __half22float2(*(__half2*)&elu.y);
            float4 ef = *(const float4*)&eEm[le*68 + j];
            float4 sc = *(const float4*)&sCoef[j];
            float4 sh = *(const float4*)&sCoef[64 + j];
            float4 eu;
            eu.x = fsp(ef.x + (el01.x*sc.x + sh.x)*m);
            eu.y = fsp(ef.y + (el01.y*sc.y + sh.y)*m);
            eu.z = fsp(ef.z + (el23.x*sc.z + sh.z)*m);
            eu.w = fsp(ef.w + (el23.y*sc.w + sh.w)*m);
            *(float4*)&out_edges[(size_t)e*64 + j] = eu;
            *(float4*)&eEm[le*68 + j] = eu;
        }
        __syncthreads();

        // GEMV: 4 edges x 4 cols per thread, activations from sE[cur]
        ull acc[4][4];
#pragma unroll
        for (int a = 0; a < 4; a++) { acc[a][0]=0; acc[a][1]=0; acc[a][2]=0; acc[a][3]=0; }
        const float* cb = &sE[cur*3264 + e0*68];
#pragma unroll 4
        for (int c4 = 0, p = 0; c4 < 64; c4 += 4, p += 2) {
            ulonglong2 cv[4];
#pragma unroll
            for (int ee = 0; ee < 4; ee++) cv[ee] = *(const ulonglong2*)(cb + ee*68 + c4);
#pragma unroll
            for (int pp = 0; pp < 2; pp++) {
                ulonglong2 wa = *(const ulonglong2*)&wbase[(p+pp)*4];
                ulonglong2 wb = *(const ulonglong2*)&wbase[(p+pp)*4 + 2];
#pragma unroll
                for (int ee = 0; ee < 4; ee++) {
                    ull c2 = pp ? cv[ee].y : cv[ee].x;
                    ffma2(acc[ee][0], c2, wa.x);
                    ffma2(acc[ee][1], c2, wa.y);
                    ffma2(acc[ee][2], c2, wb.x);
                    ffma2(acc[ee][3], c2, wb.y);
                }
            }
        }

        const __half* nav = &sNAV[cur*6528];
        float vreg[4][4];
        if (isAtt) {
            float4 b1v = *(const float4*)&sB1[j0];
            float4 w2v = *(const float4*)&sW2[j0];
#pragma unroll
            for (int ee = 0; ee < 4; ee++) {
                int le = e0 + ee;
                uint2 nu = *(const uint2*)&nav[le*136 + j0];
                float2 f0 = __half22float2(*(__half2*)&nu.x);
                float2 f1 = __half22float2(*(__half2*)&nu.y);
                float4 sa = *(const float4*)&sPS[ln*132 + j0];
                float2 u;
                float lp = 0.f;
                u = unpack2(acc[ee][0]); lp += fsp(u.x+u.y + b1v.x + sa.x + f0.x) * w2v.x;
                u = unpack2(acc[ee][1]); lp += fsp(u.x+u.y + b1v.y + sa.y + f0.y) * w2v.y;
                u = unpack2(acc[ee][2]); lp += fsp(u.x+u.y + b1v.z + sa.z + f1.x) * w2v.z;
                u = unpack2(acc[ee][3]); lp += fsp(u.x+u.y + b1v.w + sa.w + f1.y) * w2v.w;
                lp += __shfl_xor_sync(0xffffffffu, lp, 1);
                lp += __shfl_xor_sync(0xffffffffu, lp, 2);
                if ((l & 3) == 0) sLog[le*4 + h4] = lp;
            }
        } else {
            float4 bvv = *(const float4*)&sBV[j0];
#pragma unroll
            for (int ee = 0; ee < 4; ee++) {
                int le = e0 + ee;
                uint2 nu = *(const uint2*)&nav[le*136 + 64 + j0];
                float2 f0 = __half22float2(*(__half2*)&nu.x);
                float2 f1 = __half22float2(*(__half2*)&nu.y);
                float4 sa = *(const float4*)&sPS[ln*132 + 64 + j0];
                float2 u;
                u = unpack2(acc[ee][0]); vreg[ee][0] = u.x+u.y + bvv.x + sa.x + f0.x;
                u = unpack2(acc[ee][1]); vreg[ee][1] = u.x+u.y + bvv.y + sa.y + f0.y;
                u = unpack2(acc[ee][2]); vreg[ee][2] = u.x+u.y + bvv.z + sa.z + f1.x;
                u = unpack2(acc[ee][3]); vreg[ee][3] = u.x+u.y + bvv.w + sa.w + f1.y;
            }
        }
        __syncthreads();   // logits ready

        if (!isAtt) {
            // per-thread softmax over this node's 12 edges, head h4
            int le0 = ln*KNBR;
            float mx = -1e30f;
#pragma unroll
            for (int k = 0; k < KNBR; k++) {
                int le = le0 + k;
                if (sM[le] > 0.f) mx = fmaxf(mx, sLog[le*4 + h4]);
            }
            float ss = 0.f;
#pragma unroll
            for (int k = 0; k < KNBR; k++) {
                int le = le0 + k;
                ss += (sM[le] > 0.f) ? __expf(sLog[le*4 + h4] - mx) : 0.f;
            }
            float inv = 1.f / ss;
#pragma unroll
            for (int ee = 0; ee < 4; ee++) {
                int le = e0 + ee, e = eb + le;
                float m = sM[le];
                float a = (m > 0.f) ? __expf(sLog[le*4 + h4] - mx) * inv : 0.f;
                float p0 = a*vreg[ee][0], p1 = a*vreg[ee][1];
                float p2 = a*vreg[ee][2], p3 = a*vreg[ee][3];
                __half2 h0 = __floats2half2_rn(p0, p1);
                __half2 h1 = __floats2half2_rn(p2, p3);
                uint2 uu; uu.x = *(unsigned*)&h0; uu.y = *(unsigned*)&h1;
                *(uint2*)&g_ph[(size_t)e*64 + j0] = uu;
                pS[0] += p0*m; pQ[0] += p0*p0*m;
                pS[1] += p1*m; pQ[1] += p1*p1*m;
                pS[2] += p2*m; pQ[2] += p2*p2*m;
                pS[3] += p3*m; pQ[3] += p3*p3*m;
            }
        }
    }
    __syncthreads();
    if (!isAtt) {
#pragma unroll
        for (int i = 0; i < 4; i++) {
            atomicAdd(&sSum[j0+i], pS[i]);
            atomicAdd(&sSsq[j0+i], pQ[i]);
        }
    }
    __syncthreads();
    if (t < 64) {
        atomicAdd(&g_sumP[t], (double)sSum[t]);
        atomicAdd(&g_ssqP[t], (double)sSsq[t]);
    }
}

// ---------------- K5: head_feats + pooled + out-BN stats ----------------
__global__ __launch_bounds__(256) void k5_pool(
    const float* __restrict__ nmask,
    const float* __restrict__ gP, const float* __restrict__ bP)
{
    __shared__ float scf[64], shf[64];
    int t = threadIdx.x;
    if (t < 64) {
        float cnt = (float)g_cnt;
        float s = (float)g_sumP[t], q = (float)g_ssqP[t];
        float mean = s / cnt, var = q / cnt - mean*mean;
        float inv = rsqrtf(var + EPSV);
        float sc = gP[t] * inv;
        scf[t] = sc; shf[t] = bP[t] - mean*sc;
    }
    __syncthreads();
    int j = t & 63, nl = t >> 6;
    int n0 = blockIdx.x * 64;
    float scP = scf[j], shP = shf[j];
    float psum = 0.f, pssq = 0.f;
    for (int i = 0; i < 16; i++) {
        int n = n0 + nl*16 + i;
        if (n >= N_NODES) break;
        float L = g_lens[n];
        float pooled = 0.f;
#pragma unroll
        for (int k = 0; k < KNBR; k++) {
            float m = (L > 0.f) ? nmask[n*KNBR + k] : (k == 0 ? 1.f : 0.f);
            float p = __half2float(g_ph[(size_t)(n*KNBR + k)*64 + j]);
            pooled += fsp(p*scP + shP) * m;
        }
        g_pooled[n*64 + j] = pooled;
        psum += pooled; pssq += pooled*pooled;
    }
    __shared__ float red[256], red2[256];
    red[t] = psum; red2[t] = pssq;
    __syncthreads();
    if (nl == 0) {
        float s = red[j] + red[64+j] + red[128+j] + red[192+j];
        float q = red2[j] + red2[64+j] + red2[128+j] + red2[192+j];
        atomicAdd(&g_sumO[j], (double)s);
        atomicAdd(&g_ssqO[j], (double)q);
    }
}

// ---------------- K7: residual + out-BN ----------------
__global__ __launch_bounds__(256) void k7_out(
    const float* __restrict__ nodef,
    const float* __restrict__ gO, const float* __restrict__ bO,
    float* __restrict__ out_nodes)
{
    __shared__ float scf[64], shf[64];
    int t = threadIdx.x;
    if (t < 64) {
        float cnt = (float)N_NODES;
        float s = (float)g_sumO[t], q = (float)g_ssqO[t];
        float mean = s / cnt, var = q / cnt - mean*mean;
        float inv = rsqrtf(var + EPSV);
        float sc = gO[t] * inv;
        scf[t] = sc; shf[t] = bO[t] - mean*sc;
    }
    __syncthreads();
    int i = blockIdx.x * 256 + t;
    if (i < N_NODES*64) {
        int j = i & 63;
        out_nodes[i] = nodef[i] + scf[j]*g_pooled[i] + shf[j];
    }
}

// ---------------- launch ----------------
extern "C" void kernel_launch(void* const* d_in, const int* in_sizes, int n_in,
                              void* d_out, int out_size)
{
    const float* nodef  = (const float*)d_in[0];
    const float* edgef  = (const float*)d_in[1];
    const int*   nbr    = (const int*)d_in[2];
    const float* nmask  = (const float*)d_in[3];
    const float* W_edge = (const float*)d_in[4];
    const float* b_edge = (const float*)d_in[5];
    const float* g_ebn  = (const float*)d_in[6];
    const float* b_ebn  = (const float*)d_in[7];
    const float* W1     = (const float*)d_in[8];
    const float* b1     = (const float*)d_in[9];
    const float* W2     = (const float*)d_in[10];
    const float* Wv     = (const float*)d_in[12];
    const float* bv     = (const float*)d_in[13];
    const float* g_abn  = (const float*)d_in[14];
    const float* b_abn  = (const float*)d_in[15];
    const float* g_obn  = (const float*)d_in[16];
    const float* b_obn  = (const float*)d_in[17];

    float* out_nodes = (float*)d_out;
    float* out_edges = out_nodes + (size_t)N_NODES * 64;

    const int smemP = (96*130 + 16*33) * 8;
    const int smem1 = 2080*8 + 2*3264*4 + 2*3456*2 +
                      (272 + 48 + 128) * 4 + 96*4;
    const int smem3 = 32*130*8 + 2*3264*4 + 2*6528*2 + 2*3072*2 +
                      (528 + 192 + 48 + 128 + 64*3 + 128) * 4 + 96*4;  // ~100.7KB
    static int inited = 0;
    if (!inited) {
        cudaFuncSetAttribute(k_pre,  cudaFuncAttributeMaxDynamicSharedMemorySize, smemP);
        cudaFuncSetAttribute(k1_edge, cudaFuncAttributeMaxDynamicSharedMemorySize, smem1);
        cudaFuncSetAttribute(k3_att,  cudaFuncAttributeMaxDynamicSharedMemorySize, smem3);
        inited = 1;
    }

    k_lens<<<LENS_BLOCKS, 256>>>(nmask);                               // 1
    k_pre<<<2*NSM, 384, smemP>>>(nodef, W_edge, W1, Wv);               // 2
    k1_edge<<<3*NSM, 256, smem1>>>(edgef, nbr, nmask, W_edge, b_edge,
                                   g_ebn, b_ebn);                      // 3
    k3_att<<<2*NSM, 384, smem3>>>(edgef, nbr, nmask, W1, b1, W2, Wv, bv,
                                  g_ebn, b_ebn, out_edges);            // 4 -> profiled
    k5_pool<<<(N_NODES + 63)/64, 256>>>(nmask, g_abn, b_abn);          // 5
    k7_out<<<(N_NODES*64 + 255)/256, 256>>>(nodef, g_obn, b_obn,
                                            out_nodes);                // 6
}

// round 14
// speedup vs baseline: 1.5757x; 1.2669x over previous
#include <cuda_runtime.h>
#include <cuda_fp16.h>
#include <math.h>

#define N_NODES 50000
#define KNBR    12
#define NEDGE   (N_NODES*KNBR)
#define EPSV    1e-5f
#define NSM     152
#define LENS_BLOCKS 196

typedef unsigned long long ull;

// ---------------- device scratch ----------------
__device__ __half g_elinh[NEDGE*64];    // e_lin fp16 (k1 -> k3)
__device__ __half g_ph[NEDGE*64];       // p fp16 (k3 -> k5)
__device__ float  g_pooled[N_NODES*64];
__device__ float  g_pc[N_NODES*384];    // f32: cols 0-63 (k1 self), 128-255 (k3 self)
__device__ __half g_pch1[N_NODES*64];   // fp16: k1 nbr contribution
__device__ __half g_pchAV[N_NODES*128]; // fp16: k3 att|val nbr contribution
__device__ float  g_lens[N_NODES];
__device__ float  g_cntPart[LENS_BLOCKS];
__device__ double g_sumE[64], g_ssqE[64];
__device__ double g_sumP[64], g_ssqP[64];
__device__ double g_sumO[64], g_ssqO[64];
__device__ double g_cnt;
__device__ unsigned int g_tick = 0;

// ---------------- f32x2 helpers ----------------
__device__ __forceinline__ ull pack2(float x, float y) {
    ull r; asm("mov.b64 %0,{%1,%2};" : "=l"(r) : "f"(x), "f"(y)); return r;
}
__device__ __forceinline__ void ffma2(ull& d, ull a, ull b) {
    asm("fma.rn.f32x2 %0,%1,%2,%0;" : "+l"(d) : "l"(a), "l"(b));
}
__device__ __forceinline__ float2 unpack2(ull v) {
    float2 r; asm("mov.b64 {%0,%1},%2;" : "=f"(r.x), "=f"(r.y) : "l"(v)); return r;
}

// ---------------- cp.async helpers ----------------
__device__ __forceinline__ unsigned su32(const void* p) {
    return (unsigned)__cvta_generic_to_shared(p);
}
#define CP16(dst, src) asm volatile( \
    "cp.async.cg.shared.global [%0], [%1], 16;" :: "r"(dst), "l"(src) : "memory")
#define CPCOMMIT() asm volatile("cp.async.commit_group;" ::: "memory")
#define CPWAIT0()  asm volatile("cp.async.wait_group 0;" ::: "memory")

// ---------------- mma helpers ----------------
__device__ __forceinline__ void ldm_x4(unsigned& a0, unsigned& a1,
                                       unsigned& a2, unsigned& a3, unsigned addr) {
    asm volatile("ldmatrix.sync.aligned.m8n8.x4.shared.b16 {%0,%1,%2,%3}, [%4];"
        : "=r"(a0), "=r"(a1), "=r"(a2), "=r"(a3) : "r"(addr));
}
__device__ __forceinline__ void ldm_x2(unsigned& b0, unsigned& b1, unsigned addr) {
    asm volatile("ldmatrix.sync.aligned.m8n8.x2.shared.b16 {%0,%1}, [%2];"
        : "=r"(b0), "=r"(b1) : "r"(addr));
}
__device__ __forceinline__ void mma16816(float* d, const unsigned* a,
                                         unsigned b0, unsigned b1) {
    asm volatile("mma.sync.aligned.m16n8k16.row.col.f32.f16.f16.f32 "
        "{%0,%1,%2,%3}, {%4,%5,%6,%7}, {%8,%9}, {%0,%1,%2,%3};"
        : "+f"(d[0]), "+f"(d[1]), "+f"(d[2]), "+f"(d[3])
        : "r"(a[0]), "r"(a[1]), "r"(a[2]), "r"(a[3]), "r"(b0), "r"(b1));
}

// ---------------- softplus on MUFU pipe ----------------
__device__ __forceinline__ float fsp(float x) {
    return fmaxf(x, 0.f) + __logf(1.f + __expf(-fabsf(x)));
}

// ---------------- K_lens ----------------
__global__ void k_lens(const float* __restrict__ nmask) {
    int n = blockIdx.x * 256 + threadIdx.x;
    int tid = threadIdx.x;
    float eff = 0.f;
    if (n < N_NODES) {
        float L = 0.f;
#pragma unroll
        for (int k = 0; k < KNBR; k++) L += nmask[n*KNBR + k];
        g_lens[n] = L;
        eff = (L > 0.f) ? L : 1.0f;
    }
    __shared__ float red[256];
    __shared__ unsigned int tk;
    red[tid] = eff;
    __syncthreads();
    for (int s = 128; s > 0; s >>= 1) {
        if (tid < s) red[tid] += red[tid + s];
        __syncthreads();
    }
    if (tid == 0) g_cntPart[blockIdx.x] = red[0];
    __threadfence();
    if (tid == 0) tk = atomicInc(&g_tick, gridDim.x - 1);
    __syncthreads();
    if (tk == gridDim.x - 1) {
        if (tid < 64) {
            g_sumE[tid] = 0.0; g_ssqE[tid] = 0.0;
            g_sumP[tid] = 0.0; g_ssqP[tid] = 0.0;
            g_sumO[tid] = 0.0; g_ssqO[tid] = 0.0;
        }
        if (tid == 64) {
            double s = 0.0;
            for (int i = 0; i < LENS_BLOCKS; i++) s += (double)g_cntPart[i];
            g_cnt = s;
        }
    }
}

// ---------------- weight catalog for pre-GEMM ----------------
__device__ __forceinline__ float wcat(const float* We, const float* W1,
                                      const float* Wv, int c, int j) {
    if (j < 64)  return We[c*64 + j];
    if (j < 128) return We[(64+c)*64 + (j-64)];
    if (j < 192) { int jj = j-128; return W1[((jj>>4)*192 + c)*16 + (jj&15)]; }
    if (j < 256) { int jj = j-192; return Wv[((jj>>4)*192 + c)*16 + (jj&15)]; }
    if (j < 320) { int jj = j-256; return W1[((jj>>4)*192 + 64 + c)*16 + (jj&15)]; }
    { int jj = j-320; return Wv[((jj>>4)*192 + 64 + c)*16 + (jj&15)]; }
}

// ---------------- K_pre ----------------
__global__ __launch_bounds__(384,2) void k_pre(
    const float* __restrict__ nodef,
    const float* __restrict__ We, const float* __restrict__ W1,
    const float* __restrict__ Wv)
{
    extern __shared__ float smem[];
    ull* sW  = (ull*)smem;            // 96 jq * 130
    ull* sX  = sW + 96*130;           // 16 nodes * 33

    int t = threadIdx.x;
    for (int idx = t; idx < 12288; idx += 384) {
        int jq = idx >> 7, r = idx & 127, p = r >> 2, i = r & 3;
        int j = jq*4 + i, c0 = 2*p;
        sW[jq*130 + p*4 + i] = pack2(wcat(We,W1,Wv,c0,j), wcat(We,W1,Wv,c0+1,j));
    }

    int jq = t % 96, ng = t / 96;
    const int GRID = gridDim.x;
    const int NT = N_NODES / 16;  // 3125
    for (int tile = blockIdx.x; tile < NT; tile += GRID) {
        int n0 = tile * 16;
        __syncthreads();
        for (int idx = t; idx < 512; idx += 384) {
            int node = idx >> 5, p = idx & 31;
            float2 x2 = *(const float2*)&nodef[(n0+node)*64 + 2*p];
            sX[node*33 + p] = pack2(x2.x, x2.y);
        }
        __syncthreads();

        ull acc[4][4];
#pragma unroll
        for (int a = 0; a < 4; a++) { acc[a][0]=0; acc[a][1]=0; acc[a][2]=0; acc[a][3]=0; }
        const ull* wp = &sW[jq*130];
#pragma unroll 4
        for (int p = 0; p < 32; p++) {
            ulonglong2 w01 = *(const ulonglong2*)&wp[p*4];
            ulonglong2 w23 = *(const ulonglong2*)&wp[p*4 + 2];
#pragma unroll
            for (int ee = 0; ee < 4; ee++) {
                ull xv = sX[(ng*4+ee)*33 + p];
                ffma2(acc[ee][0], xv, w01.x);
                ffma2(acc[ee][1], xv, w01.y);
                ffma2(acc[ee][2], xv, w23.x);
                ffma2(acc[ee][3], xv, w23.y);
            }
        }
#pragma unroll
        for (int ee = 0; ee < 4; ee++) {
            int n = n0 + ng*4 + ee;
            float2 u0 = unpack2(acc[ee][0]), u1 = unpack2(acc[ee][1]);
            float2 u2 = unpack2(acc[ee][2]), u3 = unpack2(acc[ee][3]);
            float4 o;
            o.x = u0.x+u0.y; o.y = u1.x+u1.y; o.z = u2.x+u2.y; o.w = u3.x+u3.y;
            if (jq < 16 || (jq >= 32 && jq < 64)) {
                *(float4*)&g_pc[(size_t)n*384 + jq*4] = o;
            } else {
                __half2 h0 = __floats2half2_rn(o.x, o.y);
                __half2 h1 = __floats2half2_rn(o.z, o.w);
                uint2 uu; uu.x = *(unsigned*)&h0; uu.y = *(unsigned*)&h1;
                if (jq < 32)
                    *(uint2*)&g_pch1[(size_t)n*64 + (jq-16)*4] = uu;
                else
                    *(uint2*)&g_pchAV[(size_t)n*128 + (jq-64)*4] = uu;
            }
        }
    }
}

// ---------------- K1: e_lin (fp16 out) -------------------------------------
__global__ __launch_bounds__(256,3) void k1_edge(
    const float* __restrict__ edgef, const int* __restrict__ nbr,
    const float* __restrict__ nmask, const float* __restrict__ W,
    const float* __restrict__ bE,
    const float* __restrict__ gE, const float* __restrict__ bEbn)
{
    extern __shared__ float smem[];
    ull*    sW   = (ull*)smem;                    // 16*130
    float*  sC   = (float*)(sW + 2080);           // 2 * 48*68
    __half* sNPC = (__half*)(sC + 2*3264);        // 2 * 48*72 halves
    float*  sPS  = (float*)(sNPC + 2*3456);       // 4*68
    float*  sM   = sPS + 272;                     // 48
    int*    sNI  = (int*)(sM + 48);               // 2*48
    float*  sSum = (float*)(sNI + 96);            // 64
    float*  sSsq = sSum + 64;                     // 64

    int t = threadIdx.x;
    for (int idx = t; idx < 2048; idx += 256) {
        int jq = idx >> 7, r = idx & 127, p = r >> 2, i = r & 3;
        int j = jq*4 + i, c0 = 2*p;
        sW[jq*130 + p*4 + i] = pack2(W[(128+c0)*64 + j], W[(129+c0)*64 + j]);
    }
    if (t < 64) { sSum[t] = 0.f; sSsq[t] = 0.f; }

    int j16 = t & 15, eg = t >> 4;
    int j0 = j16*4, e0 = eg*3;
    float4 bj = *(const float4*)&bE[j0];
    const ull* wbase = &sW[j16*130];
    float pS[4] = {0,0,0,0}, pQ[4] = {0,0,0,0};

    const int GRID = gridDim.x;
    const int NT = NEDGE / 48;   // 12500
    int bid = blockIdx.x;

    if (t < 12) CP16(su32(&sNI[t*4]), &nbr[bid*48 + t*4]);
    CPCOMMIT(); CPWAIT0();
    __syncthreads();
    {
        for (int i = t; i < 768; i += 256) {
            int le = i >> 4, c4 = (i & 15) << 2;
            CP16(su32(&sC[le*68 + c4]), &edgef[(size_t)(bid*48+le)*64 + c4]);
        }
        for (int i = t; i < 384; i += 256) {
            int le = i >> 3, c8 = (i & 7) * 8;
            int nb = sNI[le];
            CP16(su32(&sNPC[le*72 + c8]), &g_pch1[(size_t)nb*64 + c8]);
        }
        int T1 = bid + GRID;
        if (T1 < NT && t < 12)
            CP16(su32(&sNI[48 + t*4]), &nbr[T1*48 + t*4]);
    }
    CPCOMMIT();

    int w = 0;
    for (int T = bid; T < NT; T += GRID, w ^= 1) {
        int cur = w, nxt = w ^ 1;
        CPWAIT0();
        __syncthreads();

        int Tn = T + GRID;
        if (Tn < NT) {
            for (int i = t; i < 768; i += 256) {
                int le = i >> 4, c4 = (i & 15) << 2;
                CP16(su32(&sC[nxt*3264 + le*68 + c4]),
                     &edgef[(size_t)(Tn*48+le)*64 + c4]);
            }
            for (int i = t; i < 384; i += 256) {
                int le = i >> 3, c8 = (i & 7) * 8;
                int nb = sNI[nxt*48 + le];
                CP16(su32(&sNPC[nxt*3456 + le*72 + c8]),
                     &g_pch1[(size_t)nb*64 + c8]);
            }
            int Tn2 = Tn + GRID;
            if (Tn2 < NT && t < 12)
                CP16(su32(&sNI[cur*48 + t*4]), &nbr[Tn2*48 + t*4]);
            CPCOMMIT();
        }

        int eb = T*48, n0 = T*4;
        if (t < 64) {
            int node = t >> 4, q = (t & 15) << 2;
            *(float4*)&sPS[node*68 + q] =
                *(const float4*)&g_pc[(size_t)(n0+node)*384 + q];
        }
        if (t < 48) {
            int e = eb + t, n = n0 + t/KNBR, k = t % KNBR;
            float L = g_lens[n];
            sM[t] = (L > 0.f) ? nmask[e] : (k == 0 ? 1.f : 0.f);
        }
        __syncthreads();

        ull acc[3][4];
#pragma unroll
        for (int a = 0; a < 3; a++) { acc[a][0]=0; acc[a][1]=0; acc[a][2]=0; acc[a][3]=0; }
        const float* cb = &sC[cur*3264 + e0*68];
#pragma unroll 4
        for (int c4 = 0, p = 0; c4 < 64; c4 += 4, p += 2) {
            ulonglong2 cv[3];
#pragma unroll
            for (int ee = 0; ee < 3; ee++) cv[ee] = *(const ulonglong2*)(cb + ee*68 + c4);
#pragma unroll
            for (int pp = 0; pp < 2; pp++) {
                ulonglong2 wa = *(const ulonglong2*)&wbase[(p+pp)*4];
                ulonglong2 wb = *(const ulonglong2*)&wbase[(p+pp)*4 + 2];
#pragma unroll
                for (int ee = 0; ee < 3; ee++) {
                    ull c2 = pp ? cv[ee].y : cv[ee].x;
                    ffma2(acc[ee][0], c2, wa.x);
                    ffma2(acc[ee][1], c2, wa.y);
                    ffma2(acc[ee][2], c2, wb.x);
                    ffma2(acc[ee][3], c2, wb.y);
                }
            }
        }
        const __half* npcb = &sNPC[cur*3456];
#pragma unroll
        for (int ee = 0; ee < 3; ee++) {
            int le = e0 + ee, e = eb + le, ln = le / KNBR;
            uint2 nu = *(const uint2*)&npcb[le*72 + j0];
            float2 n01 = __half22float2(*(__half2*)&nu.x);
            float2 n23 = __half22float2(*(__half2*)&nu.y);
            float4 sa = *(const float4*)&sPS[ln*68 + j0];
            float m = sM[le];
            float2 u;
            float o0, o1, o2, o3;
            u = unpack2(acc[ee][0]); o0 = u.x+u.y + bj.x + sa.x + n01.x;
            u = unpack2(acc[ee][1]); o1 = u.x+u.y + bj.y + sa.y + n01.y;
            u = unpack2(acc[ee][2]); o2 = u.x+u.y + bj.z + sa.z + n23.x;
            u = unpack2(acc[ee][3]); o3 = u.x+u.y + bj.w + sa.w + n23.y;
            __half2 h0 = __floats2half2_rn(o0, o1);
            __half2 h1 = __floats2half2_rn(o2, o3);
            uint2 ou; ou.x = *(unsigned*)&h0; ou.y = *(unsigned*)&h1;
            *(uint2*)&g_elinh[(size_t)e*64 + j0] = ou;
            pS[0] += o0*m; pQ[0] += o0*o0*m;
            pS[1] += o1*m; pQ[1] += o1*o1*m;
            pS[2] += o2*m; pQ[2] += o2*o2*m;
            pS[3] += o3*m; pQ[3] += o3*o3*m;
        }
    }
#pragma unroll
    for (int i = 0; i < 4; i++) {
        pS[i] += __shfl_down_sync(0xffffffffu, pS[i], 16);
        pQ[i] += __shfl_down_sync(0xffffffffu, pQ[i], 16);
    }
    __syncthreads();
    if ((t & 31) < 16) {
#pragma unroll
        for (int i = 0; i < 4; i++) {
            atomicAdd(&sSum[j0+i], pS[i]);
            atomicAdd(&sSsq[j0+i], pQ[i]);
        }
    }
    __syncthreads();
    if (t < 64) {
        atomicAdd(&g_sumE[t], (double)sSum[t]);
        atomicAdd(&g_ssqE[t], (double)sSsq[t]);
    }
}

// row c (128..191) weight for fused att|val col j in [0,128)
__device__ __forceinline__ float wrow3(const float* W1, const float* Wv,
                                       int crow, int j) {
    if (j < 64) return W1[((j>>4)*192 + crow)*16 + (j&15)];
    int jv = j - 64;
    return Wv[((jv>>4)*192 + crow)*16 + (jv&15)];
}

// ---------------- K3: HMMA fused edge-update + attention + value -----------
// persistent, 384 threads (12 warps), 2 CTAs/SM, tile = 4 nodes (48 edges).
// GEMV 48x128x64 on mma.sync.m16n8k16 fp16->fp32.
// warp w: m = w%3 (16 edges), g = w/3 (32 cols); g<2 att, g>=2 val.
__global__ __launch_bounds__(384,2) void k3_att(
    const float* __restrict__ edgef, const int* __restrict__ nbr,
    const float* __restrict__ nmask,
    const float* __restrict__ W1, const float* __restrict__ b1,
    const float* __restrict__ W2,
    const float* __restrict__ Wv, const float* __restrict__ bv,
    const float* __restrict__ gE, const float* __restrict__ bEbn,
    float* __restrict__ out_edges)
{
    extern __shared__ float smem[];
    __half* sWh  = (__half*)smem;                 // 128*72 halves  (18432B)
    __half* sCh  = sWh + 9216;                    // 48*72 halves   (6912B)
    float*  sE   = (float*)(sCh + 3456);          // 2 * 48*68      (26112B)
    __half* sNAV = (__half*)(sE + 2*3264);        // 2 * 48*136     (26112B)
    __half* sEL  = sNAV + 2*6528;                 // 2 * 48*64      (12288B)
    float*  sPS  = (float*)(sEL + 2*3072);        // 4*132          (2112B)
    float*  sLog = sPS + 528;                     // 192
    float*  sM   = sLog + 192;                    // 48
    int*    sNI  = (int*)(sM + 48);               // 2*48
    float*  sCoef= (float*)(sNI + 96);            // 128
    float*  sSum = sCoef + 128;                   // 64
    float*  sSsq = sSum + 64;                     // 64

    int t = threadIdx.x;
    // fp16 weights: sWh[j][c], row stride 72 halves (conflict-free ldmatrix)
    for (int idx = t; idx < 8192; idx += 384) {
        int j = idx >> 6, c = idx & 63;
        sWh[j*72 + c] = __float2half(wrow3(W1, Wv, 128 + c, j));
    }
    if (t < 64) {   // inline edge-BN coefs
        float cnt = (float)g_cnt;
        float s = (float)g_sumE[t], q = (float)g_ssqE[t];
        float mean = s / cnt, var = q / cnt - mean*mean;
        float inv = rsqrtf(var + EPSV);
        float sc = gE[t] * inv;
        sCoef[t] = sc;
        sCoef[64 + t] = bEbn[t] - mean*sc;
        sSum[t] = 0.f; sSsq[t] = 0.f;
    }

    int wid = t >> 5, l = t & 31;
    int m = wid % 3, g = wid / 3;        // m-tile, col-group
    int isAtt = (g < 2);
    int r0 = l >> 2, r1 = r0 + 8;
    int cq = (l & 3) * 2;

    // per-thread fixed columns: j(nu,c) = g*32 + nu*8 + cq + c
    float c1r[8], c2r[8];                // att: b1,W2 ; val: bv,-
#pragma unroll
    for (int nu = 0; nu < 4; nu++)
#pragma unroll
        for (int c = 0; c < 2; c++) {
            int j = g*32 + nu*8 + cq + c;
            if (isAtt) { c1r[nu*2+c] = b1[j]; c2r[nu*2+c] = W2[j]; }
            else       { c1r[nu*2+c] = bv[j - 64]; c2r[nu*2+c] = 0.f; }
        }

    float pS8[8], pQ8[8];
#pragma unroll
    for (int i = 0; i < 8; i++) { pS8[i] = 0.f; pQ8[i] = 0.f; }

    const int GRID = gridDim.x;
    const int NT = N_NODES / 4;    // 12500
    int bid = blockIdx.x;

    // prolog
    if (t < 12) CP16(su32(&sNI[t*4]), &nbr[bid*48 + t*4]);
    CPCOMMIT(); CPWAIT0();
    __syncthreads();
    {
        for (int i = t; i < 768; i += 384) {
            int le = i >> 4, c4 = (i & 15) << 2;
            CP16(su32(&sE[le*68 + c4]), &edgef[(size_t)(bid*48+le)*64 + c4]);
        }
        for (int i = t; i < 768; i += 384) {
            int le = i >> 4, c8 = (i & 15) * 8;
            int nb = sNI[le];
            CP16(su32(&sNAV[le*136 + c8]), &g_pchAV[(size_t)nb*128 + c8]);
        }
        for (int i = t; i < 384; i += 384) {
            int le = i >> 3, c8 = (i & 7) * 8;
            CP16(su32(&sEL[le*64 + c8]), &g_elinh[(size_t)(bid*48+le)*64 + c8]);
        }
        int T1 = bid + GRID;
        if (T1 < NT && t < 12)
            CP16(su32(&sNI[48 + t*4]), &nbr[T1*48 + t*4]);
    }
    CPCOMMIT();

    int w = 0;
    for (int T = bid; T < NT; T += GRID, w ^= 1) {
        int cur = w, nxt = w ^ 1;
        CPWAIT0();
        __syncthreads();

        int Tn = T + GRID;
        if (Tn < NT) {
            for (int i = t; i < 768; i += 384) {
                int le = i >> 4, c4 = (i & 15) << 2;
                CP16(su32(&sE[nxt*3264 + le*68 + c4]),
                     &edgef[(size_t)(Tn*48+le)*64 + c4]);
            }
            for (int i = t; i < 768; i += 384) {
                int le = i >> 4, c8 = (i & 15) * 8;
                int nb = sNI[nxt*48 + le];
                CP16(su32(&sNAV[nxt*6528 + le*136 + c8]),
                     &g_pchAV[(size_t)nb*128 + c8]);
            }
            for (int i = t; i < 384; i += 384) {
                int le = i >> 3, c8 = (i & 7) * 8;
                CP16(su32(&sEL[nxt*3072 + le*64 + c8]),
                     &g_elinh[(size_t)(Tn*48+le)*64 + c8]);
            }
            int Tn2 = Tn + GRID;
            if (Tn2 < NT && t < 12)
                CP16(su32(&sNI[cur*48 + t*4]), &nbr[Tn2*48 + t*4]);
            CPCOMMIT();
        }

        int n0 = T*4, eb = n0*KNBR;
        if (t < 48) {
            int e = eb + t, n = n0 + t/KNBR, k = t % KNBR;
            float L = g_lens[n];
            sM[t] = (L > 0.f) ? nmask[e] : (k == 0 ? 1.f : 0.f);
        }
        if (t < 128) {
            int node = t >> 5, q = (t & 31) << 2;
            *(float4*)&sPS[node*132 + q] =
                *(const float4*)&g_pc[(size_t)(n0+node)*384 + 128 + q];
        }
        __syncthreads();

        // edge_updated: fp32 -> out_edges, fp16 -> sCh
        const float*  eE = &sE[cur*3264];
        const __half* eL = &sEL[cur*3072];
        for (int i = t; i < 768; i += 384) {
            int le = i >> 4, j = (i & 15) << 2;
            int e = eb + le;
            float mm = sM[le];
            uint2 elu = *(const uint2*)&eL[le*64 + j];
            float2 el01 = __half22float2(*(__half2*)&elu.x);
            float2 el23 = __half22float2(*(__half2*)&elu.y);
            float4 ef = *(const float4*)&eE[le*68 + j];
            float4 sc = *(const float4*)&sCoef[j];
            float4 sh = *(const float4*)&sCoef[64 + j];
            float4 eu;
            eu.x = fsp(ef.x + (el01.x*sc.x + sh.x)*mm);
            eu.y = fsp(ef.y + (el01.y*sc.y + sh.y)*mm);
            eu.z = fsp(ef.z + (el23.x*sc.z + sh.z)*mm);
            eu.w = fsp(ef.w + (el23.y*sc.w + sh.w)*mm);
            *(float4*)&out_edges[(size_t)e*64 + j] = eu;
            __half2 q0 = __floats2half2_rn(eu.x, eu.y);
            __half2 q1 = __floats2half2_rn(eu.z, eu.w);
            uint2 qq; qq.x = *(unsigned*)&q0; qq.y = *(unsigned*)&q1;
            *(uint2*)&sCh[le*72 + j] = qq;
        }
        __syncthreads();

        // HMMA GEMV: D[48x128] = sCh[48x64] @ sWh^T
        float dacc[4][4];
#pragma unroll
        for (int a = 0; a < 4; a++)
#pragma unroll
            for (int b = 0; b < 4; b++) dacc[a][b] = 0.f;
        int l16 = l & 15;
#pragma unroll
        for (int kk = 0; kk < 4; kk++) {
            unsigned a4[4];
            ldm_x4(a4[0], a4[1], a4[2], a4[3],
                su32(&sCh[(m*16 + l16)*72 + kk*16 + (l >> 4)*8]));
#pragma unroll
            for (int nu = 0; nu < 4; nu++) {
                unsigned b0, b1x;
                ldm_x2(b0, b1x,
                    su32(&sWh[(g*32 + nu*8 + (l16 & 7))*72 + kk*16 + ((l16 >> 3)&1)*8]));
                mma16816(dacc[nu], a4, b0, b1x);
            }
        }

        const __half* nav = &sNAV[cur*6528];
        if (isAtt) {
            float lpAcc[4] = {0.f, 0.f, 0.f, 0.f};   // [rsel*2 + headsel]
#pragma unroll
            for (int nu = 0; nu < 4; nu++) {
                int hs = nu >> 1;
#pragma unroll
                for (int rc = 0; rc < 4; rc++) {
                    int rsel = rc >> 1, c = rc & 1;
                    int r = rsel ? r1 : r0;
                    int le = m*16 + r, ln = le / KNBR;
                    int j = g*32 + nu*8 + cq + c;
                    float h1v = fsp(dacc[nu][rc] + c1r[nu*2+c]
                                    + sPS[ln*132 + j]
                                    + __half2float(nav[le*136 + j]));
                    lpAcc[rsel*2 + hs] += h1v * c2r[nu*2+c];
                }
            }
#pragma unroll
            for (int i = 0; i < 4; i++) {
                lpAcc[i] += __shfl_xor_sync(0xffffffffu, lpAcc[i], 1);
                lpAcc[i] += __shfl_xor_sync(0xffffffffu, lpAcc[i], 2);
            }
            if ((l & 3) == 0) {
                sLog[(m*16+r0)*4 + g*2 + 0] = lpAcc[0];
                sLog[(m*16+r0)*4 + g*2 + 1] = lpAcc[1];
                sLog[(m*16+r1)*4 + g*2 + 0] = lpAcc[2];
                sLog[(m*16+r1)*4 + g*2 + 1] = lpAcc[3];
            }
        } else {
            // v = d + bv + self + nbr (in place in dacc)
#pragma unroll
            for (int nu = 0; nu < 4; nu++)
#pragma unroll
                for (int rc = 0; rc < 4; rc++) {
                    int rsel = rc >> 1, c = rc & 1;
                    int r = rsel ? r1 : r0;
                    int le = m*16 + r, ln = le / KNBR;
                    int jv = (g-2)*32 + nu*8 + cq + c;
                    dacc[nu][rc] += c1r[nu*2+c] + sPS[ln*132 + 64 + jv]
                                  + __half2float(nav[le*136 + 64 + jv]);
                }
        }
        __syncthreads();   // logits ready

        if (!isAtt) {
            // normalizer for lane's combo q: (rowsel=q>>1, headsel=q&1)
            int q = l & 3;
            int rq = (q >> 1) ? r1 : r0;
            int nodeq = (m*16 + rq) / KNBR;
            int hq = (g-2)*2 + (q & 1);
            int le0 = nodeq * KNBR;
            float mx = -1e30f;
#pragma unroll
            for (int k = 0; k < KNBR; k++) {
                int le = le0 + k;
                if (sM[le] > 0.f) mx = fmaxf(mx, sLog[le*4 + hq]);
            }
            float ss = 0.f;
#pragma unroll
            for (int k = 0; k < KNBR; k++) {
                int le = le0 + k;
                ss += (sM[le] > 0.f) ? __expf(sLog[le*4 + hq] - mx) : 0.f;
            }
            float inv = 1.f / ss;
            float mxq[4], invq[4];
            int lb = l & ~3;
#pragma unroll
            for (int i = 0; i < 4; i++) {
                mxq[i]  = __shfl_sync(0xffffffffu, mx,  lb + i);
                invq[i] = __shfl_sync(0xffffffffu, inv, lb + i);
            }
#pragma unroll
            for (int nu = 0; nu < 4; nu++) {
                int hs = nu >> 1;
                int h = (g-2)*2 + hs;
#pragma unroll
                for (int rsel = 0; rsel < 2; rsel++) {
                    int r = rsel ? r1 : r0;
                    int le = m*16 + r, e = eb + le;
                    int qi = rsel*2 + hs;
                    float mm = sM[le];
                    float a = (mm > 0.f)
                        ? __expf(sLog[le*4 + h] - mxq[qi]) * invq[qi] : 0.f;
                    float p0 = a * dacc[nu][rsel*2 + 0];
                    float p1 = a * dacc[nu][rsel*2 + 1];
                    __half2 hp = __floats2half2_rn(p0, p1);
                    *(unsigned*)&g_ph[(size_t)e*64 + (g-2)*32 + nu*8 + cq] =
                        *(unsigned*)&hp;
                    pS8[nu*2+0] += p0*mm; pQ8[nu*2+0] += p0*p0*mm;
                    pS8[nu*2+1] += p1*mm; pQ8[nu*2+1] += p1*p1*mm;
                }
            }
        }
    }
    __syncthreads();
    if (!isAtt) {
#pragma unroll
        for (int nu = 0; nu < 4; nu++)
#pragma unroll
            for (int c = 0; c < 2; c++) {
                int jv = (g-2)*32 + nu*8 + cq + c;
                atomicAdd(&sSum[jv], pS8[nu*2+c]);
                atomicAdd(&sSsq[jv], pQ8[nu*2+c]);
            }
    }
    __syncthreads();
    if (t < 64) {
        atomicAdd(&g_sumP[t], (double)sSum[t]);
        atomicAdd(&g_ssqP[t], (double)sSsq[t]);
    }
}

// ---------------- K5: head_feats + pooled + out-BN stats ----------------
__global__ __launch_bounds__(256) void k5_pool(
    const float* __restrict__ nmask,
    const float* __restrict__ gP, const float* __restrict__ bP)
{
    __shared__ float scf[64], shf[64];
    int t = threadIdx.x;
    if (t < 64) {
        float cnt = (float)g_cnt;
        float s = (float)g_sumP[t], q = (float)g_ssqP[t];
        float mean = s / cnt, var = q / cnt - mean*mean;
        float inv = rsqrtf(var + EPSV);
        float sc = gP[t] * inv;
        scf[t] = sc; shf[t] = bP[t] - mean*sc;
    }
    __syncthreads();
    int j = t & 63, nl = t >> 6;
    int n0 = blockIdx.x * 64;
    float scP = scf[j], shP = shf[j];
    float psum = 0.f, pssq = 0.f;
    for (int i = 0; i < 16; i++) {
        int n = n0 + nl*16 + i;
        if (n >= N_NODES) break;
        float L = g_lens[n];
        float pooled = 0.f;
#pragma unroll
        for (int k = 0; k < KNBR; k++) {
            float m = (L > 0.f) ? nmask[n*KNBR + k] : (k == 0 ? 1.f : 0.f);
            float p = __half2float(g_ph[(size_t)(n*KNBR + k)*64 + j]);
            pooled += fsp(p*scP + shP) * m;
        }
        g_pooled[n*64 + j] = pooled;
        psum += pooled; pssq += pooled*pooled;
    }
    __shared__ float red[256], red2[256];
    red[t] = psum; red2[t] = pssq;
    __syncthreads();
    if (nl == 0) {
        float s = red[j] + red[64+j] + red[128+j] + red[192+j];
        float q = red2[j] + red2[64+j] + red2[128+j] + red2[192+j];
        atomicAdd(&g_sumO[j], (double)s);
        atomicAdd(&g_ssqO[j], (double)q);
    }
}

// ---------------- K7: residual + out-BN ----------------
__global__ __launch_bounds__(256) void k7_out(
    const float* __restrict__ nodef,
    const float* __restrict__ gO, const float* __restrict__ bO,
    float* __restrict__ out_nodes)
{
    __shared__ float scf[64], shf[64];
    int t = threadIdx.x;
    if (t < 64) {
        float cnt = (float)N_NODES;
        float s = (float)g_sumO[t], q = (float)g_ssqO[t];
        float mean = s / cnt, var = q / cnt - mean*mean;
        float inv = rsqrtf(var + EPSV);
        float sc = gO[t] * inv;
        scf[t] = sc; shf[t] = bO[t] - mean*sc;
    }
    __syncthreads();
    int i = blockIdx.x * 256 + t;
    if (i < N_NODES*64) {
        int j = i & 63;
        out_nodes[i] = nodef[i] + scf[j]*g_pooled[i] + shf[j];
    }
}

// ---------------- launch ----------------
extern "C" void kernel_launch(void* const* d_in, const int* in_sizes, int n_in,
                              void* d_out, int out_size)
{
    const float* nodef  = (const float*)d_in[0];
    const float* edgef  = (const float*)d_in[1];
    const int*   nbr    = (const int*)d_in[2];
    const float* nmask  = (const float*)d_in[3];
    const float* W_edge = (const float*)d_in[4];
    const float* b_edge = (const float*)d_in[5];
    const float* g_ebn  = (const float*)d_in[6];
    const float* b_ebn  = (const float*)d_in[7];
    const float* W1     = (const float*)d_in[8];
    const float* b1     = (const float*)d_in[9];
    const float* W2     = (const float*)d_in[10];
    const float* Wv     = (const float*)d_in[12];
    const float* bv     = (const float*)d_in[13];
    const float* g_abn  = (const float*)d_in[14];
    const float* b_abn  = (const float*)d_in[15];
    const float* g_obn  = (const float*)d_in[16];
    const float* b_obn  = (const float*)d_in[17];

    float* out_nodes = (float*)d_out;
    float* out_edges = out_nodes + (size_t)N_NODES * 64;

    const int smemP = (96*130 + 16*33) * 8;
    const int smem1 = 2080*8 + 2*3264*4 + 2*3456*2 +
                      (272 + 48 + 128) * 4 + 96*4;
    const int smem3 = 9216*2 + 3456*2 + 2*3264*4 + 2*6528*2 + 2*3072*2 +
                      (528 + 192 + 48 + 128 + 128) * 4 + 96*4;   // ~94.3KB
    static int inited = 0;
    if (!inited) {
        cudaFuncSetAttribute(k_pre,  cudaFuncAttributeMaxDynamicSharedMemorySize, smemP);
        cudaFuncSetAttribute(k1_edge, cudaFuncAttributeMaxDynamicSharedMemorySize, smem1);
        cudaFuncSetAttribute(k3_att,  cudaFuncAttributeMaxDynamicSharedMemorySize, smem3);
        inited = 1;
    }

    k_lens<<<LENS_BLOCKS, 256>>>(nmask);                               // 1
    k_pre<<<2*NSM, 384, smemP>>>(nodef, W_edge, W1, Wv);               // 2
    k1_edge<<<3*NSM, 256, smem1>>>(edgef, nbr, nmask, W_edge, b_edge,
                                   g_ebn, b_ebn);                      // 3
    k3_att<<<2*NSM, 384, smem3>>>(edgef, nbr, nmask, W1, b1, W2, Wv, bv,
                                  g_ebn, b_ebn, out_edges);            // 4 -> profiled
    k5_pool<<<(N_NODES + 63)/64, 256>>>(nmask, g_abn, b_abn);          // 5
    k7_out<<<(N_NODES*64 + 255)/256, 256>>>(nodef, g_obn, b_obn,
                                            out_nodes);                // 6
}

// round 15
// speedup vs baseline: 1.7062x; 1.0828x over previous
#include <cuda_runtime.h>
#include <cuda_fp16.h>
#include <math.h>

#define N_NODES 50000
#define KNBR    12
#define NEDGE   (N_NODES*KNBR)
#define EPSV    1e-5f
#define NSM     152
#define LENS_BLOCKS 196

typedef unsigned long long ull;

// ---------------- device scratch ----------------
__device__ __half g_elinh[NEDGE*64];    // e_lin fp16 (k1 -> k3)
__device__ __half g_ph[NEDGE*64];       // p fp16 (k3 -> k5)
__device__ float  g_pooled[N_NODES*64];
__device__ float  g_pc[N_NODES*384];    // f32: cols 0-63 (k1 self), 128-255 (k3 self)
__device__ __half g_pch1[N_NODES*64];   // fp16: k1 nbr contribution
__device__ __half g_pchAV[N_NODES*128]; // fp16: k3 att|val nbr contribution
__device__ float  g_lens[N_NODES];
__device__ float  g_cntPart[LENS_BLOCKS];
__device__ double g_sumE[64], g_ssqE[64];
__device__ double g_sumP[64], g_ssqP[64];
__device__ double g_sumO[64], g_ssqO[64];
__device__ double g_cnt;
__device__ unsigned int g_tick = 0;

// ---------------- f32x2 helpers ----------------
__device__ __forceinline__ ull pack2(float x, float y) {
    ull r; asm("mov.b64 %0,{%1,%2};" : "=l"(r) : "f"(x), "f"(y)); return r;
}
__device__ __forceinline__ void ffma2(ull& d, ull a, ull b) {
    asm("fma.rn.f32x2 %0,%1,%2,%0;" : "+l"(d) : "l"(a), "l"(b));
}
__device__ __forceinline__ float2 unpack2(ull v) {
    float2 r; asm("mov.b64 {%0,%1},%2;" : "=f"(r.x), "=f"(r.y) : "l"(v)); return r;
}

// ---------------- cp.async helpers ----------------
__device__ __forceinline__ unsigned su32(const void* p) {
    return (unsigned)__cvta_generic_to_shared(p);
}
#define CP16(dst, src) asm volatile( \
    "cp.async.cg.shared.global [%0], [%1], 16;" :: "r"(dst), "l"(src) : "memory")
#define CPCOMMIT() asm volatile("cp.async.commit_group;" ::: "memory")
#define CPWAIT0()  asm volatile("cp.async.wait_group 0;" ::: "memory")

// ---------------- mma helpers ----------------
__device__ __forceinline__ void ldm_x4(unsigned& a0, unsigned& a1,
                                       unsigned& a2, unsigned& a3, unsigned addr) {
    asm volatile("ldmatrix.sync.aligned.m8n8.x4.shared.b16 {%0,%1,%2,%3}, [%4];"
        : "=r"(a0), "=r"(a1), "=r"(a2), "=r"(a3) : "r"(addr));
}
__device__ __forceinline__ void ldm_x2(unsigned& b0, unsigned& b1, unsigned addr) {
    asm volatile("ldmatrix.sync.aligned.m8n8.x2.shared.b16 {%0,%1}, [%2];"
        : "=r"(b0), "=r"(b1) : "r"(addr));
}
__device__ __forceinline__ void mma16816(float* d, const unsigned* a,
                                         unsigned b0, unsigned b1) {
    asm volatile("mma.sync.aligned.m16n8k16.row.col.f32.f16.f16.f32 "
        "{%0,%1,%2,%3}, {%4,%5,%6,%7}, {%8,%9}, {%0,%1,%2,%3};"
        : "+f"(d[0]), "+f"(d[1]), "+f"(d[2]), "+f"(d[3])
        : "r"(a[0]), "r"(a[1]), "r"(a[2]), "r"(a[3]), "r"(b0), "r"(b1));
}

// ---------------- softplus on MUFU pipe ----------------
__device__ __forceinline__ float fsp(float x) {
    return fmaxf(x, 0.f) + __logf(1.f + __expf(-fabsf(x)));
}

// ---------------- K_lens ----------------
__global__ void k_lens(const float* __restrict__ nmask) {
    int n = blockIdx.x * 256 + threadIdx.x;
    int tid = threadIdx.x;
    float eff = 0.f;
    if (n < N_NODES) {
        float L = 0.f;
#pragma unroll
        for (int k = 0; k < KNBR; k++) L += nmask[n*KNBR + k];
        g_lens[n] = L;
        eff = (L > 0.f) ? L : 1.0f;
    }
    __shared__ float red[256];
    __shared__ unsigned int tk;
    red[tid] = eff;
    __syncthreads();
    for (int s = 128; s > 0; s >>= 1) {
        if (tid < s) red[tid] += red[tid + s];
        __syncthreads();
    }
    if (tid == 0) g_cntPart[blockIdx.x] = red[0];
    __threadfence();
    if (tid == 0) tk = atomicInc(&g_tick, gridDim.x - 1);
    __syncthreads();
    if (tk == gridDim.x - 1) {
        if (tid < 64) {
            g_sumE[tid] = 0.0; g_ssqE[tid] = 0.0;
            g_sumP[tid] = 0.0; g_ssqP[tid] = 0.0;
            g_sumO[tid] = 0.0; g_ssqO[tid] = 0.0;
        }
        if (tid == 64) {
            double s = 0.0;
            for (int i = 0; i < LENS_BLOCKS; i++) s += (double)g_cntPart[i];
            g_cnt = s;
        }
    }
}

// ---------------- weight catalog for pre-GEMM ----------------
__device__ __forceinline__ float wcat(const float* We, const float* W1,
                                      const float* Wv, int c, int j) {
    if (j < 64)  return We[c*64 + j];
    if (j < 128) return We[(64+c)*64 + (j-64)];
    if (j < 192) { int jj = j-128; return W1[((jj>>4)*192 + c)*16 + (jj&15)]; }
    if (j < 256) { int jj = j-192; return Wv[((jj>>4)*192 + c)*16 + (jj&15)]; }
    if (j < 320) { int jj = j-256; return W1[((jj>>4)*192 + 64 + c)*16 + (jj&15)]; }
    { int jj = j-320; return Wv[((jj>>4)*192 + 64 + c)*16 + (jj&15)]; }
}

// ---------------- K_pre ----------------
__global__ __launch_bounds__(384,2) void k_pre(
    const float* __restrict__ nodef,
    const float* __restrict__ We, const float* __restrict__ W1,
    const float* __restrict__ Wv)
{
    extern __shared__ float smem[];
    ull* sW  = (ull*)smem;            // 96 jq * 130
    ull* sX  = sW + 96*130;           // 16 nodes * 33

    int t = threadIdx.x;
    for (int idx = t; idx < 12288; idx += 384) {
        int jq = idx >> 7, r = idx & 127, p = r >> 2, i = r & 3;
        int j = jq*4 + i, c0 = 2*p;
        sW[jq*130 + p*4 + i] = pack2(wcat(We,W1,Wv,c0,j), wcat(We,W1,Wv,c0+1,j));
    }

    int jq = t % 96, ng = t / 96;
    const int GRID = gridDim.x;
    const int NT = N_NODES / 16;  // 3125
    for (int tile = blockIdx.x; tile < NT; tile += GRID) {
        int n0 = tile * 16;
        __syncthreads();
        for (int idx = t; idx < 512; idx += 384) {
            int node = idx >> 5, p = idx & 31;
            float2 x2 = *(const float2*)&nodef[(n0+node)*64 + 2*p];
            sX[node*33 + p] = pack2(x2.x, x2.y);
        }
        __syncthreads();

        ull acc[4][4];
#pragma unroll
        for (int a = 0; a < 4; a++) { acc[a][0]=0; acc[a][1]=0; acc[a][2]=0; acc[a][3]=0; }
        const ull* wp = &sW[jq*130];
#pragma unroll 4
        for (int p = 0; p < 32; p++) {
            ulonglong2 w01 = *(const ulonglong2*)&wp[p*4];
            ulonglong2 w23 = *(const ulonglong2*)&wp[p*4 + 2];
#pragma unroll
            for (int ee = 0; ee < 4; ee++) {
                ull xv = sX[(ng*4+ee)*33 + p];
                ffma2(acc[ee][0], xv, w01.x);
                ffma2(acc[ee][1], xv, w01.y);
                ffma2(acc[ee][2], xv, w23.x);
                ffma2(acc[ee][3], xv, w23.y);
            }
        }
#pragma unroll
        for (int ee = 0; ee < 4; ee++) {
            int n = n0 + ng*4 + ee;
            float2 u0 = unpack2(acc[ee][0]), u1 = unpack2(acc[ee][1]);
            float2 u2 = unpack2(acc[ee][2]), u3 = unpack2(acc[ee][3]);
            float4 o;
            o.x = u0.x+u0.y; o.y = u1.x+u1.y; o.z = u2.x+u2.y; o.w = u3.x+u3.y;
            if (jq < 16 || (jq >= 32 && jq < 64)) {
                *(float4*)&g_pc[(size_t)n*384 + jq*4] = o;
            } else {
                __half2 h0 = __floats2half2_rn(o.x, o.y);
                __half2 h1 = __floats2half2_rn(o.z, o.w);
                uint2 uu; uu.x = *(unsigned*)&h0; uu.y = *(unsigned*)&h1;
                if (jq < 32)
                    *(uint2*)&g_pch1[(size_t)n*64 + (jq-16)*4] = uu;
                else
                    *(uint2*)&g_pchAV[(size_t)n*128 + (jq-64)*4] = uu;
            }
        }
    }
}

// ---------------- K1: HMMA e_lin (fp16 out) ---------------------------------
// persistent, 384 threads (12 warps), 2 CTAs/SM, tile = 4 nodes (48 edges).
// GEMV 48x64x64 via mma.sync.m16n8k16. warp w: m=w%3 (16 edges), g=w/3 (16 cols).
__global__ __launch_bounds__(384,2) void k1_edge(
    const float* __restrict__ edgef, const int* __restrict__ nbr,
    const float* __restrict__ nmask, const float* __restrict__ W,
    const float* __restrict__ bE,
    const float* __restrict__ gE, const float* __restrict__ bEbn)
{
    extern __shared__ float smem[];
    __half* sWh  = (__half*)smem;                 // 64*72 halves   (9216B)
    __half* sCh  = sWh + 4608;                    // 48*72 halves   (6912B)
    float*  sE   = (float*)(sCh + 3456);          // 2 * 48*68      (26112B)
    __half* sNPC = (__half*)(sE + 2*3264);        // 2 * 48*72      (13824B)
    float*  sPS  = (float*)(sNPC + 2*3456);       // 4*68           (1088B)
    float*  sM   = sPS + 272;                     // 48
    int*    sNI  = (int*)(sM + 48);               // 2*48
    float*  sSum = (float*)(sNI + 96);            // 64
    float*  sSsq = sSum + 64;                     // 64

    int t = threadIdx.x;
    // fp16 weights: sWh[j][c] = W_edge[(128+c)*64 + j]
    for (int idx = t; idx < 4096; idx += 384) {
        int j = idx >> 6, c = idx & 63;
        sWh[j*72 + c] = __float2half(W[(128 + c)*64 + j]);
    }
    if (t < 64) { sSum[t] = 0.f; sSsq[t] = 0.f; }

    int wid = t >> 5, l = t & 31;
    int m = wid % 3, g = wid / 3;         // m-tile (16 edges), col-group (16 cols)
    int r0 = l >> 2, r1 = r0 + 8;
    int cq = (l & 3) * 2;
    int l16 = l & 15;

    float bj4[4];                          // bias for j = g*16 + nu*8 + cq + c
#pragma unroll
    for (int nu = 0; nu < 2; nu++)
#pragma unroll
        for (int c = 0; c < 2; c++)
            bj4[nu*2+c] = bE[g*16 + nu*8 + cq + c];

    float pS[4] = {0,0,0,0}, pQ[4] = {0,0,0,0};

    const int GRID = gridDim.x;
    const int NT = NEDGE / 48;   // 12500
    int bid = blockIdx.x;

    // prolog
    if (t < 12) CP16(su32(&sNI[t*4]), &nbr[bid*48 + t*4]);
    CPCOMMIT(); CPWAIT0();
    __syncthreads();
    {
        for (int i = t; i < 768; i += 384) {
            int le = i >> 4, c4 = (i & 15) << 2;
            CP16(su32(&sE[le*68 + c4]), &edgef[(size_t)(bid*48+le)*64 + c4]);
        }
        for (int i = t; i < 384; i += 384) {
            int le = i >> 3, c8 = (i & 7) * 8;
            int nb = sNI[le];
            CP16(su32(&sNPC[le*72 + c8]), &g_pch1[(size_t)nb*64 + c8]);
        }
        int T1 = bid + GRID;
        if (T1 < NT && t < 12)
            CP16(su32(&sNI[48 + t*4]), &nbr[T1*48 + t*4]);
    }
    CPCOMMIT();

    int w = 0;
    for (int T = bid; T < NT; T += GRID, w ^= 1) {
        int cur = w, nxt = w ^ 1;
        CPWAIT0();
        __syncthreads();

        int Tn = T + GRID;
        if (Tn < NT) {
            for (int i = t; i < 768; i += 384) {
                int le = i >> 4, c4 = (i & 15) << 2;
                CP16(su32(&sE[nxt*3264 + le*68 + c4]),
                     &edgef[(size_t)(Tn*48+le)*64 + c4]);
            }
            for (int i = t; i < 384; i += 384) {
                int le = i >> 3, c8 = (i & 7) * 8;
                int nb = sNI[nxt*48 + le];
                CP16(su32(&sNPC[nxt*3456 + le*72 + c8]),
                     &g_pch1[(size_t)nb*64 + c8]);
            }
            int Tn2 = Tn + GRID;
            if (Tn2 < NT && t < 12)
                CP16(su32(&sNI[cur*48 + t*4]), &nbr[Tn2*48 + t*4]);
            CPCOMMIT();
        }

        int eb = T*48, n0 = T*4;
        if (t < 64) {
            int node = t >> 4, q = (t & 15) << 2;
            *(float4*)&sPS[node*68 + q] =
                *(const float4*)&g_pc[(size_t)(n0+node)*384 + q];
        }
        if (t < 48) {
            int e = eb + t, n = n0 + t/KNBR, k = t % KNBR;
            float L = g_lens[n];
            sM[t] = (L > 0.f) ? nmask[e] : (k == 0 ? 1.f : 0.f);
        }
        // convert staged edgef f32 -> fp16 A-tile
        const float* eE = &sE[cur*3264];
        for (int i = t; i < 768; i += 384) {
            int le = i >> 4, j = (i & 15) << 2;
            float4 v = *(const float4*)&eE[le*68 + j];
            __half2 q0 = __floats2half2_rn(v.x, v.y);
            __half2 q1 = __floats2half2_rn(v.z, v.w);
            uint2 qq; qq.x = *(unsigned*)&q0; qq.y = *(unsigned*)&q1;
            *(uint2*)&sCh[le*72 + j] = qq;
        }
        __syncthreads();

        // HMMA: D[48x64] = sCh[48x64] @ sWh^T
        float dacc[2][4];
#pragma unroll
        for (int a = 0; a < 2; a++) { dacc[a][0]=0; dacc[a][1]=0; dacc[a][2]=0; dacc[a][3]=0; }
#pragma unroll
        for (int kk = 0; kk < 4; kk++) {
            unsigned a4[4];
            ldm_x4(a4[0], a4[1], a4[2], a4[3],
                su32(&sCh[(m*16 + l16)*72 + kk*16 + (l >> 4)*8]));
#pragma unroll
            for (int nu = 0; nu < 2; nu++) {
                unsigned b0, b1x;
                ldm_x2(b0, b1x,
                    su32(&sWh[(g*16 + nu*8 + (l16 & 7))*72 + kk*16 + ((l16 >> 3)&1)*8]));
                mma16816(dacc[nu], a4, b0, b1x);
            }
        }

        // epilogue: bias + self + nbr, fp16 store, masked stats
        const __half* npcb = &sNPC[cur*3456];
#pragma unroll
        for (int nu = 0; nu < 2; nu++) {
#pragma unroll
            for (int rsel = 0; rsel < 2; rsel++) {
                int r = rsel ? r1 : r0;
                int le = m*16 + r, e = eb + le, ln = le / KNBR;
                float mm = sM[le];
                int jb = g*16 + nu*8 + cq;
                float o0 = dacc[nu][rsel*2+0] + bj4[nu*2+0]
                         + sPS[ln*68 + jb]     + __half2float(npcb[le*72 + jb]);
                float o1 = dacc[nu][rsel*2+1] + bj4[nu*2+1]
                         + sPS[ln*68 + jb + 1] + __half2float(npcb[le*72 + jb + 1]);
                __half2 hp = __floats2half2_rn(o0, o1);
                *(unsigned*)&g_elinh[(size_t)e*64 + jb] = *(unsigned*)&hp;
                pS[nu*2+0] += o0*mm; pQ[nu*2+0] += o0*o0*mm;
                pS[nu*2+1] += o1*mm; pQ[nu*2+1] += o1*o1*mm;
            }
        }
    }
    __syncthreads();
#pragma unroll
    for (int nu = 0; nu < 2; nu++)
#pragma unroll
        for (int c = 0; c < 2; c++) {
            int j = g*16 + nu*8 + cq + c;
            atomicAdd(&sSum[j], pS[nu*2+c]);
            atomicAdd(&sSsq[j], pQ[nu*2+c]);
        }
    __syncthreads();
    if (t < 64) {
        atomicAdd(&g_sumE[t], (double)sSum[t]);
        atomicAdd(&g_ssqE[t], (double)sSsq[t]);
    }
}

// row c (128..191) weight for fused att|val col j in [0,128)
__device__ __forceinline__ float wrow3(const float* W1, const float* Wv,
                                       int crow, int j) {
    if (j < 64) return W1[((j>>4)*192 + crow)*16 + (j&15)];
    int jv = j - 64;
    return Wv[((jv>>4)*192 + crow)*16 + (jv&15)];
}

// ---------------- K3: HMMA fused edge-update + attention + value -----------
__global__ __launch_bounds__(384,2) void k3_att(
    const float* __restrict__ edgef, const int* __restrict__ nbr,
    const float* __restrict__ nmask,
    const float* __restrict__ W1, const float* __restrict__ b1,
    const float* __restrict__ W2,
    const float* __restrict__ Wv, const float* __restrict__ bv,
    const float* __restrict__ gE, const float* __restrict__ bEbn,
    float* __restrict__ out_edges)
{
    extern __shared__ float smem[];
    __half* sWh  = (__half*)smem;                 // 128*72 halves  (18432B)
    __half* sCh  = sWh + 9216;                    // 48*72 halves   (6912B)
    float*  sE   = (float*)(sCh + 3456);          // 2 * 48*68      (26112B)
    __half* sNAV = (__half*)(sE + 2*3264);        // 2 * 48*136     (26112B)
    __half* sEL  = sNAV + 2*6528;                 // 2 * 48*64      (12288B)
    float*  sPS  = (float*)(sEL + 2*3072);        // 4*132          (2112B)
    float*  sLog = sPS + 528;                     // 192
    float*  sM   = sLog + 192;                    // 48
    int*    sNI  = (int*)(sM + 48);               // 2*48
    float*  sCoef= (float*)(sNI + 96);            // 128
    float*  sSum = sCoef + 128;                   // 64
    float*  sSsq = sSum + 64;                     // 64

    int t = threadIdx.x;
    for (int idx = t; idx < 8192; idx += 384) {
        int j = idx >> 6, c = idx & 63;
        sWh[j*72 + c] = __float2half(wrow3(W1, Wv, 128 + c, j));
    }
    if (t < 64) {
        float cnt = (float)g_cnt;
        float s = (float)g_sumE[t], q = (float)g_ssqE[t];
        float mean = s / cnt, var = q / cnt - mean*mean;
        float inv = rsqrtf(var + EPSV);
        float sc = gE[t] * inv;
        sCoef[t] = sc;
        sCoef[64 + t] = bEbn[t] - mean*sc;
        sSum[t] = 0.f; sSsq[t] = 0.f;
    }

    int wid = t >> 5, l = t & 31;
    int m = wid % 3, g = wid / 3;
    int isAtt = (g < 2);
    int r0 = l >> 2, r1 = r0 + 8;
    int cq = (l & 3) * 2;

    float c1r[8], c2r[8];
#pragma unroll
    for (int nu = 0; nu < 4; nu++)
#pragma unroll
        for (int c = 0; c < 2; c++) {
            int j = g*32 + nu*8 + cq + c;
            if (isAtt) { c1r[nu*2+c] = b1[j]; c2r[nu*2+c] = W2[j]; }
            else       { c1r[nu*2+c] = bv[j - 64]; c2r[nu*2+c] = 0.f; }
        }

    float pS8[8], pQ8[8];
#pragma unroll
    for (int i = 0; i < 8; i++) { pS8[i] = 0.f; pQ8[i] = 0.f; }

    const int GRID = gridDim.x;
    const int NT = N_NODES / 4;
    int bid = blockIdx.x;

    if (t < 12) CP16(su32(&sNI[t*4]), &nbr[bid*48 + t*4]);
    CPCOMMIT(); CPWAIT0();
    __syncthreads();
    {
        for (int i = t; i < 768; i += 384) {
            int le = i >> 4, c4 = (i & 15) << 2;
            CP16(su32(&sE[le*68 + c4]), &edgef[(size_t)(bid*48+le)*64 + c4]);
        }
        for (int i = t; i < 768; i += 384) {
            int le = i >> 4, c8 = (i & 15) * 8;
            int nb = sNI[le];
            CP16(su32(&sNAV[le*136 + c8]), &g_pchAV[(size_t)nb*128 + c8]);
        }
        for (int i = t; i < 384; i += 384) {
            int le = i >> 3, c8 = (i & 7) * 8;
            CP16(su32(&sEL[le*64 + c8]), &g_elinh[(size_t)(bid*48+le)*64 + c8]);
        }
        int T1 = bid + GRID;
        if (T1 < NT && t < 12)
            CP16(su32(&sNI[48 + t*4]), &nbr[T1*48 + t*4]);
    }
    CPCOMMIT();

    int w = 0;
    for (int T = bid; T < NT; T += GRID, w ^= 1) {
        int cur = w, nxt = w ^ 1;
        CPWAIT0();
        __syncthreads();

        int Tn = T + GRID;
        if (Tn < NT) {
            for (int i = t; i < 768; i += 384) {
                int le = i >> 4, c4 = (i & 15) << 2;
                CP16(su32(&sE[nxt*3264 + le*68 + c4]),
                     &edgef[(size_t)(Tn*48+le)*64 + c4]);
            }
            for (int i = t; i < 768; i += 384) {
                int le = i >> 4, c8 = (i & 15) * 8;
                int nb = sNI[nxt*48 + le];
                CP16(su32(&sNAV[nxt*6528 + le*136 + c8]),
                     &g_pchAV[(size_t)nb*128 + c8]);
            }
            for (int i = t; i < 384; i += 384) {
                int le = i >> 3, c8 = (i & 7) * 8;
                CP16(su32(&sEL[nxt*3072 + le*64 + c8]),
                     &g_elinh[(size_t)(Tn*48+le)*64 + c8]);
            }
            int Tn2 = Tn + GRID;
            if (Tn2 < NT && t < 12)
                CP16(su32(&sNI[cur*48 + t*4]), &nbr[Tn2*48 + t*4]);
            CPCOMMIT();
        }

        int n0 = T*4, eb = n0*KNBR;
        if (t < 48) {
            int e = eb + t, n = n0 + t/KNBR, k = t % KNBR;
            float L = g_lens[n];
            sM[t] = (L > 0.f) ? nmask[e] : (k == 0 ? 1.f : 0.f);
        }
        if (t < 128) {
            int node = t >> 5, q = (t & 31) << 2;
            *(float4*)&sPS[node*132 + q] =
                *(const float4*)&g_pc[(size_t)(n0+node)*384 + 128 + q];
        }
        __syncthreads();

        const float*  eE = &sE[cur*3264];
        const __half* eL = &sEL[cur*3072];
        for (int i = t; i < 768; i += 384) {
            int le = i >> 4, j = (i & 15) << 2;
            int e = eb + le;
            float mm = sM[le];
            uint2 elu = *(const uint2*)&eL[le*64 + j];
            float2 el01 = __half22float2(*(__half2*)&elu.x);
            float2 el23 = __half22float2(*(__half2*)&elu.y);
            float4 ef = *(const float4*)&eE[le*68 + j];
            float4 sc = *(const float4*)&sCoef[j];
            float4 sh = *(const float4*)&sCoef[64 + j];
            float4 eu;
            eu.x = fsp(ef.x + (el01.x*sc.x + sh.x)*mm);
            eu.y = fsp(ef.y + (el01.y*sc.y + sh.y)*mm);
            eu.z = fsp(ef.z + (el23.x*sc.z + sh.z)*mm);
            eu.w = fsp(ef.w + (el23.y*sc.w + sh.w)*mm);
            *(float4*)&out_edges[(size_t)e*64 + j] = eu;
            __half2 q0 = __floats2half2_rn(eu.x, eu.y);
            __half2 q1 = __floats2half2_rn(eu.z, eu.w);
            uint2 qq; qq.x = *(unsigned*)&q0; qq.y = *(unsigned*)&q1;
            *(uint2*)&sCh[le*72 + j] = qq;
        }
        __syncthreads();

        float dacc[4][4];
#pragma unroll
        for (int a = 0; a < 4; a++)
#pragma unroll
            for (int b = 0; b < 4; b++) dacc[a][b] = 0.f;
        int l16 = l & 15;
#pragma unroll
        for (int kk = 0; kk < 4; kk++) {
            unsigned a4[4];
            ldm_x4(a4[0], a4[1], a4[2], a4[3],
                su32(&sCh[(m*16 + l16)*72 + kk*16 + (l >> 4)*8]));
#pragma unroll
            for (int nu = 0; nu < 4; nu++) {
                unsigned b0, b1x;
                ldm_x2(b0, b1x,
                    su32(&sWh[(g*32 + nu*8 + (l16 & 7))*72 + kk*16 + ((l16 >> 3)&1)*8]));
                mma16816(dacc[nu], a4, b0, b1x);
            }
        }

        const __half* nav = &sNAV[cur*6528];
        if (isAtt) {
            float lpAcc[4] = {0.f, 0.f, 0.f, 0.f};
#pragma unroll
            for (int nu = 0; nu < 4; nu++) {
                int hs = nu >> 1;
#pragma unroll
                for (int rc = 0; rc < 4; rc++) {
                    int rsel = rc >> 1, c = rc & 1;
                    int r = rsel ? r1 : r0;
                    int le = m*16 + r, ln = le / KNBR;
                    int j = g*32 + nu*8 + cq + c;
                    float h1v = fsp(dacc[nu][rc] + c1r[nu*2+c]
                                    + sPS[ln*132 + j]
                                    + __half2float(nav[le*136 + j]));
                    lpAcc[rsel*2 + hs] += h1v * c2r[nu*2+c];
                }
            }
#pragma unroll
            for (int i = 0; i < 4; i++) {
                lpAcc[i] += __shfl_xor_sync(0xffffffffu, lpAcc[i], 1);
                lpAcc[i] += __shfl_xor_sync(0xffffffffu, lpAcc[i], 2);
            }
            if ((l & 3) == 0) {
                sLog[(m*16+r0)*4 + g*2 + 0] = lpAcc[0];
                sLog[(m*16+r0)*4 + g*2 + 1] = lpAcc[1];
                sLog[(m*16+r1)*4 + g*2 + 0] = lpAcc[2];
                sLog[(m*16+r1)*4 + g*2 + 1] = lpAcc[3];
            }
        } else {
#pragma unroll
            for (int nu = 0; nu < 4; nu++)
#pragma unroll
                for (int rc = 0; rc < 4; rc++) {
                    int rsel = rc >> 1, c = rc & 1;
                    int r = rsel ? r1 : r0;
                    int le = m*16 + r, ln = le / KNBR;
                    int jv = (g-2)*32 + nu*8 + cq + c;
                    dacc[nu][rc] += c1r[nu*2+c] + sPS[ln*132 + 64 + jv]
                                  + __half2float(nav[le*136 + 64 + jv]);
                }
        }
        __syncthreads();

        if (!isAtt) {
            int q = l & 3;
            int rq = (q >> 1) ? r1 : r0;
            int nodeq = (m*16 + rq) / KNBR;
            int hq = (g-2)*2 + (q & 1);
            int le0 = nodeq * KNBR;
            float mx = -1e30f;
#pragma unroll
            for (int k = 0; k < KNBR; k++) {
                int le = le0 + k;
                if (sM[le] > 0.f) mx = fmaxf(mx, sLog[le*4 + hq]);
            }
            float ss = 0.f;
#pragma unroll
            for (int k = 0; k < KNBR; k++) {
                int le = le0 + k;
                ss += (sM[le] > 0.f) ? __expf(sLog[le*4 + hq] - mx) : 0.f;
            }
            float inv = 1.f / ss;
            float mxq[4], invq[4];
            int lb = l & ~3;
#pragma unroll
            for (int i = 0; i < 4; i++) {
                mxq[i]  = __shfl_sync(0xffffffffu, mx,  lb + i);
                invq[i] = __shfl_sync(0xffffffffu, inv, lb + i);
            }
#pragma unroll
            for (int nu = 0; nu < 4; nu++) {
                int hs = nu >> 1;
                int h = (g-2)*2 + hs;
#pragma unroll
                for (int rsel = 0; rsel < 2; rsel++) {
                    int r = rsel ? r1 : r0;
                    int le = m*16 + r, e = eb + le;
                    int qi = rsel*2 + hs;
                    float mm = sM[le];
                    float a = (mm > 0.f)
                        ? __expf(sLog[le*4 + h] - mxq[qi]) * invq[qi] : 0.f;
                    float p0 = a * dacc[nu][rsel*2 + 0];
                    float p1 = a * dacc[nu][rsel*2 + 1];
                    __half2 hp = __floats2half2_rn(p0, p1);
                    *(unsigned*)&g_ph[(size_t)e*64 + (g-2)*32 + nu*8 + cq] =
                        *(unsigned*)&hp;
                    pS8[nu*2+0] += p0*mm; pQ8[nu*2+0] += p0*p0*mm;
                    pS8[nu*2+1] += p1*mm; pQ8[nu*2+1] += p1*p1*mm;
                }
            }
        }
    }
    __syncthreads();
    if (!isAtt) {
#pragma unroll
        for (int nu = 0; nu < 4; nu++)
#pragma unroll
            for (int c = 0; c < 2; c++) {
                int jv = (g-2)*32 + nu*8 + cq + c;
                atomicAdd(&sSum[jv], pS8[nu*2+c]);
                atomicAdd(&sSsq[jv], pQ8[nu*2+c]);
            }
    }
    __syncthreads();
    if (t < 64) {
        atomicAdd(&g_sumP[t], (double)sSum[t]);
        atomicAdd(&g_ssqP[t], (double)sSsq[t]);
    }
}

// ---------------- K5: head_feats + pooled + out-BN stats ----------------
__global__ __launch_bounds__(256) void k5_pool(
    const float* __restrict__ nmask,
    const float* __restrict__ gP, const float* __restrict__ bP)
{
    __shared__ float scf[64], shf[64];
    int t = threadIdx.x;
    if (t < 64) {
        float cnt = (float)g_cnt;
        float s = (float)g_sumP[t], q = (float)g_ssqP[t];
        float mean = s / cnt, var = q / cnt - mean*mean;
        float inv = rsqrtf(var + EPSV);
        float sc = gP[t] * inv;
        scf[t] = sc; shf[t] = bP[t] - mean*sc;
    }
    __syncthreads();
    int j = t & 63, nl = t >> 6;
    int n0 = blockIdx.x * 64;
    float scP = scf[j], shP = shf[j];
    float psum = 0.f, pssq = 0.f;
    for (int i = 0; i < 16; i++) {
        int n = n0 + nl*16 + i;
        if (n >= N_NODES) break;
        float L = g_lens[n];
        float pooled = 0.f;
#pragma unroll
        for (int k = 0; k < KNBR; k++) {
            float m = (L > 0.f) ? nmask[n*KNBR + k] : (k == 0 ? 1.f : 0.f);
            float p = __half2float(g_ph[(size_t)(n*KNBR + k)*64 + j]);
            pooled += fsp(p*scP + shP) * m;
        }
        g_pooled[n*64 + j] = pooled;
        psum += pooled; pssq += pooled*pooled;
    }
    __shared__ float red[256], red2[256];
    red[t] = psum; red2[t] = pssq;
    __syncthreads();
    if (nl == 0) {
        float s = red[j] + red[64+j] + red[128+j] + red[192+j];
        float q = red2[j] + red2[64+j] + red2[128+j] + red2[192+j];
        atomicAdd(&g_sumO[j], (double)s);
        atomicAdd(&g_ssqO[j], (double)q);
    }
}

// ---------------- K7: residual + out-BN ----------------
__global__ __launch_bounds__(256) void k7_out(
    const float* __restrict__ nodef,
    const float* __restrict__ gO, const float* __restrict__ bO,
    float* __restrict__ out_nodes)
{
    __shared__ float scf[64], shf[64];
    int t = threadIdx.x;
    if (t < 64) {
        float cnt = (float)N_NODES;
        float s = (float)g_sumO[t], q = (float)g_ssqO[t];
        float mean = s / cnt, var = q / cnt - mean*mean;
        float inv = rsqrtf(var + EPSV);
        float sc = gO[t] * inv;
        scf[t] = sc; shf[t] = bO[t] - mean*sc;
    }
    __syncthreads();
    int i = blockIdx.x * 256 + t;
    if (i < N_NODES*64) {
        int j = i & 63;
        out_nodes[i] = nodef[i] + scf[j]*g_pooled[i] + shf[j];
    }
}

// ---------------- launch ----------------
extern "C" void kernel_launch(void* const* d_in, const int* in_sizes, int n_in,
                              void* d_out, int out_size)
{
    const float* nodef  = (const float*)d_in[0];
    const float* edgef  = (const float*)d_in[1];
    const int*   nbr    = (const int*)d_in[2];
    const float* nmask  = (const float*)d_in[3];
    const float* W_edge = (const float*)d_in[4];
    const float* b_edge = (const float*)d_in[5];
    const float* g_ebn  = (const float*)d_in[6];
    const float* b_ebn  = (const float*)d_in[7];
    const float* W1     = (const float*)d_in[8];
    const float* b1     = (const float*)d_in[9];
    const float* W2     = (const float*)d_in[10];
    const float* Wv     = (const float*)d_in[12];
    const float* bv     = (const float*)d_in[13];
    const float* g_abn  = (const float*)d_in[14];
    const float* b_abn  = (const float*)d_in[15];
    const float* g_obn  = (const float*)d_in[16];
    const float* b_obn  = (const float*)d_in[17];

    float* out_nodes = (float*)d_out;
    float* out_edges = out_nodes + (size_t)N_NODES * 64;

    const int smemP = (96*130 + 16*33) * 8;
    const int smem1 = 4608*2 + 3456*2 + 2*3264*4 + 2*3456*2 +
                      (272 + 48 + 128) * 4 + 96*4;               // ~58.3KB
    const int smem3 = 9216*2 + 3456*2 + 2*3264*4 + 2*6528*2 + 2*3072*2 +
                      (528 + 192 + 48 + 128 + 128) * 4 + 96*4;   // ~94.3KB
    static int inited = 0;
    if (!inited) {
        cudaFuncSetAttribute(k_pre,  cudaFuncAttributeMaxDynamicSharedMemorySize, smemP);
        cudaFuncSetAttribute(k1_edge, cudaFuncAttributeMaxDynamicSharedMemorySize, smem1);
        cudaFuncSetAttribute(k3_att,  cudaFuncAttributeMaxDynamicSharedMemorySize, smem3);
        inited = 1;
    }

    k_lens<<<LENS_BLOCKS, 256>>>(nmask);                               // 1
    k_pre<<<2*NSM, 384, smemP>>>(nodef, W_edge, W1, Wv);               // 2
    k1_edge<<<2*NSM, 384, smem1>>>(edgef, nbr, nmask, W_edge, b_edge,
                                   g_ebn, b_ebn);                      // 3
    k3_att<<<2*NSM, 384, smem3>>>(edgef, nbr, nmask, W1, b1, W2, Wv, bv,
                                  g_ebn, b_ebn, out_edges);            // 4 -> profiled
    k5_pool<<<(N_NODES + 63)/64, 256>>>(nmask, g_abn, b_abn);          // 5
    k7_out<<<(N_NODES*64 + 255)/256, 256>>>(nodef, g_obn, b_obn,
                                            out_nodes);                // 6
}

// round 16
// speedup vs baseline: 1.7641x; 1.0339x over previous
#include <cuda_runtime.h>
#include <cuda_fp16.h>
#include <math.h>

#define N_NODES 50000
#define KNBR    12
#define NEDGE   (N_NODES*KNBR)
#define EPSV    1e-5f
#define NSM     152
#define LENS_BLOCKS 196

typedef unsigned long long ull;

// ---------------- device scratch ----------------
__device__ __half g_elinh[NEDGE*64];    // e_lin fp16 (k1 -> k3)
__device__ __half g_ph[NEDGE*64];       // p fp16 (k3 -> k5)
__device__ float  g_pooled[N_NODES*64];
__device__ float  g_pc[N_NODES*384];    // f32: cols 0-63 (k1 self), 128-255 (k3 self)
__device__ __half g_pch1[N_NODES*64];   // fp16: k1 nbr contribution
__device__ __half g_pchAV[N_NODES*128]; // fp16: k3 att|val nbr contribution
__device__ float  g_lens[N_NODES];
__device__ float  g_cntPart[LENS_BLOCKS];
__device__ double g_sumE[64], g_ssqE[64];
__device__ double g_sumP[64], g_ssqP[64];
__device__ double g_sumO[64], g_ssqO[64];
__device__ double g_cnt;
__device__ unsigned int g_tick = 0;

// ---------------- f32x2 helpers ----------------
__device__ __forceinline__ ull pack2(float x, float y) {
    ull r; asm("mov.b64 %0,{%1,%2};" : "=l"(r) : "f"(x), "f"(y)); return r;
}
__device__ __forceinline__ void ffma2(ull& d, ull a, ull b) {
    asm("fma.rn.f32x2 %0,%1,%2,%0;" : "+l"(d) : "l"(a), "l"(b));
}
__device__ __forceinline__ float2 unpack2(ull v) {
    float2 r; asm("mov.b64 {%0,%1},%2;" : "=f"(r.x), "=f"(r.y) : "l"(v)); return r;
}

// ---------------- cp.async helpers ----------------
__device__ __forceinline__ unsigned su32(const void* p) {
    return (unsigned)__cvta_generic_to_shared(p);
}
#define CP16(dst, src) asm volatile( \
    "cp.async.cg.shared.global [%0], [%1], 16;" :: "r"(dst), "l"(src) : "memory")
#define CPCOMMIT() asm volatile("cp.async.commit_group;" ::: "memory")
#define CPWAIT0()  asm volatile("cp.async.wait_group 0;" ::: "memory")

// ---------------- mma helpers ----------------
__device__ __forceinline__ void ldm_x4(unsigned& a0, unsigned& a1,
                                       unsigned& a2, unsigned& a3, unsigned addr) {
    asm volatile("ldmatrix.sync.aligned.m8n8.x4.shared.b16 {%0,%1,%2,%3}, [%4];"
        : "=r"(a0), "=r"(a1), "=r"(a2), "=r"(a3) : "r"(addr));
}
__device__ __forceinline__ void ldm_x2(unsigned& b0, unsigned& b1, unsigned addr) {
    asm volatile("ldmatrix.sync.aligned.m8n8.x2.shared.b16 {%0,%1}, [%2];"
        : "=r"(b0), "=r"(b1) : "r"(addr));
}
__device__ __forceinline__ void mma16816(float* d, const unsigned* a,
                                         unsigned b0, unsigned b1) {
    asm volatile("mma.sync.aligned.m16n8k16.row.col.f32.f16.f16.f32 "
        "{%0,%1,%2,%3}, {%4,%5,%6,%7}, {%8,%9}, {%0,%1,%2,%3};"
        : "+f"(d[0]), "+f"(d[1]), "+f"(d[2]), "+f"(d[3])
        : "r"(a[0]), "r"(a[1]), "r"(a[2]), "r"(a[3]), "r"(b0), "r"(b1));
}

// ---------------- softplus on MUFU pipe ----------------
__device__ __forceinline__ float fsp(float x) {
    return fmaxf(x, 0.f) + __logf(1.f + __expf(-fabsf(x)));
}

__global__ void k_nop() {}   // ncu launch-slot alignment

// ---------------- K_lens ----------------
__global__ void k_lens(const float* __restrict__ nmask) {
    int n = blockIdx.x * 256 + threadIdx.x;
    int tid = threadIdx.x;
    float eff = 0.f;
    if (n < N_NODES) {
        float L = 0.f;
#pragma unroll
        for (int k = 0; k < KNBR; k++) L += nmask[n*KNBR + k];
        g_lens[n] = L;
        eff = (L > 0.f) ? L : 1.0f;
    }
    __shared__ float red[256];
    __shared__ unsigned int tk;
    red[tid] = eff;
    __syncthreads();
    for (int s = 128; s > 0; s >>= 1) {
        if (tid < s) red[tid] += red[tid + s];
        __syncthreads();
    }
    if (tid == 0) g_cntPart[blockIdx.x] = red[0];
    __threadfence();
    if (tid == 0) tk = atomicInc(&g_tick, gridDim.x - 1);
    __syncthreads();
    if (tk == gridDim.x - 1) {
        if (tid < 64) {
            g_sumE[tid] = 0.0; g_ssqE[tid] = 0.0;
            g_sumP[tid] = 0.0; g_ssqP[tid] = 0.0;
            g_sumO[tid] = 0.0; g_ssqO[tid] = 0.0;
        }
        if (tid == 64) {
            double s = 0.0;
            for (int i = 0; i < LENS_BLOCKS; i++) s += (double)g_cntPart[i];
            g_cnt = s;
        }
    }
}

// ---------------- weight catalog for pre-GEMM ----------------
__device__ __forceinline__ float wcat(const float* We, const float* W1,
                                      const float* Wv, int c, int j) {
    if (j < 64)  return We[c*64 + j];
    if (j < 128) return We[(64+c)*64 + (j-64)];
    if (j < 192) { int jj = j-128; return W1[((jj>>4)*192 + c)*16 + (jj&15)]; }
    if (j < 256) { int jj = j-192; return Wv[((jj>>4)*192 + c)*16 + (jj&15)]; }
    if (j < 320) { int jj = j-256; return W1[((jj>>4)*192 + 64 + c)*16 + (jj&15)]; }
    { int jj = j-320; return Wv[((jj>>4)*192 + 64 + c)*16 + (jj&15)]; }
}

// ---------------- K_pre ----------------
__global__ __launch_bounds__(384,2) void k_pre(
    const float* __restrict__ nodef,
    const float* __restrict__ We, const float* __restrict__ W1,
    const float* __restrict__ Wv)
{
    extern __shared__ float smem[];
    ull* sW  = (ull*)smem;            // 96 jq * 130
    ull* sX  = sW + 96*130;           // 16 nodes * 33

    int t = threadIdx.x;
    for (int idx = t; idx < 12288; idx += 384) {
        int jq = idx >> 7, r = idx & 127, p = r >> 2, i = r & 3;
        int j = jq*4 + i, c0 = 2*p;
        sW[jq*130 + p*4 + i] = pack2(wcat(We,W1,Wv,c0,j), wcat(We,W1,Wv,c0+1,j));
    }

    int jq = t % 96, ng = t / 96;
    const int GRID = gridDim.x;
    const int NT = N_NODES / 16;  // 3125
    for (int tile = blockIdx.x; tile < NT; tile += GRID) {
        int n0 = tile * 16;
        __syncthreads();
        for (int idx = t; idx < 512; idx += 384) {
            int node = idx >> 5, p = idx & 31;
            float2 x2 = *(const float2*)&nodef[(n0+node)*64 + 2*p];
            sX[node*33 + p] = pack2(x2.x, x2.y);
        }
        __syncthreads();

        ull acc[4][4];
#pragma unroll
        for (int a = 0; a < 4; a++) { acc[a][0]=0; acc[a][1]=0; acc[a][2]=0; acc[a][3]=0; }
        const ull* wp = &sW[jq*130];
#pragma unroll 4
        for (int p = 0; p < 32; p++) {
            ulonglong2 w01 = *(const ulonglong2*)&wp[p*4];
            ulonglong2 w23 = *(const ulonglong2*)&wp[p*4 + 2];
#pragma unroll
            for (int ee = 0; ee < 4; ee++) {
                ull xv = sX[(ng*4+ee)*33 + p];
                ffma2(acc[ee][0], xv, w01.x);
                ffma2(acc[ee][1], xv, w01.y);
                ffma2(acc[ee][2], xv, w23.x);
                ffma2(acc[ee][3], xv, w23.y);
            }
        }
#pragma unroll
        for (int ee = 0; ee < 4; ee++) {
            int n = n0 + ng*4 + ee;
            float2 u0 = unpack2(acc[ee][0]), u1 = unpack2(acc[ee][1]);
            float2 u2 = unpack2(acc[ee][2]), u3 = unpack2(acc[ee][3]);
            float4 o;
            o.x = u0.x+u0.y; o.y = u1.x+u1.y; o.z = u2.x+u2.y; o.w = u3.x+u3.y;
            if (jq < 16 || (jq >= 32 && jq < 64)) {
                *(float4*)&g_pc[(size_t)n*384 + jq*4] = o;
            } else {
                __half2 h0 = __floats2half2_rn(o.x, o.y);
                __half2 h1 = __floats2half2_rn(o.z, o.w);
                uint2 uu; uu.x = *(unsigned*)&h0; uu.y = *(unsigned*)&h1;
                if (jq < 32)
                    *(uint2*)&g_pch1[(size_t)n*64 + (jq-16)*4] = uu;
                else
                    *(uint2*)&g_pchAV[(size_t)n*128 + (jq-64)*4] = uu;
            }
        }
    }
}

// ---------------- K1: HMMA e_lin (fp16 out) ---------------------------------
// persistent, 384 threads (12 warps), 2 CTAs/SM, tile = 8 nodes (96 edges).
// GEMM 96x64x64 via mma.sync.m16n8k16. warp w: m=w%6 (16 edges), g=w/6 (32 cols).
__global__ __launch_bounds__(384,2) void k1_edge(
    const float* __restrict__ edgef, const int* __restrict__ nbr,
    const float* __restrict__ nmask, const float* __restrict__ W,
    const float* __restrict__ bE,
    const float* __restrict__ gE, const float* __restrict__ bEbn)
{
    extern __shared__ float smem[];
    __half* sWh  = (__half*)smem;                 // 64*72 halves   (9216B)
    __half* sCh  = sWh + 4608;                    // 96*72 halves   (13824B)
    float*  sE   = (float*)(sCh + 6912);          // 2 * 96*68 f32  (52224B)
    __half* sNPC = (__half*)(sE + 2*6528);        // 2 * 96*72      (27648B)
    float*  sPS  = (float*)(sNPC + 2*6912);       // 8*68           (2176B)
    float*  sM   = sPS + 544;                     // 96
    int*    sNI  = (int*)(sM + 96);               // 2*96
    float*  sSum = (float*)(sNI + 192);           // 64
    float*  sSsq = sSum + 64;                     // 64

    int t = threadIdx.x;
    // fp16 weights: sWh[j][c] = W_edge[(128+c)*64 + j]
    for (int idx = t; idx < 4096; idx += 384) {
        int j = idx >> 6, c = idx & 63;
        sWh[j*72 + c] = __float2half(W[(128 + c)*64 + j]);
    }
    if (t < 64) { sSum[t] = 0.f; sSsq[t] = 0.f; }

    int wid = t >> 5, l = t & 31;
    int m = wid % 6, g = wid / 6;         // m-tile (16 edges), col-group (32 cols)
    int r0 = l >> 2, r1 = r0 + 8;
    int cq = (l & 3) * 2;
    int l16 = l & 15;

    float bj8[8];                          // bias for j = g*32 + nu*8 + cq + c
#pragma unroll
    for (int nu = 0; nu < 4; nu++)
#pragma unroll
        for (int c = 0; c < 2; c++)
            bj8[nu*2+c] = bE[g*32 + nu*8 + cq + c];

    float pS[8] = {0,0,0,0,0,0,0,0}, pQ[8] = {0,0,0,0,0,0,0,0};

    const int GRID = gridDim.x;
    const int NT = NEDGE / 96;   // 6250
    int bid = blockIdx.x;

    // prolog
    if (t < 24) CP16(su32(&sNI[t*4]), &nbr[bid*96 + t*4]);
    CPCOMMIT(); CPWAIT0();
    __syncthreads();
    {
        for (int i = t; i < 1536; i += 384) {
            int le = i >> 4, c4 = (i & 15) << 2;
            CP16(su32(&sE[le*68 + c4]), &edgef[(size_t)(bid*96+le)*64 + c4]);
        }
        for (int i = t; i < 768; i += 384) {
            int le = i >> 3, c8 = (i & 7) * 8;
            int nb = sNI[le];
            CP16(su32(&sNPC[le*72 + c8]), &g_pch1[(size_t)nb*64 + c8]);
        }
        int T1 = bid + GRID;
        if (T1 < NT && t < 24)
            CP16(su32(&sNI[96 + t*4]), &nbr[T1*96 + t*4]);
    }
    CPCOMMIT();

    int w = 0;
    for (int T = bid; T < NT; T += GRID, w ^= 1) {
        int cur = w, nxt = w ^ 1;
        CPWAIT0();
        __syncthreads();

        int Tn = T + GRID;
        if (Tn < NT) {
            for (int i = t; i < 1536; i += 384) {
                int le = i >> 4, c4 = (i & 15) << 2;
                CP16(su32(&sE[nxt*6528 + le*68 + c4]),
                     &edgef[(size_t)(Tn*96+le)*64 + c4]);
            }
            for (int i = t; i < 768; i += 384) {
                int le = i >> 3, c8 = (i & 7) * 8;
                int nb = sNI[nxt*96 + le];
                CP16(su32(&sNPC[nxt*6912 + le*72 + c8]),
                     &g_pch1[(size_t)nb*64 + c8]);
            }
            int Tn2 = Tn + GRID;
            if (Tn2 < NT && t < 24)
                CP16(su32(&sNI[cur*96 + t*4]), &nbr[Tn2*96 + t*4]);
            CPCOMMIT();
        }

        int eb = T*96, n0 = T*8;
        if (t < 128) {
            int node = t >> 4, q = (t & 15) << 2;
            *(float4*)&sPS[node*68 + q] =
                *(const float4*)&g_pc[(size_t)(n0+node)*384 + q];
        }
        if (t < 96) {
            int e = eb + t, n = n0 + t/KNBR, k = t % KNBR;
            float L = g_lens[n];
            sM[t] = (L > 0.f) ? nmask[e] : (k == 0 ? 1.f : 0.f);
        }
        // convert staged edgef f32 -> fp16 A-tile
        const float* eE = &sE[cur*6528];
        for (int i = t; i < 1536; i += 384) {
            int le = i >> 4, j = (i & 15) << 2;
            float4 v = *(const float4*)&eE[le*68 + j];
            __half2 q0 = __floats2half2_rn(v.x, v.y);
            __half2 q1 = __floats2half2_rn(v.z, v.w);
            uint2 qq; qq.x = *(unsigned*)&q0; qq.y = *(unsigned*)&q1;
            *(uint2*)&sCh[le*72 + j] = qq;
        }
        __syncthreads();

        // HMMA: D[96x64] = sCh[96x64] @ sWh^T
        float dacc[4][4];
#pragma unroll
        for (int a = 0; a < 4; a++) { dacc[a][0]=0; dacc[a][1]=0; dacc[a][2]=0; dacc[a][3]=0; }
#pragma unroll
        for (int kk = 0; kk < 4; kk++) {
            unsigned a4[4];
            ldm_x4(a4[0], a4[1], a4[2], a4[3],
                su32(&sCh[(m*16 + l16)*72 + kk*16 + (l >> 4)*8]));
#pragma unroll
            for (int nu = 0; nu < 4; nu++) {
                unsigned b0, b1x;
                ldm_x2(b0, b1x,
                    su32(&sWh[(g*32 + nu*8 + (l16 & 7))*72 + kk*16 + ((l16 >> 3)&1)*8]));
                mma16816(dacc[nu], a4, b0, b1x);
            }
        }

        // epilogue: bias + self + nbr, fp16 store, masked stats
        const __half* npcb = &sNPC[cur*6912];
#pragma unroll
        for (int nu = 0; nu < 4; nu++) {
#pragma unroll
            for (int rsel = 0; rsel < 2; rsel++) {
                int r = rsel ? r1 : r0;
                int le = m*16 + r, e = eb + le, ln = le / KNBR;
                float mm = sM[le];
                int jb = g*32 + nu*8 + cq;
                float o0 = dacc[nu][rsel*2+0] + bj8[nu*2+0]
                         + sPS[ln*68 + jb]     + __half2float(npcb[le*72 + jb]);
                float o1 = dacc[nu][rsel*2+1] + bj8[nu*2+1]
                         + sPS[ln*68 + jb + 1] + __half2float(npcb[le*72 + jb + 1]);
                __half2 hp = __floats2half2_rn(o0, o1);
                *(unsigned*)&g_elinh[(size_t)e*64 + jb] = *(unsigned*)&hp;
                pS[nu*2+0] += o0*mm; pQ[nu*2+0] += o0*o0*mm;
                pS[nu*2+1] += o1*mm; pQ[nu*2+1] += o1*o1*mm;
            }
        }
    }
    __syncthreads();
#pragma unroll
    for (int nu = 0; nu < 4; nu++)
#pragma unroll
        for (int c = 0; c < 2; c++) {
            int j = g*32 + nu*8 + cq + c;
            atomicAdd(&sSum[j], pS[nu*2+c]);
            atomicAdd(&sSsq[j], pQ[nu*2+c]);
        }
    __syncthreads();
    if (t < 64) {
        atomicAdd(&g_sumE[t], (double)sSum[t]);
        atomicAdd(&g_ssqE[t], (double)sSsq[t]);
    }
}

// row c (128..191) weight for fused att|val col j in [0,128)
__device__ __forceinline__ float wrow3(const float* W1, const float* Wv,
                                       int crow, int j) {
    if (j < 64) return W1[((j>>4)*192 + crow)*16 + (j&15)];
    int jv = j - 64;
    return Wv[((jv>>4)*192 + crow)*16 + (jv&15)];
}

// ---------------- K3: HMMA fused edge-update + attention + value -----------
__global__ __launch_bounds__(384,2) void k3_att(
    const float* __restrict__ edgef, const int* __restrict__ nbr,
    const float* __restrict__ nmask,
    const float* __restrict__ W1, const float* __restrict__ b1,
    const float* __restrict__ W2,
    const float* __restrict__ Wv, const float* __restrict__ bv,
    const float* __restrict__ gE, const float* __restrict__ bEbn,
    float* __restrict__ out_edges)
{
    extern __shared__ float smem[];
    __half* sWh  = (__half*)smem;                 // 128*72 halves  (18432B)
    __half* sCh  = sWh + 9216;                    // 48*72 halves   (6912B)
    float*  sE   = (float*)(sCh + 3456);          // 2 * 48*68      (26112B)
    __half* sNAV = (__half*)(sE + 2*3264);        // 2 * 48*136     (26112B)
    __half* sEL  = sNAV + 2*6528;                 // 2 * 48*64      (12288B)
    float*  sPS  = (float*)(sEL + 2*3072);        // 4*132          (2112B)
    float*  sLog = sPS + 528;                     // 192
    float*  sM   = sLog + 192;                    // 48
    int*    sNI  = (int*)(sM + 48);               // 2*48
    float*  sCoef= (float*)(sNI + 96);            // 128
    float*  sSum = sCoef + 128;                   // 64
    float*  sSsq = sSum + 64;                     // 64

    int t = threadIdx.x;
    for (int idx = t; idx < 8192; idx += 384) {
        int j = idx >> 6, c = idx & 63;
        sWh[j*72 + c] = __float2half(wrow3(W1, Wv, 128 + c, j));
    }
    if (t < 64) {
        float cnt = (float)g_cnt;
        float s = (float)g_sumE[t], q = (float)g_ssqE[t];
        float mean = s / cnt, var = q / cnt - mean*mean;
        float inv = rsqrtf(var + EPSV);
        float sc = gE[t] * inv;
        sCoef[t] = sc;
        sCoef[64 + t] = bEbn[t] - mean*sc;
        sSum[t] = 0.f; sSsq[t] = 0.f;
    }

    int wid = t >> 5, l = t & 31;
    int m = wid % 3, g = wid / 3;
    int isAtt = (g < 2);
    int r0 = l >> 2, r1 = r0 + 8;
    int cq = (l & 3) * 2;

    float c1r[8], c2r[8];
#pragma unroll
    for (int nu = 0; nu < 4; nu++)
#pragma unroll
        for (int c = 0; c < 2; c++) {
            int j = g*32 + nu*8 + cq + c;
            if (isAtt) { c1r[nu*2+c] = b1[j]; c2r[nu*2+c] = W2[j]; }
            else       { c1r[nu*2+c] = bv[j - 64]; c2r[nu*2+c] = 0.f; }
        }

    float pS8[8], pQ8[8];
#pragma unroll
    for (int i = 0; i < 8; i++) { pS8[i] = 0.f; pQ8[i] = 0.f; }

    const int GRID = gridDim.x;
    const int NT = N_NODES / 4;
    int bid = blockIdx.x;

    if (t < 12) CP16(su32(&sNI[t*4]), &nbr[bid*48 + t*4]);
    CPCOMMIT(); CPWAIT0();
    __syncthreads();
    {
        for (int i = t; i < 768; i += 384) {
            int le = i >> 4, c4 = (i & 15) << 2;
            CP16(su32(&sE[le*68 + c4]), &edgef[(size_t)(bid*48+le)*64 + c4]);
        }
        for (int i = t; i < 768; i += 384) {
            int le = i >> 4, c8 = (i & 15) * 8;
            int nb = sNI[le];
            CP16(su32(&sNAV[le*136 + c8]), &g_pchAV[(size_t)nb*128 + c8]);
        }
        for (int i = t; i < 384; i += 384) {
            int le = i >> 3, c8 = (i & 7) * 8;
            CP16(su32(&sEL[le*64 + c8]), &g_elinh[(size_t)(bid*48+le)*64 + c8]);
        }
        int T1 = bid + GRID;
        if (T1 < NT && t < 12)
            CP16(su32(&sNI[48 + t*4]), &nbr[T1*48 + t*4]);
    }
    CPCOMMIT();

    int w = 0;
    for (int T = bid; T < NT; T += GRID, w ^= 1) {
        int cur = w, nxt = w ^ 1;
        CPWAIT0();
        __syncthreads();

        int Tn = T + GRID;
        if (Tn < NT) {
            for (int i = t; i < 768; i += 384) {
                int le = i >> 4, c4 = (i & 15) << 2;
                CP16(su32(&sE[nxt*3264 + le*68 + c4]),
                     &edgef[(size_t)(Tn*48+le)*64 + c4]);
            }
            for (int i = t; i < 768; i += 384) {
                int le = i >> 4, c8 = (i & 15) * 8;
                int nb = sNI[nxt*48 + le];
                CP16(su32(&sNAV[nxt*6528 + le*136 + c8]),
                     &g_pchAV[(size_t)nb*128 + c8]);
            }
            for (int i = t; i < 384; i += 384) {
                int le = i >> 3, c8 = (i & 7) * 8;
                CP16(su32(&sEL[nxt*3072 + le*64 + c8]),
                     &g_elinh[(size_t)(Tn*48+le)*64 + c8]);
            }
            int Tn2 = Tn + GRID;
            if (Tn2 < NT && t < 12)
                CP16(su32(&sNI[cur*48 + t*4]), &nbr[Tn2*48 + t*4]);
            CPCOMMIT();
        }

        int n0 = T*4, eb = n0*KNBR;
        if (t < 48) {
            int e = eb + t, n = n0 + t/KNBR, k = t % KNBR;
            float L = g_lens[n];
            sM[t] = (L > 0.f) ? nmask[e] : (k == 0 ? 1.f : 0.f);
        }
        if (t < 128) {
            int node = t >> 5, q = (t & 31) << 2;
            *(float4*)&sPS[node*132 + q] =
                *(const float4*)&g_pc[(size_t)(n0+node)*384 + 128 + q];
        }
        __syncthreads();

        const float*  eE = &sE[cur*3264];
        const __half* eL = &sEL[cur*3072];
        for (int i = t; i < 768; i += 384) {
            int le = i >> 4, j = (i & 15) << 2;
            int e = eb + le;
            float mm = sM[le];
            uint2 elu = *(const uint2*)&eL[le*64 + j];
            float2 el01 = __half22float2(*(__half2*)&elu.x);
            float2 el23 = __half22float2(*(__half2*)&elu.y);
            float4 ef = *(const float4*)&eE[le*68 + j];
            float4 sc = *(const float4*)&sCoef[j];
            float4 sh = *(const float4*)&sCoef[64 + j];
            float4 eu;
            eu.x = fsp(ef.x + (el01.x*sc.x + sh.x)*mm);
            eu.y = fsp(ef.y + (el01.y*sc.y + sh.y)*mm);
            eu.z = fsp(ef.z + (el23.x*sc.z + sh.z)*mm);
            eu.w = fsp(ef.w + (el23.y*sc.w + sh.w)*mm);
            *(float4*)&out_edges[(size_t)e*64 + j] = eu;
            __half2 q0 = __floats2half2_rn(eu.x, eu.y);
            __half2 q1 = __floats2half2_rn(eu.z, eu.w);
            uint2 qq; qq.x = *(unsigned*)&q0; qq.y = *(unsigned*)&q1;
            *(uint2*)&sCh[le*72 + j] = qq;
        }
        __syncthreads();

        float dacc[4][4];
#pragma unroll
        for (int a = 0; a < 4; a++)
#pragma unroll
            for (int b = 0; b < 4; b++) dacc[a][b] = 0.f;
        int l16 = l & 15;
#pragma unroll
        for (int kk = 0; kk < 4; kk++) {
            unsigned a4[4];
            ldm_x4(a4[0], a4[1], a4[2], a4[3],
                su32(&sCh[(m*16 + l16)*72 + kk*16 + (l >> 4)*8]));
#pragma unroll
            for (int nu = 0; nu < 4; nu++) {
                unsigned b0, b1x;
                ldm_x2(b0, b1x,
                    su32(&sWh[(g*32 + nu*8 + (l16 & 7))*72 + kk*16 + ((l16 >> 3)&1)*8]));
                mma16816(dacc[nu], a4, b0, b1x);
            }
        }

        const __half* nav = &sNAV[cur*6528];
        if (isAtt) {
            float lpAcc[4] = {0.f, 0.f, 0.f, 0.f};
#pragma unroll
            for (int nu = 0; nu < 4; nu++) {
                int hs = nu >> 1;
#pragma unroll
                for (int rc = 0; rc < 4; rc++) {
                    int rsel = rc >> 1, c = rc & 1;
                    int r = rsel ? r1 : r0;
                    int le = m*16 + r, ln = le / KNBR;
                    int j = g*32 + nu*8 + cq + c;
                    float h1v = fsp(dacc[nu][rc] + c1r[nu*2+c]
                                    + sPS[ln*132 + j]
                                    + __half2float(nav[le*136 + j]));
                    lpAcc[rsel*2 + hs] += h1v * c2r[nu*2+c];
                }
            }
#pragma unroll
            for (int i = 0; i < 4; i++) {
                lpAcc[i] += __shfl_xor_sync(0xffffffffu, lpAcc[i], 1);
                lpAcc[i] += __shfl_xor_sync(0xffffffffu, lpAcc[i], 2);
            }
            if ((l & 3) == 0) {
                sLog[(m*16+r0)*4 + g*2 + 0] = lpAcc[0];
                sLog[(m*16+r0)*4 + g*2 + 1] = lpAcc[1];
                sLog[(m*16+r1)*4 + g*2 + 0] = lpAcc[2];
                sLog[(m*16+r1)*4 + g*2 + 1] = lpAcc[3];
            }
        } else {
#pragma unroll
            for (int nu = 0; nu < 4; nu++)
#pragma unroll
                for (int rc = 0; rc < 4; rc++) {
                    int rsel = rc >> 1, c = rc & 1;
                    int r = rsel ? r1 : r0;
                    int le = m*16 + r, ln = le / KNBR;
                    int jv = (g-2)*32 + nu*8 + cq + c;
                    dacc[nu][rc] += c1r[nu*2+c] + sPS[ln*132 + 64 + jv]
                                  + __half2float(nav[le*136 + 64 + jv]);
                }
        }
        __syncthreads();

        if (!isAtt) {
            int q = l & 3;
            int rq = (q >> 1) ? r1 : r0;
            int nodeq = (m*16 + rq) / KNBR;
            int hq = (g-2)*2 + (q & 1);
            int le0 = nodeq * KNBR;
            float mx = -1e30f;
#pragma unroll
            for (int k = 0; k < KNBR; k++) {
                int le = le0 + k;
                if (sM[le] > 0.f) mx = fmaxf(mx, sLog[le*4 + hq]);
            }
            float ss = 0.f;
#pragma unroll
            for (int k = 0; k < KNBR; k++) {
                int le = le0 + k;
                ss += (sM[le] > 0.f) ? __expf(sLog[le*4 + hq] - mx) : 0.f;
            }
            float inv = 1.f / ss;
            float mxq[4], invq[4];
            int lb = l & ~3;
#pragma unroll
            for (int i = 0; i < 4; i++) {
                mxq[i]  = __shfl_sync(0xffffffffu, mx,  lb + i);
                invq[i] = __shfl_sync(0xffffffffu, inv, lb + i);
            }
#pragma unroll
            for (int nu = 0; nu < 4; nu++) {
                int hs = nu >> 1;
                int h = (g-2)*2 + hs;
#pragma unroll
                for (int rsel = 0; rsel < 2; rsel++) {
                    int r = rsel ? r1 : r0;
                    int le = m*16 + r, e = eb + le;
                    int qi = rsel*2 + hs;
                    float mm = sM[le];
                    float a = (mm > 0.f)
                        ? __expf(sLog[le*4 + h] - mxq[qi]) * invq[qi] : 0.f;
                    float p0 = a * dacc[nu][rsel*2 + 0];
                    float p1 = a * dacc[nu][rsel*2 + 1];
                    __half2 hp = __floats2half2_rn(p0, p1);
                    *(unsigned*)&g_ph[(size_t)e*64 + (g-2)*32 + nu*8 + cq] =
                        *(unsigned*)&hp;
                    pS8[nu*2+0] += p0*mm; pQ8[nu*2+0] += p0*p0*mm;
                    pS8[nu*2+1] += p1*mm; pQ8[nu*2+1] += p1*p1*mm;
                }
            }
        }
    }
    __syncthreads();
    if (!isAtt) {
#pragma unroll
        for (int nu = 0; nu < 4; nu++)
#pragma unroll
            for (int c = 0; c < 2; c++) {
                int jv = (g-2)*32 + nu*8 + cq + c;
                atomicAdd(&sSum[jv], pS8[nu*2+c]);
                atomicAdd(&sSsq[jv], pQ8[nu*2+c]);
            }
    }
    __syncthreads();
    if (t < 64) {
        atomicAdd(&g_sumP[t], (double)sSum[t]);
        atomicAdd(&g_ssqP[t], (double)sSsq[t]);
    }
}

// ---------------- K5: head_feats + pooled + out-BN stats ----------------
__global__ __launch_bounds__(256) void k5_pool(
    const float* __restrict__ nmask,
    const float* __restrict__ gP, const float* __restrict__ bP)
{
    __shared__ float scf[64], shf[64];
    int t = threadIdx.x;
    if (t < 64) {
        float cnt = (float)g_cnt;
        float s = (float)g_sumP[t], q = (float)g_ssqP[t];
        float mean = s / cnt, var = q / cnt - mean*mean;
        float inv = rsqrtf(var + EPSV);
        float sc = gP[t] * inv;
        scf[t] = sc; shf[t] = bP[t] - mean*sc;
    }
    __syncthreads();
    int j = t & 63, nl = t >> 6;
    int n0 = blockIdx.x * 64;
    float scP = scf[j], shP = shf[j];
    float psum = 0.f, pssq = 0.f;
    for (int i = 0; i < 16; i++) {
        int n = n0 + nl*16 + i;
        if (n >= N_NODES) break;
        float L = g_lens[n];
        float pooled = 0.f;
#pragma unroll
        for (int k = 0; k < KNBR; k++) {
            float m = (L > 0.f) ? nmask[n*KNBR + k] : (k == 0 ? 1.f : 0.f);
            float p = __half2float(g_ph[(size_t)(n*KNBR + k)*64 + j]);
            pooled += fsp(p*scP + shP) * m;
        }
        g_pooled[n*64 + j] = pooled;
        psum += pooled; pssq += pooled*pooled;
    }
    __shared__ float red[256], red2[256];
    red[t] = psum; red2[t] = pssq;
    __syncthreads();
    if (nl == 0) {
        float s = red[j] + red[64+j] + red[128+j] + red[192+j];
        float q = red2[j] + red2[64+j] + red2[128+j] + red2[192+j];
        atomicAdd(&g_sumO[j], (double)s);
        atomicAdd(&g_ssqO[j], (double)q);
    }
}

// ---------------- K7: residual + out-BN ----------------
__global__ __launch_bounds__(256) void k7_out(
    const float* __restrict__ nodef,
    const float* __restrict__ gO, const float* __restrict__ bO,
    float* __restrict__ out_nodes)
{
    __shared__ float scf[64], shf[64];
    int t = threadIdx.x;
    if (t < 64) {
        float cnt = (float)N_NODES;
        float s = (float)g_sumO[t], q = (float)g_ssqO[t];
        float mean = s / cnt, var = q / cnt - mean*mean;
        float inv = rsqrtf(var + EPSV);
        float sc = gO[t] * inv;
        scf[t] = sc; shf[t] = bO[t] - mean*sc;
    }
    __syncthreads();
    int i = blockIdx.x * 256 + t;
    if (i < N_NODES*64) {
        int j = i & 63;
        out_nodes[i] = nodef[i] + scf[j]*g_pooled[i] + shf[j];
    }
}

// ---------------- launch ----------------
extern "C" void kernel_launch(void* const* d_in, const int* in_sizes, int n_in,
                              void* d_out, int out_size)
{
    const float* nodef  = (const float*)d_in[0];
    const float* edgef  = (const float*)d_in[1];
    const int*   nbr    = (const int*)d_in[2];
    const float* nmask  = (const float*)d_in[3];
    const float* W_edge = (const float*)d_in[4];
    const float* b_edge = (const float*)d_in[5];
    const float* g_ebn  = (const float*)d_in[6];
    const float* b_ebn  = (const float*)d_in[7];
    const float* W1     = (const float*)d_in[8];
    const float* b1     = (const float*)d_in[9];
    const float* W2     = (const float*)d_in[10];
    const float* Wv     = (const float*)d_in[12];
    const float* bv     = (const float*)d_in[13];
    const float* g_abn  = (const float*)d_in[14];
    const float* b_abn  = (const float*)d_in[15];
    const float* g_obn  = (const float*)d_in[16];
    const float* b_obn  = (const float*)d_in[17];

    float* out_nodes = (float*)d_out;
    float* out_edges = out_nodes + (size_t)N_NODES * 64;

    const int smemP = (96*130 + 16*33) * 8;
    const int smem1 = 9216 + 13824 + 52224 + 27648 + 2176
                      + 96*4 + 192*4 + 512;                      // ~104.3KB
    const int smem3 = 9216*2 + 3456*2 + 2*3264*4 + 2*6528*2 + 2*3072*2 +
                      (528 + 192 + 48 + 128 + 128) * 4 + 96*4;   // ~94.3KB
    static int inited = 0;
    if (!inited) {
        cudaFuncSetAttribute(k_pre,  cudaFuncAttributeMaxDynamicSharedMemorySize, smemP);
        cudaFuncSetAttribute(k1_edge, cudaFuncAttributeMaxDynamicSharedMemorySize, smem1);
        cudaFuncSetAttribute(k3_att,  cudaFuncAttributeMaxDynamicSharedMemorySize, smem3);
        inited = 1;
    }

    k_lens<<<LENS_BLOCKS, 256>>>(nmask);                               // 1
    k_pre<<<2*NSM, 384, smemP>>>(nodef, W_edge, W1, Wv);               // 2
    k_nop<<<1, 32>>>();                                                // 3 (align ncu)
    k1_edge<<<2*NSM, 384, smem1>>>(edgef, nbr, nmask, W_edge, b_edge,
                                   g_ebn, b_ebn);                      // 4 -> profiled
    k3_att<<<2*NSM, 384, smem3>>>(edgef, nbr, nmask, W1, b1, W2, Wv, bv,
                                  g_ebn, b_ebn, out_edges);            // 5
    k5_pool<<<(N_NODES + 63)/64, 256>>>(nmask, g_abn, b_abn);          // 6
    k7_out<<<(N_NODES*64 + 255)/256, 256>>>(nodef, g_obn, b_obn,
                                            out_nodes);                // 7
}

// round 17
// speedup vs baseline: 1.8105x; 1.0263x over previous
#include <cuda_runtime.h>
#include <cuda_fp16.h>
#include <math.h>

#define N_NODES 50000
#define KNBR    12
#define NEDGE   (N_NODES*KNBR)
#define EPSV    1e-5f
#define NSM     152
#define LENS_BLOCKS 196

typedef unsigned long long ull;

// ---------------- device scratch ----------------
__device__ __half g_elinh[NEDGE*64];    // e_lin fp16 (k1 -> k3)
__device__ __half g_ph[NEDGE*64];       // p fp16 (k3 -> k5)
__device__ float  g_pooled[N_NODES*64];
__device__ float  g_pc[N_NODES*384];    // f32: cols 0-63 (k1 self), 128-255 (k3 self)
__device__ __half g_pch1[N_NODES*64];   // fp16: k1 nbr contribution
__device__ __half g_pchAV[N_NODES*128]; // fp16: k3 att|val nbr contribution
__device__ float  g_lens[N_NODES];
__device__ float  g_cntPart[LENS_BLOCKS];
__device__ double g_sumE[64], g_ssqE[64];
__device__ double g_sumP[64], g_ssqP[64];
__device__ double g_sumO[64], g_ssqO[64];
__device__ double g_cnt;
__device__ unsigned int g_tick = 0;

// ---------------- f32x2 helpers ----------------
__device__ __forceinline__ ull pack2(float x, float y) {
    ull r; asm("mov.b64 %0,{%1,%2};" : "=l"(r) : "f"(x), "f"(y)); return r;
}
__device__ __forceinline__ void ffma2(ull& d, ull a, ull b) {
    asm("fma.rn.f32x2 %0,%1,%2,%0;" : "+l"(d) : "l"(a), "l"(b));
}
__device__ __forceinline__ float2 unpack2(ull v) {
    float2 r; asm("mov.b64 {%0,%1},%2;" : "=f"(r.x), "=f"(r.y) : "l"(v)); return r;
}

// ---------------- cp.async helpers ----------------
__device__ __forceinline__ unsigned su32(const void* p) {
    return (unsigned)__cvta_generic_to_shared(p);
}
#define CP16(dst, src) asm volatile( \
    "cp.async.cg.shared.global [%0], [%1], 16;" :: "r"(dst), "l"(src) : "memory")
#define CPCOMMIT() asm volatile("cp.async.commit_group;" ::: "memory")
#define CPWAIT0()  asm volatile("cp.async.wait_group 0;" ::: "memory")

// ---------------- mma helpers ----------------
__device__ __forceinline__ void ldm_x4(unsigned& a0, unsigned& a1,
                                       unsigned& a2, unsigned& a3, unsigned addr) {
    asm volatile("ldmatrix.sync.aligned.m8n8.x4.shared.b16 {%0,%1,%2,%3}, [%4];"
        : "=r"(a0), "=r"(a1), "=r"(a2), "=r"(a3) : "r"(addr));
}
__device__ __forceinline__ void ldm_x2(unsigned& b0, unsigned& b1, unsigned addr) {
    asm volatile("ldmatrix.sync.aligned.m8n8.x2.shared.b16 {%0,%1}, [%2];"
        : "=r"(b0), "=r"(b1) : "r"(addr));
}
__device__ __forceinline__ void mma16816(float* d, const unsigned* a,
                                         unsigned b0, unsigned b1) {
    asm volatile("mma.sync.aligned.m16n8k16.row.col.f32.f16.f16.f32 "
        "{%0,%1,%2,%3}, {%4,%5,%6,%7}, {%8,%9}, {%0,%1,%2,%3};"
        : "+f"(d[0]), "+f"(d[1]), "+f"(d[2]), "+f"(d[3])
        : "r"(a[0]), "r"(a[1]), "r"(a[2]), "r"(a[3]), "r"(b0), "r"(b1));
}

// ---------------- softplus on MUFU pipe ----------------
__device__ __forceinline__ float fsp(float x) {
    return fmaxf(x, 0.f) + __logf(1.f + __expf(-fabsf(x)));
}

// ---------------- K_lens ----------------
__global__ void k_lens(const float* __restrict__ nmask) {
    int n = blockIdx.x * 256 + threadIdx.x;
    int tid = threadIdx.x;
    float eff = 0.f;
    if (n < N_NODES) {
        float L = 0.f;
#pragma unroll
        for (int k = 0; k < KNBR; k++) L += nmask[n*KNBR + k];
        g_lens[n] = L;
        eff = (L > 0.f) ? L : 1.0f;
    }
    __shared__ float red[256];
    __shared__ unsigned int tk;
    red[tid] = eff;
    __syncthreads();
    for (int s = 128; s > 0; s >>= 1) {
        if (tid < s) red[tid] += red[tid + s];
        __syncthreads();
    }
    if (tid == 0) g_cntPart[blockIdx.x] = red[0];
    __threadfence();
    if (tid == 0) tk = atomicInc(&g_tick, gridDim.x - 1);
    __syncthreads();
    if (tk == gridDim.x - 1) {
        if (tid < 64) {
            g_sumE[tid] = 0.0; g_ssqE[tid] = 0.0;
            g_sumP[tid] = 0.0; g_ssqP[tid] = 0.0;
            g_sumO[tid] = 0.0; g_ssqO[tid] = 0.0;
        }
        if (tid == 64) {
            double s = 0.0;
            for (int i = 0; i < LENS_BLOCKS; i++) s += (double)g_cntPart[i];
            g_cnt = s;
        }
    }
}

// ---------------- weight catalog for pre-GEMM ----------------
__device__ __forceinline__ float wcat(const float* We, const float* W1,
                                      const float* Wv, int c, int j) {
    if (j < 64)  return We[c*64 + j];
    if (j < 128) return We[(64+c)*64 + (j-64)];
    if (j < 192) { int jj = j-128; return W1[((jj>>4)*192 + c)*16 + (jj&15)]; }
    if (j < 256) { int jj = j-192; return Wv[((jj>>4)*192 + c)*16 + (jj&15)]; }
    if (j < 320) { int jj = j-256; return W1[((jj>>4)*192 + 64 + c)*16 + (jj&15)]; }
    { int jj = j-320; return Wv[((jj>>4)*192 + 64 + c)*16 + (jj&15)]; }
}

// ---------------- K_pre ----------------
__global__ __launch_bounds__(384,2) void k_pre(
    const float* __restrict__ nodef,
    const float* __restrict__ We, const float* __restrict__ W1,
    const float* __restrict__ Wv)
{
    extern __shared__ float smem[];
    ull* sW  = (ull*)smem;            // 96 jq * 130
    ull* sX  = sW + 96*130;           // 16 nodes * 33

    int t = threadIdx.x;
    for (int idx = t; idx < 12288; idx += 384) {
        int jq = idx >> 7, r = idx & 127, p = r >> 2, i = r & 3;
        int j = jq*4 + i, c0 = 2*p;
        sW[jq*130 + p*4 + i] = pack2(wcat(We,W1,Wv,c0,j), wcat(We,W1,Wv,c0+1,j));
    }

    int jq = t % 96, ng = t / 96;
    const int GRID = gridDim.x;
    const int NT = N_NODES / 16;  // 3125
    for (int tile = blockIdx.x; tile < NT; tile += GRID) {
        int n0 = tile * 16;
        __syncthreads();
        for (int idx = t; idx < 512; idx += 384) {
            int node = idx >> 5, p = idx & 31;
            float2 x2 = *(const float2*)&nodef[(n0+node)*64 + 2*p];
            sX[node*33 + p] = pack2(x2.x, x2.y);
        }
        __syncthreads();

        ull acc[4][4];
#pragma unroll
        for (int a = 0; a < 4; a++) { acc[a][0]=0; acc[a][1]=0; acc[a][2]=0; acc[a][3]=0; }
        const ull* wp = &sW[jq*130];
#pragma unroll 4
        for (int p = 0; p < 32; p++) {
            ulonglong2 w01 = *(const ulonglong2*)&wp[p*4];
            ulonglong2 w23 = *(const ulonglong2*)&wp[p*4 + 2];
#pragma unroll
            for (int ee = 0; ee < 4; ee++) {
                ull xv = sX[(ng*4+ee)*33 + p];
                ffma2(acc[ee][0], xv, w01.x);
                ffma2(acc[ee][1], xv, w01.y);
                ffma2(acc[ee][2], xv, w23.x);
                ffma2(acc[ee][3], xv, w23.y);
            }
        }
#pragma unroll
        for (int ee = 0; ee < 4; ee++) {
            int n = n0 + ng*4 + ee;
            float2 u0 = unpack2(acc[ee][0]), u1 = unpack2(acc[ee][1]);
            float2 u2 = unpack2(acc[ee][2]), u3 = unpack2(acc[ee][3]);
            float4 o;
            o.x = u0.x+u0.y; o.y = u1.x+u1.y; o.z = u2.x+u2.y; o.w = u3.x+u3.y;
            if (jq < 16 || (jq >= 32 && jq < 64)) {
                *(float4*)&g_pc[(size_t)n*384 + jq*4] = o;
            } else {
                __half2 h0 = __floats2half2_rn(o.x, o.y);
                __half2 h1 = __floats2half2_rn(o.z, o.w);
                uint2 uu; uu.x = *(unsigned*)&h0; uu.y = *(unsigned*)&h1;
                if (jq < 32)
                    *(uint2*)&g_pch1[(size_t)n*64 + (jq-16)*4] = uu;
                else
                    *(uint2*)&g_pchAV[(size_t)n*128 + (jq-64)*4] = uu;
            }
        }
    }
}

// ---------------- K1: HMMA e_lin (fp16 out) ---------------------------------
// persistent, 384 threads (12 warps), 2 CTAs/SM, tile = 8 nodes (96 edges).
__global__ __launch_bounds__(384,2) void k1_edge(
    const float* __restrict__ edgef, const int* __restrict__ nbr,
    const float* __restrict__ nmask, const float* __restrict__ W,
    const float* __restrict__ bE,
    const float* __restrict__ gE, const float* __restrict__ bEbn)
{
    extern __shared__ float smem[];
    __half* sWh  = (__half*)smem;                 // 64*72 halves   (9216B)
    __half* sCh  = sWh + 4608;                    // 96*72 halves   (13824B)
    float*  sE   = (float*)(sCh + 6912);          // 2 * 96*68 f32  (52224B)
    __half* sNPC = (__half*)(sE + 2*6528);        // 2 * 96*72      (27648B)
    float*  sPS  = (float*)(sNPC + 2*6912);       // 8*68           (2176B)
    float*  sM   = sPS + 544;                     // 96
    int*    sNI  = (int*)(sM + 96);               // 2*96
    float*  sSum = (float*)(sNI + 192);           // 64
    float*  sSsq = sSum + 64;                     // 64

    int t = threadIdx.x;
    for (int idx = t; idx < 4096; idx += 384) {
        int j = idx >> 6, c = idx & 63;
        sWh[j*72 + c] = __float2half(W[(128 + c)*64 + j]);
    }
    if (t < 64) { sSum[t] = 0.f; sSsq[t] = 0.f; }

    int wid = t >> 5, l = t & 31;
    int m = wid % 6, g = wid / 6;
    int r0 = l >> 2, r1 = r0 + 8;
    int cq = (l & 3) * 2;
    int l16 = l & 15;

    float bj8[8];
#pragma unroll
    for (int nu = 0; nu < 4; nu++)
#pragma unroll
        for (int c = 0; c < 2; c++)
            bj8[nu*2+c] = bE[g*32 + nu*8 + cq + c];

    float pS[8] = {0,0,0,0,0,0,0,0}, pQ[8] = {0,0,0,0,0,0,0,0};

    const int GRID = gridDim.x;
    const int NT = NEDGE / 96;   // 6250
    int bid = blockIdx.x;

    if (t < 24) CP16(su32(&sNI[t*4]), &nbr[bid*96 + t*4]);
    CPCOMMIT(); CPWAIT0();
    __syncthreads();
    {
        for (int i = t; i < 1536; i += 384) {
            int le = i >> 4, c4 = (i & 15) << 2;
            CP16(su32(&sE[le*68 + c4]), &edgef[(size_t)(bid*96+le)*64 + c4]);
        }
        for (int i = t; i < 768; i += 384) {
            int le = i >> 3, c8 = (i & 7) * 8;
            int nb = sNI[le];
            CP16(su32(&sNPC[le*72 + c8]), &g_pch1[(size_t)nb*64 + c8]);
        }
        int T1 = bid + GRID;
        if (T1 < NT && t < 24)
            CP16(su32(&sNI[96 + t*4]), &nbr[T1*96 + t*4]);
    }
    CPCOMMIT();

    int w = 0;
    for (int T = bid; T < NT; T += GRID, w ^= 1) {
        int cur = w, nxt = w ^ 1;
        CPWAIT0();
        __syncthreads();

        int Tn = T + GRID;
        if (Tn < NT) {
            for (int i = t; i < 1536; i += 384) {
                int le = i >> 4, c4 = (i & 15) << 2;
                CP16(su32(&sE[nxt*6528 + le*68 + c4]),
                     &edgef[(size_t)(Tn*96+le)*64 + c4]);
            }
            for (int i = t; i < 768; i += 384) {
                int le = i >> 3, c8 = (i & 7) * 8;
                int nb = sNI[nxt*96 + le];
                CP16(su32(&sNPC[nxt*6912 + le*72 + c8]),
                     &g_pch1[(size_t)nb*64 + c8]);
            }
            int Tn2 = Tn + GRID;
            if (Tn2 < NT && t < 24)
                CP16(su32(&sNI[cur*96 + t*4]), &nbr[Tn2*96 + t*4]);
            CPCOMMIT();
        }

        int eb = T*96, n0 = T*8;
        if (t < 128) {
            int node = t >> 4, q = (t & 15) << 2;
            *(float4*)&sPS[node*68 + q] =
                *(const float4*)&g_pc[(size_t)(n0+node)*384 + q];
        }
        if (t < 96) {
            int e = eb + t, n = n0 + t/KNBR, k = t % KNBR;
            float L = g_lens[n];
            sM[t] = (L > 0.f) ? nmask[e] : (k == 0 ? 1.f : 0.f);
        }
        const float* eE = &sE[cur*6528];
        for (int i = t; i < 1536; i += 384) {
            int le = i >> 4, j = (i & 15) << 2;
            float4 v = *(const float4*)&eE[le*68 + j];
            __half2 q0 = __floats2half2_rn(v.x, v.y);
            __half2 q1 = __floats2half2_rn(v.z, v.w);
            uint2 qq; qq.x = *(unsigned*)&q0; qq.y = *(unsigned*)&q1;
            *(uint2*)&sCh[le*72 + j] = qq;
        }
        __syncthreads();

        float dacc[4][4];
#pragma unroll
        for (int a = 0; a < 4; a++) { dacc[a][0]=0; dacc[a][1]=0; dacc[a][2]=0; dacc[a][3]=0; }
#pragma unroll
        for (int kk = 0; kk < 4; kk++) {
            unsigned a4[4];
            ldm_x4(a4[0], a4[1], a4[2], a4[3],
                su32(&sCh[(m*16 + l16)*72 + kk*16 + (l >> 4)*8]));
#pragma unroll
            for (int nu = 0; nu < 4; nu++) {
                unsigned b0, b1x;
                ldm_x2(b0, b1x,
                    su32(&sWh[(g*32 + nu*8 + (l16 & 7))*72 + kk*16 + ((l16 >> 3)&1)*8]));
                mma16816(dacc[nu], a4, b0, b1x);
            }
        }

        const __half* npcb = &sNPC[cur*6912];
#pragma unroll
        for (int nu = 0; nu < 4; nu++) {
#pragma unroll
            for (int rsel = 0; rsel < 2; rsel++) {
                int r = rsel ? r1 : r0;
                int le = m*16 + r, e = eb + le, ln = le / KNBR;
                float mm = sM[le];
                int jb = g*32 + nu*8 + cq;
                float o0 = dacc[nu][rsel*2+0] + bj8[nu*2+0]
                         + sPS[ln*68 + jb]     + __half2float(npcb[le*72 + jb]);
                float o1 = dacc[nu][rsel*2+1] + bj8[nu*2+1]
                         + sPS[ln*68 + jb + 1] + __half2float(npcb[le*72 + jb + 1]);
                __half2 hp = __floats2half2_rn(o0, o1);
                *(unsigned*)&g_elinh[(size_t)e*64 + jb] = *(unsigned*)&hp;
                pS[nu*2+0] += o0*mm; pQ[nu*2+0] += o0*o0*mm;
                pS[nu*2+1] += o1*mm; pQ[nu*2+1] += o1*o1*mm;
            }
        }
    }
    __syncthreads();
#pragma unroll
    for (int nu = 0; nu < 4; nu++)
#pragma unroll
        for (int c = 0; c < 2; c++) {
            int j = g*32 + nu*8 + cq + c;
            atomicAdd(&sSum[j], pS[nu*2+c]);
            atomicAdd(&sSsq[j], pQ[nu*2+c]);
        }
    __syncthreads();
    if (t < 64) {
        atomicAdd(&g_sumE[t], (double)sSum[t]);
        atomicAdd(&g_ssqE[t], (double)sSsq[t]);
    }
}

// row c (128..191) weight for fused att|val col j in [0,128)
__device__ __forceinline__ float wrow3(const float* W1, const float* Wv,
                                       int crow, int j) {
    if (j < 64) return W1[((j>>4)*192 + crow)*16 + (j&15)];
    int jv = j - 64;
    return Wv[((jv>>4)*192 + crow)*16 + (jv&15)];
}

// ---------------- K3: HMMA fused edge-update + attention + value -----------
__global__ __launch_bounds__(384,2) void k3_att(
    const float* __restrict__ edgef, const int* __restrict__ nbr,
    const float* __restrict__ nmask,
    const float* __restrict__ W1, const float* __restrict__ b1,
    const float* __restrict__ W2,
    const float* __restrict__ Wv, const float* __restrict__ bv,
    const float* __restrict__ gE, const float* __restrict__ bEbn,
    float* __restrict__ out_edges)
{
    extern __shared__ float smem[];
    __half* sWh  = (__half*)smem;                 // 128*72 halves  (18432B)
    __half* sCh  = sWh + 9216;                    // 48*72 halves   (6912B)
    float*  sE   = (float*)(sCh + 3456);          // 2 * 48*68      (26112B)
    __half* sNAV = (__half*)(sE + 2*3264);        // 2 * 48*136     (26112B)
    __half* sEL  = sNAV + 2*6528;                 // 2 * 48*64      (12288B)
    float*  sPS  = (float*)(sEL + 2*3072);        // 4*132          (2112B)
    float*  sLog = sPS + 528;                     // 192
    float*  sM   = sLog + 192;                    // 48
    int*    sNI  = (int*)(sM + 48);               // 2*48
    float*  sCoef= (float*)(sNI + 96);            // 128
    float*  sSum = sCoef + 128;                   // 64
    float*  sSsq = sSum + 64;                     // 64

    int t = threadIdx.x;
    for (int idx = t; idx < 8192; idx += 384) {
        int j = idx >> 6, c = idx & 63;
        sWh[j*72 + c] = __float2half(wrow3(W1, Wv, 128 + c, j));
    }
    if (t < 64) {
        float cnt = (float)g_cnt;
        float s = (float)g_sumE[t], q = (float)g_ssqE[t];
        float mean = s / cnt, var = q / cnt - mean*mean;
        float inv = rsqrtf(var + EPSV);
        float sc = gE[t] * inv;
        sCoef[t] = sc;
        sCoef[64 + t] = bEbn[t] - mean*sc;
        sSum[t] = 0.f; sSsq[t] = 0.f;
    }

    int wid = t >> 5, l = t & 31;
    int m = wid % 3, g = wid / 3;
    int isAtt = (g < 2);
    int r0 = l >> 2, r1 = r0 + 8;
    int cq = (l & 3) * 2;

    float c1r[8], c2r[8];
#pragma unroll
    for (int nu = 0; nu < 4; nu++)
#pragma unroll
        for (int c = 0; c < 2; c++) {
            int j = g*32 + nu*8 + cq + c;
            if (isAtt) { c1r[nu*2+c] = b1[j]; c2r[nu*2+c] = W2[j]; }
            else       { c1r[nu*2+c] = bv[j - 64]; c2r[nu*2+c] = 0.f; }
        }

    float pS8[8], pQ8[8];
#pragma unroll
    for (int i = 0; i < 8; i++) { pS8[i] = 0.f; pQ8[i] = 0.f; }

    const int GRID = gridDim.x;
    const int NT = N_NODES / 4;
    int bid = blockIdx.x;

    if (t < 12) CP16(su32(&sNI[t*4]), &nbr[bid*48 + t*4]);
    CPCOMMIT(); CPWAIT0();
    __syncthreads();
    {
        for (int i = t; i < 768; i += 384) {
            int le = i >> 4, c4 = (i & 15) << 2;
            CP16(su32(&sE[le*68 + c4]), &edgef[(size_t)(bid*48+le)*64 + c4]);
        }
        for (int i = t; i < 768; i += 384) {
            int le = i >> 4, c8 = (i & 15) * 8;
            int nb = sNI[le];
            CP16(su32(&sNAV[le*136 + c8]), &g_pchAV[(size_t)nb*128 + c8]);
        }
        for (int i = t; i < 384; i += 384) {
            int le = i >> 3, c8 = (i & 7) * 8;
            CP16(su32(&sEL[le*64 + c8]), &g_elinh[(size_t)(bid*48+le)*64 + c8]);
        }
        int T1 = bid + GRID;
        if (T1 < NT && t < 12)
            CP16(su32(&sNI[48 + t*4]), &nbr[T1*48 + t*4]);
    }
    CPCOMMIT();

    int w = 0;
    for (int T = bid; T < NT; T += GRID, w ^= 1) {
        int cur = w, nxt = w ^ 1;
        CPWAIT0();
        __syncthreads();

        int Tn = T + GRID;
        if (Tn < NT) {
            for (int i = t; i < 768; i += 384) {
                int le = i >> 4, c4 = (i & 15) << 2;
                CP16(su32(&sE[nxt*3264 + le*68 + c4]),
                     &edgef[(size_t)(Tn*48+le)*64 + c4]);
            }
            for (int i = t; i < 768; i += 384) {
                int le = i >> 4, c8 = (i & 15) * 8;
                int nb = sNI[nxt*48 + le];
                CP16(su32(&sNAV[nxt*6528 + le*136 + c8]),
                     &g_pchAV[(size_t)nb*128 + c8]);
            }
            for (int i = t; i < 384; i += 384) {
                int le = i >> 3, c8 = (i & 7) * 8;
                CP16(su32(&sEL[nxt*3072 + le*64 + c8]),
                     &g_elinh[(size_t)(Tn*48+le)*64 + c8]);
            }
            int Tn2 = Tn + GRID;
            if (Tn2 < NT && t < 12)
                CP16(su32(&sNI[cur*48 + t*4]), &nbr[Tn2*48 + t*4]);
            CPCOMMIT();
        }

        int n0 = T*4, eb = n0*KNBR;
        if (t < 48) {
            int e = eb + t, n = n0 + t/KNBR, k = t % KNBR;
            float L = g_lens[n];
            sM[t] = (L > 0.f) ? nmask[e] : (k == 0 ? 1.f : 0.f);
        }
        if (t < 128) {
            int node = t >> 5, q = (t & 31) << 2;
            *(float4*)&sPS[node*132 + q] =
                *(const float4*)&g_pc[(size_t)(n0+node)*384 + 128 + q];
        }
        __syncthreads();

        const float*  eE = &sE[cur*3264];
        const __half* eL = &sEL[cur*3072];
        for (int i = t; i < 768; i += 384) {
            int le = i >> 4, j = (i & 15) << 2;
            int e = eb + le;
            float mm = sM[le];
            uint2 elu = *(const uint2*)&eL[le*64 + j];
            float2 el01 = __half22float2(*(__half2*)&elu.x);
            float2 el23 = __half22float2(*(__half2*)&elu.y);
            float4 ef = *(const float4*)&eE[le*68 + j];
            float4 sc = *(const float4*)&sCoef[j];
            float4 sh = *(const float4*)&sCoef[64 + j];
            float4 eu;
            eu.x = fsp(ef.x + (el01.x*sc.x + sh.x)*mm);
            eu.y = fsp(ef.y + (el01.y*sc.y + sh.y)*mm);
            eu.z = fsp(ef.z + (el23.x*sc.z + sh.z)*mm);
            eu.w = fsp(ef.w + (el23.y*sc.w + sh.w)*mm);
            *(float4*)&out_edges[(size_t)e*64 + j] = eu;
            __half2 q0 = __floats2half2_rn(eu.x, eu.y);
            __half2 q1 = __floats2half2_rn(eu.z, eu.w);
            uint2 qq; qq.x = *(unsigned*)&q0; qq.y = *(unsigned*)&q1;
            *(uint2*)&sCh[le*72 + j] = qq;
        }
        __syncthreads();

        float dacc[4][4];
#pragma unroll
        for (int a = 0; a < 4; a++)
#pragma unroll
            for (int b = 0; b < 4; b++) dacc[a][b] = 0.f;
        int l16 = l & 15;
#pragma unroll
        for (int kk = 0; kk < 4; kk++) {
            unsigned a4[4];
            ldm_x4(a4[0], a4[1], a4[2], a4[3],
                su32(&sCh[(m*16 + l16)*72 + kk*16 + (l >> 4)*8]));
#pragma unroll
            for (int nu = 0; nu < 4; nu++) {
                unsigned b0, b1x;
                ldm_x2(b0, b1x,
                    su32(&sWh[(g*32 + nu*8 + (l16 & 7))*72 + kk*16 + ((l16 >> 3)&1)*8]));
                mma16816(dacc[nu], a4, b0, b1x);
            }
        }

        const __half* nav = &sNAV[cur*6528];
        if (isAtt) {
            float lpAcc[4] = {0.f, 0.f, 0.f, 0.f};
#pragma unroll
            for (int nu = 0; nu < 4; nu++) {
                int hs = nu >> 1;
#pragma unroll
                for (int rc = 0; rc < 4; rc++) {
                    int rsel = rc >> 1, c = rc & 1;
                    int r = rsel ? r1 : r0;
                    int le = m*16 + r, ln = le / KNBR;
                    int j = g*32 + nu*8 + cq + c;
                    float h1v = fsp(dacc[nu][rc] + c1r[nu*2+c]
                                    + sPS[ln*132 + j]
                                    + __half2float(nav[le*136 + j]));
                    lpAcc[rsel*2 + hs] += h1v * c2r[nu*2+c];
                }
            }
#pragma unroll
            for (int i = 0; i < 4; i++) {
                lpAcc[i] += __shfl_xor_sync(0xffffffffu, lpAcc[i], 1);
                lpAcc[i] += __shfl_xor_sync(0xffffffffu, lpAcc[i], 2);
            }
            if ((l & 3) == 0) {
                sLog[(m*16+r0)*4 + g*2 + 0] = lpAcc[0];
                sLog[(m*16+r0)*4 + g*2 + 1] = lpAcc[1];
                sLog[(m*16+r1)*4 + g*2 + 0] = lpAcc[2];
                sLog[(m*16+r1)*4 + g*2 + 1] = lpAcc[3];
            }
        } else {
#pragma unroll
            for (int nu = 0; nu < 4; nu++)
#pragma unroll
                for (int rc = 0; rc < 4; rc++) {
                    int rsel = rc >> 1, c = rc & 1;
                    int r = rsel ? r1 : r0;
                    int le = m*16 + r, ln = le / KNBR;
                    int jv = (g-2)*32 + nu*8 + cq + c;
                    dacc[nu][rc] += c1r[nu*2+c] + sPS[ln*132 + 64 + jv]
                                  + __half2float(nav[le*136 + 64 + jv]);
                }
        }
        __syncthreads();

        if (!isAtt) {
            int q = l & 3;
            int rq = (q >> 1) ? r1 : r0;
            int nodeq = (m*16 + rq) / KNBR;
            int hq = (g-2)*2 + (q & 1);
            int le0 = nodeq * KNBR;
            float mx = -1e30f;
#pragma unroll
            for (int k = 0; k < KNBR; k++) {
                int le = le0 + k;
                if (sM[le] > 0.f) mx = fmaxf(mx, sLog[le*4 + hq]);
            }
            float ss = 0.f;
#pragma unroll
            for (int k = 0; k < KNBR; k++) {
                int le = le0 + k;
                ss += (sM[le] > 0.f) ? __expf(sLog[le*4 + hq] - mx) : 0.f;
            }
            float inv = 1.f / ss;
            float mxq[4], invq[4];
            int lb = l & ~3;
#pragma unroll
            for (int i = 0; i < 4; i++) {
                mxq[i]  = __shfl_sync(0xffffffffu, mx,  lb + i);
                invq[i] = __shfl_sync(0xffffffffu, inv, lb + i);
            }
#pragma unroll
            for (int nu = 0; nu < 4; nu++) {
                int hs = nu >> 1;
                int h = (g-2)*2 + hs;
#pragma unroll
                for (int rsel = 0; rsel < 2; rsel++) {
                    int r = rsel ? r1 : r0;
                    int le = m*16 + r, e = eb + le;
                    int qi = rsel*2 + hs;
                    float mm = sM[le];
                    float a = (mm > 0.f)
                        ? __expf(sLog[le*4 + h] - mxq[qi]) * invq[qi] : 0.f;
                    float p0 = a * dacc[nu][rsel*2 + 0];
                    float p1 = a * dacc[nu][rsel*2 + 1];
                    __half2 hp = __floats2half2_rn(p0, p1);
                    *(unsigned*)&g_ph[(size_t)e*64 + (g-2)*32 + nu*8 + cq] =
                        *(unsigned*)&hp;
                    pS8[nu*2+0] += p0*mm; pQ8[nu*2+0] += p0*p0*mm;
                    pS8[nu*2+1] += p1*mm; pQ8[nu*2+1] += p1*p1*mm;
                }
            }
        }
    }
    __syncthreads();
    if (!isAtt) {
#pragma unroll
        for (int nu = 0; nu < 4; nu++)
#pragma unroll
            for (int c = 0; c < 2; c++) {
                int jv = (g-2)*32 + nu*8 + cq + c;
                atomicAdd(&sSum[jv], pS8[nu*2+c]);
                atomicAdd(&sSsq[jv], pQ8[nu*2+c]);
            }
    }
    __syncthreads();
    if (t < 64) {
        atomicAdd(&g_sumP[t], (double)sSum[t]);
        atomicAdd(&g_ssqP[t], (double)sSsq[t]);
    }
}

// ---------------- K5: head_feats + pooled + out-BN stats (half2 stream) ----
// 256 threads: 32 channel-pairs x 8 node-lanes; block = 64 nodes.
__global__ __launch_bounds__(256) void k5_pool(
    const float* __restrict__ nmask,
    const float* __restrict__ gP, const float* __restrict__ bP)
{
    __shared__ float scf[64], shf[64];
    int t = threadIdx.x;
    if (t < 64) {
        float cnt = (float)g_cnt;
        float s = (float)g_sumP[t], q = (float)g_ssqP[t];
        float mean = s / cnt, var = q / cnt - mean*mean;
        float inv = rsqrtf(var + EPSV);
        float sc = gP[t] * inv;
        scf[t] = sc; shf[t] = bP[t] - mean*sc;
    }
    __syncthreads();
    int j2 = t & 31, nl = t >> 5;          // channel pair, node lane
    int n0 = blockIdx.x * 64;
    float scx = scf[2*j2], scy = scf[2*j2+1];
    float shx = shf[2*j2], shy = shf[2*j2+1];
    float psx = 0.f, psy = 0.f, pqx = 0.f, pqy = 0.f;
    for (int i = 0; i < 8; i++) {
        int n = n0 + nl*8 + i;
        if (n >= N_NODES) break;
        float L = g_lens[n];
        float px = 0.f, py = 0.f;
#pragma unroll
        for (int k = 0; k < KNBR; k++) {
            float m = (L > 0.f) ? nmask[n*KNBR + k] : (k == 0 ? 1.f : 0.f);
            __half2 ph = *(const __half2*)&g_ph[(size_t)(n*KNBR + k)*64 + 2*j2];
            float2 p = __half22float2(ph);
            px += fsp(p.x*scx + shx) * m;
            py += fsp(p.y*scy + shy) * m;
        }
        *(float2*)&g_pooled[n*64 + 2*j2] = make_float2(px, py);
        psx += px; pqx += px*px;
        psy += py; pqy += py*py;
    }
    __shared__ float rsx[256], rsy[256], rqx[256], rqy[256];
    rsx[t] = psx; rsy[t] = psy; rqx[t] = pqx; rqy[t] = pqy;
    __syncthreads();
    if (nl == 0) {
        float sx = 0.f, sy = 0.f, qx = 0.f, qy = 0.f;
#pragma unroll
        for (int lane = 0; lane < 8; lane++) {
            sx += rsx[lane*32 + j2]; sy += rsy[lane*32 + j2];
            qx += rqx[lane*32 + j2]; qy += rqy[lane*32 + j2];
        }
        atomicAdd(&g_sumO[2*j2],   (double)sx);
        atomicAdd(&g_sumO[2*j2+1], (double)sy);
        atomicAdd(&g_ssqO[2*j2],   (double)qx);
        atomicAdd(&g_ssqO[2*j2+1], (double)qy);
    }
}

// ---------------- K7: residual + out-BN (float4) ----------------
__global__ __launch_bounds__(256) void k7_out(
    const float* __restrict__ nodef,
    const float* __restrict__ gO, const float* __restrict__ bO,
    float* __restrict__ out_nodes)
{
    __shared__ float scf[64], shf[64];
    int t = threadIdx.x;
    if (t < 64) {
        float cnt = (float)N_NODES;
        float s = (float)g_sumO[t], q = (float)g_ssqO[t];
        float mean = s / cnt, var = q / cnt - mean*mean;
        float inv = rsqrtf(var + EPSV);
        float sc = gO[t] * inv;
        scf[t] = sc; shf[t] = bO[t] - mean*sc;
    }
    __syncthreads();
    int i4 = (blockIdx.x * 256 + t) * 4;
    if (i4 < N_NODES*64) {
        int j = i4 & 63;
        float4 pl = *(const float4*)&g_pooled[i4];
        float4 nf = *(const float4*)&nodef[i4];
        float4 o;
        o.x = nf.x + scf[j]  *pl.x + shf[j];
        o.y = nf.y + scf[j+1]*pl.y + shf[j+1];
        o.z = nf.z + scf[j+2]*pl.z + shf[j+2];
        o.w = nf.w + scf[j+3]*pl.w + shf[j+3];
        *(float4*)&out_nodes[i4] = o;
    }
}

// ---------------- launch ----------------
extern "C" void kernel_launch(void* const* d_in, const int* in_sizes, int n_in,
                              void* d_out, int out_size)
{
    const float* nodef  = (const float*)d_in[0];
    const float* edgef  = (const float*)d_in[1];
    const int*   nbr    = (const int*)d_in[2];
    const float* nmask  = (const float*)d_in[3];
    const float* W_edge = (const float*)d_in[4];
    const float* b_edge = (const float*)d_in[5];
    const float* g_ebn  = (const float*)d_in[6];
    const float* b_ebn  = (const float*)d_in[7];
    const float* W1     = (const float*)d_in[8];
    const float* b1     = (const float*)d_in[9];
    const float* W2     = (const float*)d_in[10];
    const float* Wv     = (const float*)d_in[12];
    const float* bv     = (const float*)d_in[13];
    const float* g_abn  = (const float*)d_in[14];
    const float* b_abn  = (const float*)d_in[15];
    const float* g_obn  = (const float*)d_in[16];
    const float* b_obn  = (const float*)d_in[17];

    float* out_nodes = (float*)d_out;
    float* out_edges = out_nodes + (size_t)N_NODES * 64;

    const int smemP = (96*130 + 16*33) * 8;
    const int smem1 = 9216 + 13824 + 52224 + 27648 + 2176
                      + 96*4 + 192*4 + 512;                      // ~104.3KB
    const int smem3 = 9216*2 + 3456*2 + 2*3264*4 + 2*6528*2 + 2*3072*2 +
                      (528 + 192 + 48 + 128 + 128) * 4 + 96*4;   // ~94.3KB
    static int inited = 0;
    if (!inited) {
        cudaFuncSetAttribute(k_pre,  cudaFuncAttributeMaxDynamicSharedMemorySize, smemP);
        cudaFuncSetAttribute(k1_edge, cudaFuncAttributeMaxDynamicSharedMemorySize, smem1);
        cudaFuncSetAttribute(k3_att,  cudaFuncAttributeMaxDynamicSharedMemorySize, smem3);
        inited = 1;
    }

    k_lens<<<LENS_BLOCKS, 256>>>(nmask);                               // 1
    k_pre<<<2*NSM, 384, smemP>>>(nodef, W_edge, W1, Wv);               // 2
    k1_edge<<<2*NSM, 384, smem1>>>(edgef, nbr, nmask, W_edge, b_edge,
                                   g_ebn, b_ebn);                      // 3
    k3_att<<<2*NSM, 384, smem3>>>(edgef, nbr, nmask, W1, b1, W2, Wv, bv,
                                  g_ebn, b_ebn, out_edges);            // 4 -> profiled
    k5_pool<<<(N_NODES + 63)/64, 256>>>(nmask, g_abn, b_abn);          // 5
    k7_out<<<(N_NODES*64/4 + 255)/256, 256>>>(nodef, g_obn, b_obn,
                                              out_nodes);              // 6
}